// round 1
// baseline (speedup 1.0000x reference)
#include <cuda_runtime.h>

#define S_LEN 2048
#define V_DIM 1024
#define NH    16
#define HD    64
#define QKV_LD 3072
#define SCALE 0.125f

// Scratch (allocation-free rule: __device__ globals)
__device__ float g_qkv[S_LEN * QKV_LD];   // [S][3V]: q | k | v
__device__ float g_pos[S_LEN * V_DIM];    // rel_embed @ W_pos^T
__device__ float g_attn[S_LEN * V_DIM];   // attention output, head-concat

// ---------------------------------------------------------------------------
// C[M,N] = A[M,K] * B[N,K]^T   (classic 128x128x8 register-tiled SGEMM)
// M,N multiples of 128; K multiple of 8.
// ---------------------------------------------------------------------------
__global__ __launch_bounds__(256) void sgemm_tn(const float* __restrict__ A,
                                                const float* __restrict__ B,
                                                float* __restrict__ C,
                                                int M, int N, int K)
{
    __shared__ float As[8][128];
    __shared__ float Bs[8][128];
    const int bm = blockIdx.y * 128, bn = blockIdx.x * 128;
    const int tid = threadIdx.x;
    const int lrow = tid >> 1;
    const int lcol = (tid & 1) * 4;
    const int tx = tid & 15, ty = tid >> 4;
    const float* Ab = A + (size_t)(bm + lrow) * K + lcol;
    const float* Bb = B + (size_t)(bn + lrow) * K + lcol;

    float acc[8][8];
#pragma unroll
    for (int i = 0; i < 8; i++)
#pragma unroll
        for (int j = 0; j < 8; j++) acc[i][j] = 0.f;

    for (int k0 = 0; k0 < K; k0 += 8) {
        float4 av = *(const float4*)(Ab + k0);
        float4 bv = *(const float4*)(Bb + k0);
        __syncthreads();
        As[lcol + 0][lrow] = av.x; As[lcol + 1][lrow] = av.y;
        As[lcol + 2][lrow] = av.z; As[lcol + 3][lrow] = av.w;
        Bs[lcol + 0][lrow] = bv.x; Bs[lcol + 1][lrow] = bv.y;
        Bs[lcol + 2][lrow] = bv.z; Bs[lcol + 3][lrow] = bv.w;
        __syncthreads();
#pragma unroll
        for (int k = 0; k < 8; k++) {
            float a[8], b[8];
            *(float4*)&a[0] = *(float4*)&As[k][ty * 8];
            *(float4*)&a[4] = *(float4*)&As[k][ty * 8 + 4];
            *(float4*)&b[0] = *(float4*)&Bs[k][tx * 8];
            *(float4*)&b[4] = *(float4*)&Bs[k][tx * 8 + 4];
#pragma unroll
            for (int i = 0; i < 8; i++)
#pragma unroll
                for (int j = 0; j < 8; j++)
                    acc[i][j] += a[i] * b[j];
        }
    }
#pragma unroll
    for (int i = 0; i < 8; i++) {
        float* Cr = C + (size_t)(bm + ty * 8 + i) * N + bn + tx * 8;
#pragma unroll
        for (int j = 0; j < 8; j++) Cr[j] = acc[i][j];
    }
}

// ---------------------------------------------------------------------------
// Fused flash-attention with Transformer-XL relative-position shift.
// Grid: (S/64, H). 256 threads. Dynamic smem ~138 KB.
//
// score[i,j] = (q_i+u_h)·k_j + (q_i+v_h)·r_{(j-i-1) mod S}  (j<=i), *SCALE
// where r_m[d] = g_pos[m][h*64+d]. For tile (i0,j0) the needed m values are
// the contiguous band mbase..mbase+126, mbase = j0 - i0 + S - 64, and the
// band-local index is t = j - i + 63  (j = t + i - 63).
// ---------------------------------------------------------------------------
__global__ __launch_bounds__(256, 1) void flash_xl(const float* __restrict__ u_vec,
                                                   const float* __restrict__ v_vec)
{
    extern __shared__ float sm[];
    float* sQUt = sm;              // [64 d][68]  (q+u), d-major
    float* sQVt = sQUt + 64 * 68;  // [64 d][68]  (q+v), d-major
    float* sKt  = sQVt + 64 * 68;  // [64 d][68]  k, d-major
    float* sV   = sKt  + 64 * 68;  // [64 j][68]  v, row-major
    float* sRt  = sV   + 64 * 68;  // [64 d][132] pos band, d-major, 128 t's
    float* sS   = sRt  + 64 * 132; // [64 i][65]  scores
    float* sPt  = sS   + 64 * 65;  // [64 j][68]  exp probs, j-major
    float* rowM = sPt  + 64 * 68;  // [64]
    float* rowL = rowM + 64;       // [64]
    float* rowC = rowL + 64;       // [64]

    const int h   = blockIdx.y;
    const int i0  = blockIdx.x * 64;
    const int tid = threadIdx.x;
    const int tx  = tid & 15, ty  = tid >> 4;   // 16x16 for 64x64 GEMMs
    const int tx2 = tid & 31, ty2 = tid >> 5;   // 32x8  for 64x128 GEMM

    // Load QU/QV tiles (transposed, d-major)
    for (int idx = tid; idx < 64 * 16; idx += 256) {
        int i = idx >> 4, cg = (idx & 15) << 2;
        float4 q4 = *(const float4*)&g_qkv[(size_t)(i0 + i) * QKV_LD + h * HD + cg];
        float4 u4 = *(const float4*)&u_vec[h * HD + cg];
        float4 v4 = *(const float4*)&v_vec[h * HD + cg];
        sQUt[(cg + 0) * 68 + i] = q4.x + u4.x;
        sQUt[(cg + 1) * 68 + i] = q4.y + u4.y;
        sQUt[(cg + 2) * 68 + i] = q4.z + u4.z;
        sQUt[(cg + 3) * 68 + i] = q4.w + u4.w;
        sQVt[(cg + 0) * 68 + i] = q4.x + v4.x;
        sQVt[(cg + 1) * 68 + i] = q4.y + v4.y;
        sQVt[(cg + 2) * 68 + i] = q4.z + v4.z;
        sQVt[(cg + 3) * 68 + i] = q4.w + v4.w;
    }
    if (tid < 64) { rowM[tid] = -1e30f; rowL[tid] = 0.f; }

    float o[4][4];
#pragma unroll
    for (int r = 0; r < 4; r++)
#pragma unroll
        for (int c = 0; c < 4; c++) o[r][c] = 0.f;

    for (int j0 = 0; j0 <= i0; j0 += 64) {
        __syncthreads();  // protect smem reuse (sV/sPt from previous GEMM3)

        // Load K (transposed), V (row-major)
        for (int idx = tid; idx < 64 * 16; idx += 256) {
            int j = idx >> 4, cg = (idx & 15) << 2;
            float4 k4 = *(const float4*)&g_qkv[(size_t)(j0 + j) * QKV_LD + V_DIM + h * HD + cg];
            sKt[(cg + 0) * 68 + j] = k4.x;
            sKt[(cg + 1) * 68 + j] = k4.y;
            sKt[(cg + 2) * 68 + j] = k4.z;
            sKt[(cg + 3) * 68 + j] = k4.w;
            float4 v4 = *(const float4*)&g_qkv[(size_t)(j0 + j) * QKV_LD + 2 * V_DIM + h * HD + cg];
            *(float4*)&sV[j * 68 + cg] = v4;
        }
        // Load pos band (transposed): t in [0,128)
        const int mbase = j0 - i0 + S_LEN - 64;
        for (int idx = tid; idx < 128 * 16; idx += 256) {
            int t = idx >> 4, cg = (idx & 15) << 2;
            int m = mbase + t; if (m >= S_LEN) m -= S_LEN;
            float4 r4 = *(const float4*)&g_pos[(size_t)m * V_DIM + h * HD + cg];
            sRt[(cg + 0) * 132 + t] = r4.x;
            sRt[(cg + 1) * 132 + t] = r4.y;
            sRt[(cg + 2) * 132 + t] = r4.z;
            sRt[(cg + 3) * 132 + t] = r4.w;
        }
        __syncthreads();

        // ---- GEMM1: content scores  sS[i][j] = SCALE * (q+u)_i . k_j ----
        {
            float acc[4][4];
#pragma unroll
            for (int r = 0; r < 4; r++)
#pragma unroll
                for (int c = 0; c < 4; c++) acc[r][c] = 0.f;
#pragma unroll 8
            for (int d = 0; d < 64; d++) {
                float a[4], b[4];
                *(float4*)a = *(float4*)&sQUt[d * 68 + ty * 4];
                *(float4*)b = *(float4*)&sKt [d * 68 + tx * 4];
#pragma unroll
                for (int r = 0; r < 4; r++)
#pragma unroll
                    for (int c = 0; c < 4; c++) acc[r][c] += a[r] * b[c];
            }
#pragma unroll
            for (int r = 0; r < 4; r++)
#pragma unroll
                for (int c = 0; c < 4; c++)
                    sS[(ty * 4 + r) * 65 + tx * 4 + c] = acc[r][c] * SCALE;
        }
        __syncthreads();

        // ---- GEMM2: position band T[i][t] = (q+v)_i . r_t ; scatter to sS ----
        {
            float acc[8][4];
#pragma unroll
            for (int r = 0; r < 8; r++)
#pragma unroll
                for (int c = 0; c < 4; c++) acc[r][c] = 0.f;
#pragma unroll 4
            for (int d = 0; d < 64; d++) {
                float a[8], b[4];
                *(float4*)&a[0] = *(float4*)&sQVt[d * 68 + ty2 * 8];
                *(float4*)&a[4] = *(float4*)&sQVt[d * 68 + ty2 * 8 + 4];
                *(float4*)b     = *(float4*)&sRt [d * 132 + tx2 * 4];
#pragma unroll
                for (int r = 0; r < 8; r++)
#pragma unroll
                    for (int c = 0; c < 4; c++) acc[r][c] += a[r] * b[c];
            }
#pragma unroll
            for (int r = 0; r < 8; r++) {
                int i = ty2 * 8 + r;
#pragma unroll
                for (int c = 0; c < 4; c++) {
                    int t = tx2 * 4 + c;
                    int j = t + i - 63;                 // band-local -> tile col
                    if ((unsigned)j < 64u)
                        sS[i * 65 + j] += acc[r][c] * SCALE;
                }
            }
        }
        __syncthreads();

        // ---- online softmax update (one thread per row) ----
        if (tid < 64) {
            const int i = tid;
            const int jmax = min(63, i0 + i - j0);      // causal: j0+j <= i0+i
            float mOld = rowM[i], mNew = mOld;
            for (int j = 0; j <= jmax; j++)
                mNew = fmaxf(mNew, sS[i * 65 + j]);
            float corr = __expf(mOld - mNew);
            float l = rowL[i] * corr;
            for (int j = 0; j < 64; j++) {
                float p = (j <= jmax) ? __expf(sS[i * 65 + j] - mNew) : 0.f;
                sPt[j * 68 + i] = p;
                l += p;
            }
            rowM[i] = mNew; rowL[i] = l; rowC[i] = corr;
        }
        __syncthreads();

        // ---- rescale O and GEMM3: O[i][d] += P[i][j] * V[j][d] ----
        {
            float cr[4];
#pragma unroll
            for (int r = 0; r < 4; r++) cr[r] = rowC[ty * 4 + r];
#pragma unroll
            for (int r = 0; r < 4; r++)
#pragma unroll
                for (int c = 0; c < 4; c++) o[r][c] *= cr[r];
#pragma unroll 8
            for (int j = 0; j < 64; j++) {
                float a[4], b[4];
                *(float4*)a = *(float4*)&sPt[j * 68 + ty * 4];
                *(float4*)b = *(float4*)&sV [j * 68 + tx * 4];
#pragma unroll
                for (int r = 0; r < 4; r++)
#pragma unroll
                    for (int c = 0; c < 4; c++) o[r][c] += a[r] * b[c];
            }
        }
    }

    // epilogue: normalize and write head-concat layout
    float invl[4];
#pragma unroll
    for (int r = 0; r < 4; r++) invl[r] = 1.f / rowL[ty * 4 + r];
#pragma unroll
    for (int r = 0; r < 4; r++)
#pragma unroll
        for (int c = 0; c < 4; c++)
            g_attn[(size_t)(i0 + ty * 4 + r) * V_DIM + h * HD + tx * 4 + c] =
                o[r][c] * invl[r];
}

// ---------------------------------------------------------------------------
extern "C" void kernel_launch(void* const* d_in, const int* in_sizes, int n_in,
                              void* d_out, int out_size)
{
    const float* x    = (const float*)d_in[0];  // [1,2048,1024]
    const float* Wqkv = (const float*)d_in[1];  // [3072,1024]
    const float* Wout = (const float*)d_in[2];  // [1024,1024]
    const float* Wpos = (const float*)d_in[3];  // [1024,1024]
    const float* u    = (const float*)d_in[4];  // [1,16,1,64]
    const float* v    = (const float*)d_in[5];  // [1,16,1,64]
    const float* rel  = (const float*)d_in[6];  // [2048,1024]
    float* out = (float*)d_out;                 // [1,2048,1024]

    void *pqkv, *ppos, *pattn;
    cudaGetSymbolAddress(&pqkv,  g_qkv);
    cudaGetSymbolAddress(&ppos,  g_pos);
    cudaGetSymbolAddress(&pattn, g_attn);

    const int smem_bytes = 34560 * (int)sizeof(float);  // 138240 B
    cudaFuncSetAttribute(flash_xl, cudaFuncAttributeMaxDynamicSharedMemorySize,
                         smem_bytes);

    // qkv = x @ Wqkv^T      [2048,3072]
    sgemm_tn<<<dim3(QKV_LD / 128, S_LEN / 128), 256>>>(x, Wqkv, (float*)pqkv,
                                                       S_LEN, QKV_LD, V_DIM);
    // pos = rel @ Wpos^T    [2048,1024]
    sgemm_tn<<<dim3(V_DIM / 128, S_LEN / 128), 256>>>(rel, Wpos, (float*)ppos,
                                                      S_LEN, V_DIM, V_DIM);
    // fused attention       -> g_attn [2048,1024]
    flash_xl<<<dim3(S_LEN / 64, NH), 256, smem_bytes>>>(u, v);
    // out = attn @ Wout^T   [2048,1024]
    sgemm_tn<<<dim3(V_DIM / 128, S_LEN / 128), 256>>>((const float*)pattn, Wout,
                                                      out, S_LEN, V_DIM, V_DIM);
}

// round 3
// speedup vs baseline: 1.6718x; 1.6718x over previous
#include <cuda_runtime.h>
#include <cuda_bf16.h>
#include <cstdint>

#define S_LEN 2048
#define V_DIM 1024
#define NH    16
#define HD    64
#define QKV_LD 3072
#define SCALE 0.125f

// ---------------- scratch (__device__ globals; no allocation allowed) ------
__device__ float g_qkv[S_LEN * QKV_LD];   // [S][3V]: q | k | v
__device__ float g_pos[S_LEN * V_DIM];    // rel_embed @ W_pos^T
__device__ float g_attn[S_LEN * V_DIM];   // attention output, head-concat

// bf16 split buffers (hi/lo) for tensor-core GEMMs
__device__ __nv_bfloat16 g_xh[S_LEN * V_DIM],  g_xl[S_LEN * V_DIM];
__device__ __nv_bfloat16 g_wqh[QKV_LD * V_DIM], g_wql[QKV_LD * V_DIM];
__device__ __nv_bfloat16 g_rh[S_LEN * V_DIM],  g_rl[S_LEN * V_DIM];
__device__ __nv_bfloat16 g_wph[V_DIM * V_DIM], g_wpl[V_DIM * V_DIM];
__device__ __nv_bfloat16 g_ah[S_LEN * V_DIM],  g_al[S_LEN * V_DIM];
__device__ __nv_bfloat16 g_woh[V_DIM * V_DIM], g_wol[V_DIM * V_DIM];

// ---------------- helpers ---------------------------------------------------
__device__ __forceinline__ uint32_t s2u(const void* p) {
    uint32_t a;
    asm("{ .reg .u64 t; cvta.to.shared.u64 t, %1; cvt.u32.u64 %0, t; }"
        : "=r"(a) : "l"(p));
    return a;
}
__device__ __forceinline__ void ldm4(uint32_t* f, uint32_t addr) {
    asm volatile("ldmatrix.sync.aligned.m8n8.x4.shared.b16 {%0,%1,%2,%3}, [%4];"
                 : "=r"(f[0]), "=r"(f[1]), "=r"(f[2]), "=r"(f[3]) : "r"(addr));
}
__device__ __forceinline__ void mma_bf16(float* d, const uint32_t* a,
                                         const uint32_t* b) {
    asm volatile(
        "mma.sync.aligned.m16n8k16.row.col.f32.bf16.bf16.f32 "
        "{%0,%1,%2,%3}, {%4,%5,%6,%7}, {%8,%9}, {%0,%1,%2,%3};"
        : "+f"(d[0]), "+f"(d[1]), "+f"(d[2]), "+f"(d[3])
        : "r"(a[0]), "r"(a[1]), "r"(a[2]), "r"(a[3]), "r"(b[0]), "r"(b[1]));
}
// A-tile fragment m16k16 at (m0,k0); tile: 128 rows x 128B, XOR-swizzled
__device__ __forceinline__ void ldsA(uint32_t* f, uint32_t tile, int m0, int k0,
                                     int lane) {
    int r = lane & 7, g = lane >> 3;
    int row = m0 + r + (g & 1) * 8;
    int kch = (k0 >> 3) + (g >> 1);
    ldm4(f, tile + row * 128 + (((kch ^ (row & 7)) & 7) << 4));
}
// B-tile fragment n16k16 at (n0,k0) -> two n8k16 frags {f0,f1},{f2,f3}
__device__ __forceinline__ void ldsB(uint32_t* f, uint32_t tile, int n0, int k0,
                                     int lane) {
    int r = lane & 7, g = lane >> 3;
    int row = n0 + r + (g >> 1) * 8;
    int kch = (k0 >> 3) + (g & 1);
    ldm4(f, tile + row * 128 + (((kch ^ (row & 7)) & 7) << 4));
}

// ---------------- split fp32 -> bf16 hi/lo ---------------------------------
__global__ __launch_bounds__(256) void split_bf16(const float4* __restrict__ x,
                                                  __nv_bfloat16* __restrict__ h,
                                                  __nv_bfloat16* __restrict__ l,
                                                  int n4)
{
    int i = blockIdx.x * 256 + threadIdx.x;
    if (i >= n4) return;
    float4 v = x[i];
    __nv_bfloat16 hx = __float2bfloat16(v.x);
    __nv_bfloat16 hy = __float2bfloat16(v.y);
    __nv_bfloat16 hz = __float2bfloat16(v.z);
    __nv_bfloat16 hw = __float2bfloat16(v.w);
    __nv_bfloat16 lx = __float2bfloat16(v.x - __bfloat162float(hx));
    __nv_bfloat16 ly = __float2bfloat16(v.y - __bfloat162float(hy));
    __nv_bfloat16 lz = __float2bfloat16(v.z - __bfloat162float(hz));
    __nv_bfloat16 lw = __float2bfloat16(v.w - __bfloat162float(hw));
    __nv_bfloat162* H = (__nv_bfloat162*)h;
    __nv_bfloat162* L = (__nv_bfloat162*)l;
    H[2 * i]     = __halves2bfloat162(hx, hy);
    H[2 * i + 1] = __halves2bfloat162(hz, hw);
    L[2 * i]     = __halves2bfloat162(lx, ly);
    L[2 * i + 1] = __halves2bfloat162(lz, lw);
}

// ---------------------------------------------------------------------------
// C[M,N] = A[M,K] * B[N,K]^T  via mma.sync bf16, x3 split (fp32 accuracy).
// 128x128 CTA tile, K-chunk 64, double-buffered cp.async, 8 warps (4x2).
// ---------------------------------------------------------------------------
#define GEMM_SMEM (2 * 65536 + 1024)

__global__ __launch_bounds__(256, 1) void gemm_bf16x3(
    const __nv_bfloat16* __restrict__ Ah, const __nv_bfloat16* __restrict__ Al,
    const __nv_bfloat16* __restrict__ Bh, const __nv_bfloat16* __restrict__ Bl,
    float* __restrict__ C, int M, int N, int K)
{
    extern __shared__ char smem[];
    uint32_t tiles = (s2u(smem) + 1023u) & ~1023u;
    const int tid = threadIdx.x;
    const int lane = tid & 31, wid = tid >> 5;
    const int wm = wid & 3, wn = wid >> 2;         // warp tile 32x64
    const int bn = blockIdx.x * 128, bm = blockIdx.y * 128;

    // per-thread cp.async slots: tiles (Ah,Al,Bh,Bl) x 128 rows x 8 16B chunks
    const __nv_bfloat16* gsrc[16];
    uint32_t sdst[16];
#pragma unroll
    for (int u = 0; u < 16; u++) {
        int idx = u * 256 + tid;
        int tile = idx >> 10, row = (idx >> 3) & 127, cc = idx & 7;
        const __nv_bfloat16* bp = (tile == 0) ? Ah : (tile == 1) ? Al
                                 : (tile == 2) ? Bh : Bl;
        int gr = ((tile < 2) ? bm : bn) + row;
        gsrc[u] = bp + (size_t)gr * K + cc * 8;
        sdst[u] = tiles + tile * 16384u + row * 128u
                + (uint32_t)((cc ^ (row & 7)) << 4);
    }
    const int NC = K >> 6;

    float acc[2][8][4];
#pragma unroll
    for (int mi = 0; mi < 2; mi++)
#pragma unroll
        for (int ni = 0; ni < 8; ni++)
#pragma unroll
            for (int q = 0; q < 4; q++) acc[mi][ni][q] = 0.f;

    // prologue: chunk 0 -> stage 0
#pragma unroll
    for (int u = 0; u < 16; u++)
        asm volatile("cp.async.cg.shared.global [%0], [%1], 16;"
                     :: "r"(sdst[u]), "l"(gsrc[u]) : "memory");
    asm volatile("cp.async.commit_group;" ::: "memory");

    for (int c = 0; c < NC; c++) {
        if (c + 1 < NC) {
            uint32_t nst = (uint32_t)((c + 1) & 1) * 65536u;
            int ke = (c + 1) << 6;
#pragma unroll
            for (int u = 0; u < 16; u++)
                asm volatile("cp.async.cg.shared.global [%0], [%1], 16;"
                             :: "r"(sdst[u] + nst), "l"(gsrc[u] + ke) : "memory");
            asm volatile("cp.async.commit_group;" ::: "memory");
            asm volatile("cp.async.wait_group 1;" ::: "memory");
        } else {
            asm volatile("cp.async.wait_group 0;" ::: "memory");
        }
        __syncthreads();

        uint32_t st = (uint32_t)(c & 1) * 65536u;
        uint32_t tAh = tiles + st, tAl = tAh + 16384u;
        uint32_t tBh = tAl + 16384u, tBl = tBh + 16384u;
#pragma unroll
        for (int ks = 0; ks < 4; ks++) {
            int k0 = ks * 16;
            uint32_t ah[8], al[8], bb[16];
#pragma unroll
            for (int mi = 0; mi < 2; mi++)
                ldsA(&ah[mi * 4], tAh, wm * 32 + mi * 16, k0, lane);
#pragma unroll
            for (int nb = 0; nb < 4; nb++)
                ldsB(&bb[nb * 4], tBh, wn * 64 + nb * 16, k0, lane);
#pragma unroll
            for (int mi = 0; mi < 2; mi++)
#pragma unroll
                for (int ni = 0; ni < 8; ni++)
                    mma_bf16(acc[mi][ni], &ah[mi * 4], &bb[ni * 2]);
#pragma unroll
            for (int mi = 0; mi < 2; mi++)
                ldsA(&al[mi * 4], tAl, wm * 32 + mi * 16, k0, lane);
#pragma unroll
            for (int mi = 0; mi < 2; mi++)
#pragma unroll
                for (int ni = 0; ni < 8; ni++)
                    mma_bf16(acc[mi][ni], &al[mi * 4], &bb[ni * 2]);
#pragma unroll
            for (int nb = 0; nb < 4; nb++)
                ldsB(&bb[nb * 4], tBl, wn * 64 + nb * 16, k0, lane);
#pragma unroll
            for (int mi = 0; mi < 2; mi++)
#pragma unroll
                for (int ni = 0; ni < 8; ni++)
                    mma_bf16(acc[mi][ni], &ah[mi * 4], &bb[ni * 2]);
        }
        __syncthreads();
    }

    // epilogue: C frag mapping: d0,d1 -> (row=lane>>2, col=(lane&3)*2 {,+1});
    //           d2,d3 -> row+8
    const int r0 = lane >> 2, c0 = (lane & 3) * 2;
#pragma unroll
    for (int mi = 0; mi < 2; mi++) {
        int gm = bm + wm * 32 + mi * 16;
#pragma unroll
        for (int ni = 0; ni < 8; ni++) {
            int gn = bn + wn * 64 + ni * 8;
            float* p0 = C + (size_t)(gm + r0) * N + gn + c0;
            float* p1 = C + (size_t)(gm + r0 + 8) * N + gn + c0;
            *(float2*)p0 = make_float2(acc[mi][ni][0], acc[mi][ni][1]);
            *(float2*)p1 = make_float2(acc[mi][ni][2], acc[mi][ni][3]);
        }
    }
}

// ---------------------------------------------------------------------------
// Fused flash-attention with Transformer-XL relative-position shift (fp32).
// Grid: (S/64, H). 256 threads. Dynamic smem ~138 KB.
// ---------------------------------------------------------------------------
__global__ __launch_bounds__(256, 1) void flash_xl(const float* __restrict__ u_vec,
                                                   const float* __restrict__ v_vec)
{
    extern __shared__ float sm[];
    float* sQUt = sm;              // [64 d][68]  (q+u), d-major
    float* sQVt = sQUt + 64 * 68;  // [64 d][68]  (q+v), d-major
    float* sKt  = sQVt + 64 * 68;  // [64 d][68]  k, d-major
    float* sV   = sKt  + 64 * 68;  // [64 j][68]  v, row-major
    float* sRt  = sV   + 64 * 68;  // [64 d][132] pos band, d-major, 128 t's
    float* sS   = sRt  + 64 * 132; // [64 i][65]  scores
    float* sPt  = sS   + 64 * 65;  // [64 j][68]  exp probs, j-major
    float* rowM = sPt  + 64 * 68;  // [64]
    float* rowL = rowM + 64;       // [64]
    float* rowC = rowL + 64;       // [64]

    const int h   = blockIdx.y;
    const int i0  = blockIdx.x * 64;
    const int tid = threadIdx.x;
    const int tx  = tid & 15, ty  = tid >> 4;
    const int tx2 = tid & 31, ty2 = tid >> 5;

    for (int idx = tid; idx < 64 * 16; idx += 256) {
        int i = idx >> 4, cg = (idx & 15) << 2;
        float4 q4 = *(const float4*)&g_qkv[(size_t)(i0 + i) * QKV_LD + h * HD + cg];
        float4 u4 = *(const float4*)&u_vec[h * HD + cg];
        float4 v4 = *(const float4*)&v_vec[h * HD + cg];
        sQUt[(cg + 0) * 68 + i] = q4.x + u4.x;
        sQUt[(cg + 1) * 68 + i] = q4.y + u4.y;
        sQUt[(cg + 2) * 68 + i] = q4.z + u4.z;
        sQUt[(cg + 3) * 68 + i] = q4.w + u4.w;
        sQVt[(cg + 0) * 68 + i] = q4.x + v4.x;
        sQVt[(cg + 1) * 68 + i] = q4.y + v4.y;
        sQVt[(cg + 2) * 68 + i] = q4.z + v4.z;
        sQVt[(cg + 3) * 68 + i] = q4.w + v4.w;
    }
    if (tid < 64) { rowM[tid] = -1e30f; rowL[tid] = 0.f; }

    float o[4][4];
#pragma unroll
    for (int r = 0; r < 4; r++)
#pragma unroll
        for (int c = 0; c < 4; c++) o[r][c] = 0.f;

    for (int j0 = 0; j0 <= i0; j0 += 64) {
        __syncthreads();

        for (int idx = tid; idx < 64 * 16; idx += 256) {
            int j = idx >> 4, cg = (idx & 15) << 2;
            float4 k4 = *(const float4*)&g_qkv[(size_t)(j0 + j) * QKV_LD + V_DIM + h * HD + cg];
            sKt[(cg + 0) * 68 + j] = k4.x;
            sKt[(cg + 1) * 68 + j] = k4.y;
            sKt[(cg + 2) * 68 + j] = k4.z;
            sKt[(cg + 3) * 68 + j] = k4.w;
            float4 v4 = *(const float4*)&g_qkv[(size_t)(j0 + j) * QKV_LD + 2 * V_DIM + h * HD + cg];
            *(float4*)&sV[j * 68 + cg] = v4;
        }
        const int mbase = j0 - i0 + S_LEN - 64;
        for (int idx = tid; idx < 128 * 16; idx += 256) {
            int t = idx >> 4, cg = (idx & 15) << 2;
            int m = mbase + t; if (m >= S_LEN) m -= S_LEN;
            float4 r4 = *(const float4*)&g_pos[(size_t)m * V_DIM + h * HD + cg];
            sRt[(cg + 0) * 132 + t] = r4.x;
            sRt[(cg + 1) * 132 + t] = r4.y;
            sRt[(cg + 2) * 132 + t] = r4.z;
            sRt[(cg + 3) * 132 + t] = r4.w;
        }
        __syncthreads();

        // GEMM1: content scores
        {
            float acc[4][4];
#pragma unroll
            for (int r = 0; r < 4; r++)
#pragma unroll
                for (int c = 0; c < 4; c++) acc[r][c] = 0.f;
#pragma unroll 8
            for (int d = 0; d < 64; d++) {
                float a[4], b[4];
                *(float4*)a = *(float4*)&sQUt[d * 68 + ty * 4];
                *(float4*)b = *(float4*)&sKt [d * 68 + tx * 4];
#pragma unroll
                for (int r = 0; r < 4; r++)
#pragma unroll
                    for (int c = 0; c < 4; c++) acc[r][c] += a[r] * b[c];
            }
#pragma unroll
            for (int r = 0; r < 4; r++)
#pragma unroll
                for (int c = 0; c < 4; c++)
                    sS[(ty * 4 + r) * 65 + tx * 4 + c] = acc[r][c] * SCALE;
        }
        __syncthreads();

        // GEMM2: position band + diagonal scatter
        {
            float acc[8][4];
#pragma unroll
            for (int r = 0; r < 8; r++)
#pragma unroll
                for (int c = 0; c < 4; c++) acc[r][c] = 0.f;
#pragma unroll 4
            for (int d = 0; d < 64; d++) {
                float a[8], b[4];
                *(float4*)&a[0] = *(float4*)&sQVt[d * 68 + ty2 * 8];
                *(float4*)&a[4] = *(float4*)&sQVt[d * 68 + ty2 * 8 + 4];
                *(float4*)b     = *(float4*)&sRt [d * 132 + tx2 * 4];
#pragma unroll
                for (int r = 0; r < 8; r++)
#pragma unroll
                    for (int c = 0; c < 4; c++) acc[r][c] += a[r] * b[c];
            }
#pragma unroll
            for (int r = 0; r < 8; r++) {
                int i = ty2 * 8 + r;
#pragma unroll
                for (int c = 0; c < 4; c++) {
                    int t = tx2 * 4 + c;
                    int j = t + i - 63;
                    if ((unsigned)j < 64u)
                        sS[i * 65 + j] += acc[r][c] * SCALE;
                }
            }
        }
        __syncthreads();

        // online softmax: 4 threads per row + shfl reductions
        {
            const int i = tid >> 2, sub = tid & 3;
            const int jmax = min(63, i0 + i - j0);
            float mOld = rowM[i], mNew = mOld;
#pragma unroll
            for (int jj = 0; jj < 16; jj++) {
                int j = jj * 4 + sub;
                if (j <= jmax) mNew = fmaxf(mNew, sS[i * 65 + j]);
            }
            mNew = fmaxf(mNew, __shfl_xor_sync(0xffffffffu, mNew, 1));
            mNew = fmaxf(mNew, __shfl_xor_sync(0xffffffffu, mNew, 2));
            float l = 0.f;
#pragma unroll
            for (int jj = 0; jj < 16; jj++) {
                int j = jj * 4 + sub;
                float p = (j <= jmax) ? __expf(sS[i * 65 + j] - mNew) : 0.f;
                sPt[j * 68 + i] = p;
                l += p;
            }
            l += __shfl_xor_sync(0xffffffffu, l, 1);
            l += __shfl_xor_sync(0xffffffffu, l, 2);
            if (sub == 0) {
                float corr = __expf(mOld - mNew);
                rowC[i] = corr;
                rowL[i] = rowL[i] * corr + l;
                rowM[i] = mNew;
            }
        }
        __syncthreads();

        // rescale O and GEMM3
        {
            float cr[4];
#pragma unroll
            for (int r = 0; r < 4; r++) cr[r] = rowC[ty * 4 + r];
#pragma unroll
            for (int r = 0; r < 4; r++)
#pragma unroll
                for (int c = 0; c < 4; c++) o[r][c] *= cr[r];
#pragma unroll 8
            for (int j = 0; j < 64; j++) {
                float a[4], b[4];
                *(float4*)a = *(float4*)&sPt[j * 68 + ty * 4];
                *(float4*)b = *(float4*)&sV [j * 68 + tx * 4];
#pragma unroll
                for (int r = 0; r < 4; r++)
#pragma unroll
                    for (int c = 0; c < 4; c++) o[r][c] += a[r] * b[c];
            }
        }
    }

    float invl[4];
#pragma unroll
    for (int r = 0; r < 4; r++) invl[r] = 1.f / rowL[ty * 4 + r];
#pragma unroll
    for (int r = 0; r < 4; r++)
#pragma unroll
        for (int c = 0; c < 4; c++)
            g_attn[(size_t)(i0 + ty * 4 + r) * V_DIM + h * HD + tx * 4 + c] =
                o[r][c] * invl[r];
}

// ---------------------------------------------------------------------------
extern "C" void kernel_launch(void* const* d_in, const int* in_sizes, int n_in,
                              void* d_out, int out_size)
{
    const float* x    = (const float*)d_in[0];
    const float* Wqkv = (const float*)d_in[1];
    const float* Wout = (const float*)d_in[2];
    const float* Wpos = (const float*)d_in[3];
    const float* u    = (const float*)d_in[4];
    const float* v    = (const float*)d_in[5];
    const float* rel  = (const float*)d_in[6];
    float* out = (float*)d_out;

    void *pqkv, *ppos, *pattn;
    cudaGetSymbolAddress(&pqkv,  g_qkv);
    cudaGetSymbolAddress(&ppos,  g_pos);
    cudaGetSymbolAddress(&pattn, g_attn);
    void *xh, *xl, *wqh, *wql, *rh, *rl, *wph, *wpl, *ah, *al, *woh, *wol;
    cudaGetSymbolAddress(&xh,  g_xh);  cudaGetSymbolAddress(&xl,  g_xl);
    cudaGetSymbolAddress(&wqh, g_wqh); cudaGetSymbolAddress(&wql, g_wql);
    cudaGetSymbolAddress(&rh,  g_rh);  cudaGetSymbolAddress(&rl,  g_rl);
    cudaGetSymbolAddress(&wph, g_wph); cudaGetSymbolAddress(&wpl, g_wpl);
    cudaGetSymbolAddress(&ah,  g_ah);  cudaGetSymbolAddress(&al,  g_al);
    cudaGetSymbolAddress(&woh, g_woh); cudaGetSymbolAddress(&wol, g_wol);

    const int flash_smem = 34560 * (int)sizeof(float);
    cudaFuncSetAttribute(flash_xl, cudaFuncAttributeMaxDynamicSharedMemorySize,
                         flash_smem);
    cudaFuncSetAttribute(gemm_bf16x3, cudaFuncAttributeMaxDynamicSharedMemorySize,
                         GEMM_SMEM);

    const int n_x  = S_LEN * V_DIM  / 4;   // float4 counts
    const int n_wq = QKV_LD * V_DIM / 4;
    const int n_w  = V_DIM * V_DIM  / 4;

    split_bf16<<<(n_x  + 255) / 256, 256>>>((const float4*)x,    (__nv_bfloat16*)xh,  (__nv_bfloat16*)xl,  n_x);
    split_bf16<<<(n_wq + 255) / 256, 256>>>((const float4*)Wqkv, (__nv_bfloat16*)wqh, (__nv_bfloat16*)wql, n_wq);
    split_bf16<<<(n_x  + 255) / 256, 256>>>((const float4*)rel,  (__nv_bfloat16*)rh,  (__nv_bfloat16*)rl,  n_x);
    split_bf16<<<(n_w  + 255) / 256, 256>>>((const float4*)Wpos, (__nv_bfloat16*)wph, (__nv_bfloat16*)wpl, n_w);
    split_bf16<<<(n_w  + 255) / 256, 256>>>((const float4*)Wout, (__nv_bfloat16*)woh, (__nv_bfloat16*)wol, n_w);

    // qkv = x @ Wqkv^T   [2048,3072]
    gemm_bf16x3<<<dim3(QKV_LD / 128, S_LEN / 128), 256, GEMM_SMEM>>>(
        (const __nv_bfloat16*)xh, (const __nv_bfloat16*)xl,
        (const __nv_bfloat16*)wqh, (const __nv_bfloat16*)wql,
        (float*)pqkv, S_LEN, QKV_LD, V_DIM);
    // pos = rel @ Wpos^T [2048,1024]
    gemm_bf16x3<<<dim3(V_DIM / 128, S_LEN / 128), 256, GEMM_SMEM>>>(
        (const __nv_bfloat16*)rh, (const __nv_bfloat16*)rl,
        (const __nv_bfloat16*)wph, (const __nv_bfloat16*)wpl,
        (float*)ppos, S_LEN, V_DIM, V_DIM);
    // fused attention -> g_attn
    flash_xl<<<dim3(S_LEN / 64, NH), 256, flash_smem>>>(u, v);
    // split attn, then out = attn @ Wout^T
    split_bf16<<<(n_x + 255) / 256, 256>>>((const float4*)pattn,
                                           (__nv_bfloat16*)ah, (__nv_bfloat16*)al, n_x);
    gemm_bf16x3<<<dim3(V_DIM / 128, S_LEN / 128), 256, GEMM_SMEM>>>(
        (const __nv_bfloat16*)ah, (const __nv_bfloat16*)al,
        (const __nv_bfloat16*)woh, (const __nv_bfloat16*)wol,
        out, S_LEN, V_DIM, V_DIM);
}

// round 4
// speedup vs baseline: 2.5493x; 1.5249x over previous
#include <cuda_runtime.h>
#include <cuda_bf16.h>
#include <cstdint>

#define S_LEN 2048
#define V_DIM 1024
#define NH    16
#define HD    64
#define QKV_LD 3072
#define SCALE 0.125f

// ---------------- scratch (__device__ globals; no allocation allowed) ------
__device__ float g_qkv[S_LEN * QKV_LD];   // [S][3V]: q | k | v
__device__ float g_pos[S_LEN * V_DIM];    // rel_embed @ W_pos^T
__device__ float g_attn[S_LEN * V_DIM];   // attention output, head-concat

// bf16 split buffers (hi/lo) for projection GEMMs
__device__ __nv_bfloat16 g_xh[S_LEN * V_DIM],  g_xl[S_LEN * V_DIM];
__device__ __nv_bfloat16 g_wqh[QKV_LD * V_DIM], g_wql[QKV_LD * V_DIM];
__device__ __nv_bfloat16 g_rh[S_LEN * V_DIM],  g_rl[S_LEN * V_DIM];
__device__ __nv_bfloat16 g_wph[V_DIM * V_DIM], g_wpl[V_DIM * V_DIM];
__device__ __nv_bfloat16 g_ah[S_LEN * V_DIM],  g_al[S_LEN * V_DIM];
__device__ __nv_bfloat16 g_woh[V_DIM * V_DIM], g_wol[V_DIM * V_DIM];

// ---------------- helpers ---------------------------------------------------
__device__ __forceinline__ uint32_t s2u(const void* p) {
    uint32_t a;
    asm("{ .reg .u64 t; cvta.to.shared.u64 t, %1; cvt.u32.u64 %0, t; }"
        : "=r"(a) : "l"(p));
    return a;
}
__device__ __forceinline__ void ldm4(uint32_t* f, uint32_t addr) {
    asm volatile("ldmatrix.sync.aligned.m8n8.x4.shared.b16 {%0,%1,%2,%3}, [%4];"
                 : "=r"(f[0]), "=r"(f[1]), "=r"(f[2]), "=r"(f[3]) : "r"(addr));
}
__device__ __forceinline__ void ldm4t(uint32_t* f, uint32_t addr) {
    asm volatile("ldmatrix.sync.aligned.m8n8.x4.trans.shared.b16 {%0,%1,%2,%3}, [%4];"
                 : "=r"(f[0]), "=r"(f[1]), "=r"(f[2]), "=r"(f[3]) : "r"(addr));
}
__device__ __forceinline__ void mma_bf16(float* d, const uint32_t* a,
                                         const uint32_t* b) {
    asm volatile(
        "mma.sync.aligned.m16n8k16.row.col.f32.bf16.bf16.f32 "
        "{%0,%1,%2,%3}, {%4,%5,%6,%7}, {%8,%9}, {%0,%1,%2,%3};"
        : "+f"(d[0]), "+f"(d[1]), "+f"(d[2]), "+f"(d[3])
        : "r"(a[0]), "r"(a[1]), "r"(a[2]), "r"(a[3]), "r"(b[0]), "r"(b[1]));
}
// A fragment m16k16 at (m0,k0); tile rows of 128B, XOR-swizzled 16B chunks
__device__ __forceinline__ void ldsA(uint32_t* f, uint32_t tile, int m0, int k0,
                                     int lane) {
    int r = lane & 7, g = lane >> 3;
    int row = m0 + r + (g & 1) * 8;
    int kch = (k0 >> 3) + (g >> 1);
    ldm4(f, tile + row * 128 + (((kch ^ (row & 7)) & 7) << 4));
}
// B fragments (two n8k16) at (n0,k0) from [n][k] row-major storage
__device__ __forceinline__ void ldsB(uint32_t* f, uint32_t tile, int n0, int k0,
                                     int lane) {
    int r = lane & 7, g = lane >> 3;
    int row = n0 + r + (g >> 1) * 8;
    int kch = (k0 >> 3) + (g & 1);
    ldm4(f, tile + row * 128 + (((kch ^ (row & 7)) & 7) << 4));
}
// B fragments (two n8k16) at (n0,k0) from [k][n] row-major storage (trans)
__device__ __forceinline__ void ldsBT(uint32_t* f, uint32_t tile, int n0, int k0,
                                      int lane) {
    int r = lane & 7, g = lane >> 3;
    int row = k0 + r + (g & 1) * 8;
    int bch = (n0 + (g >> 1) * 8) >> 3;   // 16B chunk index of byte col
    ldm4t(f, tile + row * 128 + (((bch ^ (row & 7)) & 7) << 4));
}
// split two floats into packed-bf16 hi and lo words
__device__ __forceinline__ void split2(float a, float b, uint32_t& hi,
                                       uint32_t& lo) {
    __nv_bfloat16 ah = __float2bfloat16(a), bh = __float2bfloat16(b);
    __nv_bfloat16 al = __float2bfloat16(a - __bfloat162float(ah));
    __nv_bfloat16 bl = __float2bfloat16(b - __bfloat162float(bh));
    hi = (uint32_t)*(uint16_t*)&ah | ((uint32_t)*(uint16_t*)&bh << 16);
    lo = (uint32_t)*(uint16_t*)&al | ((uint32_t)*(uint16_t*)&bl << 16);
}

// ---------------- split fp32 -> bf16 hi/lo (for projection GEMMs) ----------
__global__ __launch_bounds__(256) void split_bf16(const float4* __restrict__ x,
                                                  __nv_bfloat16* __restrict__ h,
                                                  __nv_bfloat16* __restrict__ l,
                                                  int n4)
{
    int i = blockIdx.x * 256 + threadIdx.x;
    if (i >= n4) return;
    float4 v = x[i];
    uint32_t h0, l0, h1, l1;
    split2(v.x, v.y, h0, l0);
    split2(v.z, v.w, h1, l1);
    uint32_t* H = (uint32_t*)h;
    uint32_t* L = (uint32_t*)l;
    H[2 * i] = h0; H[2 * i + 1] = h1;
    L[2 * i] = l0; L[2 * i + 1] = l1;
}

// ---------------------------------------------------------------------------
// C[M,N] = A[M,K] * B[N,K]^T  via mma.sync bf16, x3 split (fp32 accuracy).
// ---------------------------------------------------------------------------
#define GEMM_SMEM (2 * 65536 + 1024)

__global__ __launch_bounds__(256, 1) void gemm_bf16x3(
    const __nv_bfloat16* __restrict__ Ah, const __nv_bfloat16* __restrict__ Al,
    const __nv_bfloat16* __restrict__ Bh, const __nv_bfloat16* __restrict__ Bl,
    float* __restrict__ C, int M, int N, int K)
{
    extern __shared__ char smem[];
    uint32_t tiles = (s2u(smem) + 1023u) & ~1023u;
    const int tid = threadIdx.x;
    const int lane = tid & 31, wid = tid >> 5;
    const int wm = wid & 3, wn = wid >> 2;
    const int bn = blockIdx.x * 128, bm = blockIdx.y * 128;

    const __nv_bfloat16* gsrc[16];
    uint32_t sdst[16];
#pragma unroll
    for (int u = 0; u < 16; u++) {
        int idx = u * 256 + tid;
        int tile = idx >> 10, row = (idx >> 3) & 127, cc = idx & 7;
        const __nv_bfloat16* bp = (tile == 0) ? Ah : (tile == 1) ? Al
                                 : (tile == 2) ? Bh : Bl;
        int gr = ((tile < 2) ? bm : bn) + row;
        gsrc[u] = bp + (size_t)gr * K + cc * 8;
        sdst[u] = tiles + tile * 16384u + row * 128u
                + (uint32_t)((cc ^ (row & 7)) << 4);
    }
    const int NC = K >> 6;

    float acc[2][8][4];
#pragma unroll
    for (int mi = 0; mi < 2; mi++)
#pragma unroll
        for (int ni = 0; ni < 8; ni++)
#pragma unroll
            for (int q = 0; q < 4; q++) acc[mi][ni][q] = 0.f;

#pragma unroll
    for (int u = 0; u < 16; u++)
        asm volatile("cp.async.cg.shared.global [%0], [%1], 16;"
                     :: "r"(sdst[u]), "l"(gsrc[u]) : "memory");
    asm volatile("cp.async.commit_group;" ::: "memory");

    for (int c = 0; c < NC; c++) {
        if (c + 1 < NC) {
            uint32_t nst = (uint32_t)((c + 1) & 1) * 65536u;
            int ke = (c + 1) << 6;
#pragma unroll
            for (int u = 0; u < 16; u++)
                asm volatile("cp.async.cg.shared.global [%0], [%1], 16;"
                             :: "r"(sdst[u] + nst), "l"(gsrc[u] + ke) : "memory");
            asm volatile("cp.async.commit_group;" ::: "memory");
            asm volatile("cp.async.wait_group 1;" ::: "memory");
        } else {
            asm volatile("cp.async.wait_group 0;" ::: "memory");
        }
        __syncthreads();

        uint32_t st = (uint32_t)(c & 1) * 65536u;
        uint32_t tAh = tiles + st, tAl = tAh + 16384u;
        uint32_t tBh = tAl + 16384u, tBl = tBh + 16384u;
#pragma unroll
        for (int ks = 0; ks < 4; ks++) {
            int k0 = ks * 16;
            uint32_t ah[8], al[8], bb[16];
#pragma unroll
            for (int mi = 0; mi < 2; mi++)
                ldsA(&ah[mi * 4], tAh, wm * 32 + mi * 16, k0, lane);
#pragma unroll
            for (int nb = 0; nb < 4; nb++)
                ldsB(&bb[nb * 4], tBh, wn * 64 + nb * 16, k0, lane);
#pragma unroll
            for (int mi = 0; mi < 2; mi++)
#pragma unroll
                for (int ni = 0; ni < 8; ni++)
                    mma_bf16(acc[mi][ni], &ah[mi * 4], &bb[ni * 2]);
#pragma unroll
            for (int mi = 0; mi < 2; mi++)
                ldsA(&al[mi * 4], tAl, wm * 32 + mi * 16, k0, lane);
#pragma unroll
            for (int mi = 0; mi < 2; mi++)
#pragma unroll
                for (int ni = 0; ni < 8; ni++)
                    mma_bf16(acc[mi][ni], &al[mi * 4], &bb[ni * 2]);
#pragma unroll
            for (int nb = 0; nb < 4; nb++)
                ldsB(&bb[nb * 4], tBl, wn * 64 + nb * 16, k0, lane);
#pragma unroll
            for (int mi = 0; mi < 2; mi++)
#pragma unroll
                for (int ni = 0; ni < 8; ni++)
                    mma_bf16(acc[mi][ni], &ah[mi * 4], &bb[ni * 2]);
        }
        __syncthreads();
    }

    const int r0 = lane >> 2, c0 = (lane & 3) * 2;
#pragma unroll
    for (int mi = 0; mi < 2; mi++) {
        int gm = bm + wm * 32 + mi * 16;
#pragma unroll
        for (int ni = 0; ni < 8; ni++) {
            int gn = bn + wn * 64 + ni * 8;
            float* p0 = C + (size_t)(gm + r0) * N + gn + c0;
            float* p1 = C + (size_t)(gm + r0 + 8) * N + gn + c0;
            *(float2*)p0 = make_float2(acc[mi][ni][0], acc[mi][ni][1]);
            *(float2*)p1 = make_float2(acc[mi][ni][2], acc[mi][ni][3]);
        }
    }
}

// ---------------------------------------------------------------------------
// Fused flash-attention, Transformer-XL shift, tensor-core version.
// Grid (32, 16), 256 threads (8 warps). smem ~129 KB, 1 CTA/SM.
// Warp (s = wid>>1, nh = wid&1): rows s*16..s*16+15, n-half nh.
// ---------------------------------------------------------------------------
// smem offsets (bytes)
#define oQUh 0
#define oQUl 8192
#define oQVh 16384
#define oQVl 24576
#define oKh  32768
#define oKl  40960
#define oVh  49152
#define oVl  57344
#define oRh  65536
#define oRl  81920
#define oS   98304              /* fp32 [64][66] = 16896 B */
#define oPh  115200
#define oPl  123392
#define oRow 131584             /* rowM[64], rowL[64], rowC[64] fp32 */
#define FL_SMEM (131584 + 768)

__global__ __launch_bounds__(256, 1) void flash_xl_mma(
    const float* __restrict__ u_vec, const float* __restrict__ v_vec)
{
    extern __shared__ char fsm[];
    const uint32_t base = s2u(fsm);
    float* sS   = (float*)(fsm + oS);
    float* rowM = (float*)(fsm + oRow);
    float* rowL = rowM + 64;
    float* rowC = rowL + 64;

    const int h   = blockIdx.y;
    const int i0  = (int)(gridDim.x - 1 - blockIdx.x) * 64;  // heavy tiles first
    const int tid = threadIdx.x;
    const int lane = tid & 31, wid = tid >> 5;
    const int m0 = (wid >> 1) * 16;       // warp row-strip
    const int nh = wid & 1;               // warp n-half
    const int fr = lane >> 2, fc = (lane & 3) * 2;  // mma C-frag row/col

    // ---- load QU/QV tiles (bf16 hi/lo, swizzled rows of 64 bf16) ----------
    for (int idx = tid; idx < 1024; idx += 256) {
        int i = idx >> 4, cg = (idx & 15) << 2;
        float4 q4 = *(const float4*)&g_qkv[(size_t)(i0 + i) * QKV_LD + h * HD + cg];
        float4 u4 = *(const float4*)&u_vec[h * HD + cg];
        float4 v4 = *(const float4*)&v_vec[h * HD + cg];
        uint32_t off = (uint32_t)(i * 128 + (((cg >> 3) ^ (i & 7)) << 4)
                                  + ((cg & 7) << 1));
        uint32_t h0, l0, h1, l1;
        split2(q4.x + u4.x, q4.y + u4.y, h0, l0);
        split2(q4.z + u4.z, q4.w + u4.w, h1, l1);
        *(uint32_t*)(fsm + oQUh + off) = h0; *(uint32_t*)(fsm + oQUh + off + 4) = h1;
        *(uint32_t*)(fsm + oQUl + off) = l0; *(uint32_t*)(fsm + oQUl + off + 4) = l1;
        split2(q4.x + v4.x, q4.y + v4.y, h0, l0);
        split2(q4.z + v4.z, q4.w + v4.w, h1, l1);
        *(uint32_t*)(fsm + oQVh + off) = h0; *(uint32_t*)(fsm + oQVh + off + 4) = h1;
        *(uint32_t*)(fsm + oQVl + off) = l0; *(uint32_t*)(fsm + oQVl + off + 4) = l1;
    }
    if (tid < 64) { rowM[tid] = -1e30f; rowL[tid] = 0.f; }

    float o[4][4];
#pragma unroll
    for (int nd = 0; nd < 4; nd++)
#pragma unroll
        for (int q = 0; q < 4; q++) o[nd][q] = 0.f;

    for (int j0 = 0; j0 <= i0; j0 += 64) {
        __syncthreads();   // (A) previous-iteration readers done

        // ---- fill K, V (row-major [j][d]) ---------------------------------
        for (int idx = tid; idx < 1024; idx += 256) {
            int j = idx >> 4, cg = (idx & 15) << 2;
            const float* kp = &g_qkv[(size_t)(j0 + j) * QKV_LD + V_DIM + h * HD + cg];
            float4 k4 = *(const float4*)kp;
            float4 v4 = *(const float4*)(kp + V_DIM);
            uint32_t off = (uint32_t)(j * 128 + (((cg >> 3) ^ (j & 7)) << 4)
                                      + ((cg & 7) << 1));
            uint32_t h0, l0, h1, l1;
            split2(k4.x, k4.y, h0, l0); split2(k4.z, k4.w, h1, l1);
            *(uint32_t*)(fsm + oKh + off) = h0; *(uint32_t*)(fsm + oKh + off + 4) = h1;
            *(uint32_t*)(fsm + oKl + off) = l0; *(uint32_t*)(fsm + oKl + off + 4) = l1;
            split2(v4.x, v4.y, h0, l0); split2(v4.z, v4.w, h1, l1);
            *(uint32_t*)(fsm + oVh + off) = h0; *(uint32_t*)(fsm + oVh + off + 4) = h1;
            *(uint32_t*)(fsm + oVl + off) = l0; *(uint32_t*)(fsm + oVl + off + 4) = l1;
        }
        // ---- fill position band R [t][d], t in [0,128) --------------------
        const int mbase = j0 - i0 + S_LEN - 64;
        for (int idx = tid; idx < 2048; idx += 256) {
            int t = idx >> 4, cg = (idx & 15) << 2;
            int m = mbase + t; if (m >= S_LEN) m -= S_LEN;
            float4 r4 = *(const float4*)&g_pos[(size_t)m * V_DIM + h * HD + cg];
            uint32_t off = (uint32_t)(t * 128 + (((cg >> 3) ^ (t & 7)) << 4)
                                      + ((cg & 7) << 1));
            uint32_t h0, l0, h1, l1;
            split2(r4.x, r4.y, h0, l0); split2(r4.z, r4.w, h1, l1);
            *(uint32_t*)(fsm + oRh + off) = h0; *(uint32_t*)(fsm + oRh + off + 4) = h1;
            *(uint32_t*)(fsm + oRl + off) = l0; *(uint32_t*)(fsm + oRl + off + 4) = l1;
        }
        __syncthreads();   // (B) tiles ready

        // ---- GEMM1: content scores (warp: 16 rows x 32 cols) --------------
        {
            float aS[2][2][4];
#pragma unroll
            for (int nb = 0; nb < 2; nb++)
#pragma unroll
                for (int hf = 0; hf < 2; hf++)
#pragma unroll
                    for (int q = 0; q < 4; q++) aS[nb][hf][q] = 0.f;
#pragma unroll
            for (int ks = 0; ks < 4; ks++) {
                int k0 = ks * 16;
                uint32_t ah[4], al[4];
                ldsA(ah, base + oQUh, m0, k0, lane);
                ldsA(al, base + oQUl, m0, k0, lane);
#pragma unroll
                for (int nb = 0; nb < 2; nb++) {
                    int n0 = nh * 32 + nb * 16;
                    uint32_t bh[4], bl[4];
                    ldsB(bh, base + oKh, n0, k0, lane);
                    ldsB(bl, base + oKl, n0, k0, lane);
                    mma_bf16(aS[nb][0], ah, bh); mma_bf16(aS[nb][1], ah, bh + 2);
                    mma_bf16(aS[nb][0], al, bh); mma_bf16(aS[nb][1], al, bh + 2);
                    mma_bf16(aS[nb][0], ah, bl); mma_bf16(aS[nb][1], ah, bl + 2);
                }
            }
#pragma unroll
            for (int nb = 0; nb < 2; nb++)
#pragma unroll
                for (int hf = 0; hf < 2; hf++)
#pragma unroll
                    for (int q = 0; q < 4; q++) {
                        int row = m0 + fr + (q >> 1) * 8;
                        int col = nh * 32 + nb * 16 + hf * 8 + fc + (q & 1);
                        sS[row * 66 + col] = aS[nb][hf][q] * SCALE;
                    }
        }

        // ---- GEMM2: position band (warp: 16 rows x 64 t's) ----------------
        float aT[4][2][4];
#pragma unroll
        for (int nb = 0; nb < 4; nb++)
#pragma unroll
            for (int hf = 0; hf < 2; hf++)
#pragma unroll
                for (int q = 0; q < 4; q++) aT[nb][hf][q] = 0.f;
#pragma unroll
        for (int ks = 0; ks < 4; ks++) {
            int k0 = ks * 16;
            uint32_t ah[4], al[4];
            ldsA(ah, base + oQVh, m0, k0, lane);
            ldsA(al, base + oQVl, m0, k0, lane);
#pragma unroll
            for (int nb = 0; nb < 4; nb++) {
                int n0 = nh * 64 + nb * 16;
                uint32_t bh[4], bl[4];
                ldsB(bh, base + oRh, n0, k0, lane);
                ldsB(bl, base + oRl, n0, k0, lane);
                mma_bf16(aT[nb][0], ah, bh); mma_bf16(aT[nb][1], ah, bh + 2);
                mma_bf16(aT[nb][0], al, bh); mma_bf16(aT[nb][1], al, bh + 2);
                mma_bf16(aT[nb][0], ah, bl); mma_bf16(aT[nb][1], ah, bl + 2);
            }
        }
        __syncthreads();   // (C) sS fully written by both halves

        // scatter band -> scores: j = t + i - 63
#pragma unroll
        for (int nb = 0; nb < 4; nb++)
#pragma unroll
            for (int hf = 0; hf < 2; hf++)
#pragma unroll
                for (int q = 0; q < 4; q++) {
                    int il = m0 + fr + (q >> 1) * 8;
                    int t  = nh * 64 + nb * 16 + hf * 8 + fc + (q & 1);
                    int j  = t + il - 63;
                    if ((unsigned)j < 64u)
                        sS[il * 66 + j] += aT[nb][hf][q] * SCALE;
                }
        __syncthreads();   // (D) scatter complete

        // ---- online softmax: 4 threads per row ----------------------------
        {
            const int il = tid >> 2, sub = tid & 3;
            const int jmax = (j0 == i0) ? il : 63;
            const float* srow = sS + il * 66;
            float mOld = rowM[il], mNew = mOld;
#pragma unroll
            for (int jj = 0; jj < 16; jj++) {
                int j = sub * 16 + jj;
                if (j <= jmax) mNew = fmaxf(mNew, srow[j]);
            }
            mNew = fmaxf(mNew, __shfl_xor_sync(0xffffffffu, mNew, 1));
            mNew = fmaxf(mNew, __shfl_xor_sync(0xffffffffu, mNew, 2));
            float lsum = 0.f;
#pragma unroll
            for (int c = 0; c < 2; c++) {
                int chunk = sub * 2 + c;
                uint32_t hpk[4], lpk[4];
#pragma unroll
                for (int pr = 0; pr < 4; pr++) {
                    int j = chunk * 8 + pr * 2;
                    float p0 = (j     <= jmax) ? __expf(srow[j]     - mNew) : 0.f;
                    float p1 = (j + 1 <= jmax) ? __expf(srow[j + 1] - mNew) : 0.f;
                    lsum += p0 + p1;
                    split2(p0, p1, hpk[pr], lpk[pr]);
                }
                uint32_t off = (uint32_t)(il * 128 + (((chunk ^ (il & 7)) & 7) << 4));
                *(uint4*)(fsm + oPh + off) = *(uint4*)hpk;
                *(uint4*)(fsm + oPl + off) = *(uint4*)lpk;
            }
            lsum += __shfl_xor_sync(0xffffffffu, lsum, 1);
            lsum += __shfl_xor_sync(0xffffffffu, lsum, 2);
            if (sub == 0) {
                float corr = __expf(mOld - mNew);
                rowC[il] = corr;
                rowL[il] = rowL[il] * corr + lsum;
                rowM[il] = mNew;
            }
        }
        __syncthreads();   // (E) P + rowC ready

        // ---- rescale O, GEMM3: O += P * V (warp: 16 rows x 32 d's) --------
        {
            float cr0 = rowC[m0 + fr], cr1 = rowC[m0 + fr + 8];
#pragma unroll
            for (int nd = 0; nd < 4; nd++) {
                o[nd][0] *= cr0; o[nd][1] *= cr0;
                o[nd][2] *= cr1; o[nd][3] *= cr1;
            }
#pragma unroll
            for (int ks = 0; ks < 4; ks++) {
                int k0 = ks * 16;
                uint32_t ah[4], al[4];
                ldsA(ah, base + oPh, m0, k0, lane);
                ldsA(al, base + oPl, m0, k0, lane);
#pragma unroll
                for (int nb = 0; nb < 2; nb++) {
                    int n0 = nh * 32 + nb * 16;
                    uint32_t bh[4], bl[4];
                    ldsBT(bh, base + oVh, n0, k0, lane);
                    ldsBT(bl, base + oVl, n0, k0, lane);
                    float* o0 = o[nb * 2 + 0];
                    float* o1 = o[nb * 2 + 1];
                    mma_bf16(o0, ah, bh); mma_bf16(o1, ah, bh + 2);
                    mma_bf16(o0, al, bh); mma_bf16(o1, al, bh + 2);
                    mma_bf16(o0, ah, bl); mma_bf16(o1, ah, bl + 2);
                }
            }
        }
    }

    // ---- epilogue: normalize and store -----------------------------------
    {
        int il0 = m0 + fr, il1 = il0 + 8;
        float inv0 = 1.f / rowL[il0];
        float inv1 = 1.f / rowL[il1];
#pragma unroll
        for (int nd = 0; nd < 4; nd++) {
            int col = h * HD + nh * 32 + nd * 8 + fc;
            *(float2*)&g_attn[(size_t)(i0 + il0) * V_DIM + col] =
                make_float2(o[nd][0] * inv0, o[nd][1] * inv0);
            *(float2*)&g_attn[(size_t)(i0 + il1) * V_DIM + col] =
                make_float2(o[nd][2] * inv1, o[nd][3] * inv1);
        }
    }
}

// ---------------------------------------------------------------------------
extern "C" void kernel_launch(void* const* d_in, const int* in_sizes, int n_in,
                              void* d_out, int out_size)
{
    const float* x    = (const float*)d_in[0];
    const float* Wqkv = (const float*)d_in[1];
    const float* Wout = (const float*)d_in[2];
    const float* Wpos = (const float*)d_in[3];
    const float* u    = (const float*)d_in[4];
    const float* v    = (const float*)d_in[5];
    const float* rel  = (const float*)d_in[6];
    float* out = (float*)d_out;

    void *pqkv, *ppos, *pattn;
    cudaGetSymbolAddress(&pqkv,  g_qkv);
    cudaGetSymbolAddress(&ppos,  g_pos);
    cudaGetSymbolAddress(&pattn, g_attn);
    void *xh, *xl, *wqh, *wql, *rh, *rl, *wph, *wpl, *ah, *al, *woh, *wol;
    cudaGetSymbolAddress(&xh,  g_xh);  cudaGetSymbolAddress(&xl,  g_xl);
    cudaGetSymbolAddress(&wqh, g_wqh); cudaGetSymbolAddress(&wql, g_wql);
    cudaGetSymbolAddress(&rh,  g_rh);  cudaGetSymbolAddress(&rl,  g_rl);
    cudaGetSymbolAddress(&wph, g_wph); cudaGetSymbolAddress(&wpl, g_wpl);
    cudaGetSymbolAddress(&ah,  g_ah);  cudaGetSymbolAddress(&al,  g_al);
    cudaGetSymbolAddress(&woh, g_woh); cudaGetSymbolAddress(&wol, g_wol);

    cudaFuncSetAttribute(flash_xl_mma,
                         cudaFuncAttributeMaxDynamicSharedMemorySize, FL_SMEM);
    cudaFuncSetAttribute(gemm_bf16x3,
                         cudaFuncAttributeMaxDynamicSharedMemorySize, GEMM_SMEM);

    const int n_x  = S_LEN * V_DIM  / 4;
    const int n_wq = QKV_LD * V_DIM / 4;
    const int n_w  = V_DIM * V_DIM  / 4;

    split_bf16<<<(n_x  + 255) / 256, 256>>>((const float4*)x,    (__nv_bfloat16*)xh,  (__nv_bfloat16*)xl,  n_x);
    split_bf16<<<(n_wq + 255) / 256, 256>>>((const float4*)Wqkv, (__nv_bfloat16*)wqh, (__nv_bfloat16*)wql, n_wq);
    split_bf16<<<(n_x  + 255) / 256, 256>>>((const float4*)rel,  (__nv_bfloat16*)rh,  (__nv_bfloat16*)rl,  n_x);
    split_bf16<<<(n_w  + 255) / 256, 256>>>((const float4*)Wpos, (__nv_bfloat16*)wph, (__nv_bfloat16*)wpl, n_w);
    split_bf16<<<(n_w  + 255) / 256, 256>>>((const float4*)Wout, (__nv_bfloat16*)woh, (__nv_bfloat16*)wol, n_w);

    gemm_bf16x3<<<dim3(QKV_LD / 128, S_LEN / 128), 256, GEMM_SMEM>>>(
        (const __nv_bfloat16*)xh, (const __nv_bfloat16*)xl,
        (const __nv_bfloat16*)wqh, (const __nv_bfloat16*)wql,
        (float*)pqkv, S_LEN, QKV_LD, V_DIM);
    gemm_bf16x3<<<dim3(V_DIM / 128, S_LEN / 128), 256, GEMM_SMEM>>>(
        (const __nv_bfloat16*)rh, (const __nv_bfloat16*)rl,
        (const __nv_bfloat16*)wph, (const __nv_bfloat16*)wpl,
        (float*)ppos, S_LEN, V_DIM, V_DIM);

    flash_xl_mma<<<dim3(S_LEN / 64, NH), 256, FL_SMEM>>>(u, v);

    split_bf16<<<(n_x + 255) / 256, 256>>>((const float4*)pattn,
                                           (__nv_bfloat16*)ah, (__nv_bfloat16*)al, n_x);
    gemm_bf16x3<<<dim3(V_DIM / 128, S_LEN / 128), 256, GEMM_SMEM>>>(
        (const __nv_bfloat16*)ah, (const __nv_bfloat16*)al,
        (const __nv_bfloat16*)woh, (const __nv_bfloat16*)wol,
        out, S_LEN, V_DIM, V_DIM);
}

// round 5
// speedup vs baseline: 3.3461x; 1.3126x over previous
#include <cuda_runtime.h>
#include <cuda_bf16.h>
#include <cstdint>

#define S_LEN 2048
#define V_DIM 1024
#define NH    16
#define HD    64
#define QKV_LD 3072
#define SCALE 0.125f

// ---------------- scratch (__device__ globals; no allocation allowed) ------
__device__ float g_qkv[S_LEN * QKV_LD];   // [S][3V]: q | k | v
__device__ float g_pos[S_LEN * V_DIM];    // rel_embed @ W_pos^T
__device__ float g_attn[S_LEN * V_DIM];   // attention output, head-concat

// bf16 split buffers (hi/lo) for projection GEMMs
__device__ __nv_bfloat16 g_xh[S_LEN * V_DIM],  g_xl[S_LEN * V_DIM];
__device__ __nv_bfloat16 g_wqh[QKV_LD * V_DIM], g_wql[QKV_LD * V_DIM];
__device__ __nv_bfloat16 g_rh[S_LEN * V_DIM],  g_rl[S_LEN * V_DIM];
__device__ __nv_bfloat16 g_wph[V_DIM * V_DIM], g_wpl[V_DIM * V_DIM];
__device__ __nv_bfloat16 g_ah[S_LEN * V_DIM],  g_al[S_LEN * V_DIM];
__device__ __nv_bfloat16 g_woh[V_DIM * V_DIM], g_wol[V_DIM * V_DIM];

// per-head bf16 hi/lo tensors for flash: layout [H][S][64]
#define HSD (NH * S_LEN * HD)
__device__ __nv_bfloat16 g_quh[HSD], g_qul[HSD];   // q + u
__device__ __nv_bfloat16 g_qvh[HSD], g_qvl[HSD];   // q + v
__device__ __nv_bfloat16 g_kh[HSD],  g_kl[HSD];
__device__ __nv_bfloat16 g_vh[HSD],  g_vl[HSD];
__device__ __nv_bfloat16 g_rph[HSD], g_rpl[HSD];   // pos

// ---------------- helpers ---------------------------------------------------
__device__ __forceinline__ uint32_t s2u(const void* p) {
    uint32_t a;
    asm("{ .reg .u64 t; cvta.to.shared.u64 t, %1; cvt.u32.u64 %0, t; }"
        : "=r"(a) : "l"(p));
    return a;
}
__device__ __forceinline__ void ldm4(uint32_t* f, uint32_t addr) {
    asm volatile("ldmatrix.sync.aligned.m8n8.x4.shared.b16 {%0,%1,%2,%3}, [%4];"
                 : "=r"(f[0]), "=r"(f[1]), "=r"(f[2]), "=r"(f[3]) : "r"(addr));
}
__device__ __forceinline__ void ldm4t(uint32_t* f, uint32_t addr) {
    asm volatile("ldmatrix.sync.aligned.m8n8.x4.trans.shared.b16 {%0,%1,%2,%3}, [%4];"
                 : "=r"(f[0]), "=r"(f[1]), "=r"(f[2]), "=r"(f[3]) : "r"(addr));
}
__device__ __forceinline__ void mma_bf16(float* d, const uint32_t* a,
                                         const uint32_t* b) {
    asm volatile(
        "mma.sync.aligned.m16n8k16.row.col.f32.bf16.bf16.f32 "
        "{%0,%1,%2,%3}, {%4,%5,%6,%7}, {%8,%9}, {%0,%1,%2,%3};"
        : "+f"(d[0]), "+f"(d[1]), "+f"(d[2]), "+f"(d[3])
        : "r"(a[0]), "r"(a[1]), "r"(a[2]), "r"(a[3]), "r"(b[0]), "r"(b[1]));
}
__device__ __forceinline__ void ldsA(uint32_t* f, uint32_t tile, int m0, int k0,
                                     int lane) {
    int r = lane & 7, g = lane >> 3;
    int row = m0 + r + (g & 1) * 8;
    int kch = (k0 >> 3) + (g >> 1);
    ldm4(f, tile + row * 128 + (((kch ^ (row & 7)) & 7) << 4));
}
__device__ __forceinline__ void ldsB(uint32_t* f, uint32_t tile, int n0, int k0,
                                     int lane) {
    int r = lane & 7, g = lane >> 3;
    int row = n0 + r + (g >> 1) * 8;
    int kch = (k0 >> 3) + (g & 1);
    ldm4(f, tile + row * 128 + (((kch ^ (row & 7)) & 7) << 4));
}
__device__ __forceinline__ void ldsBT(uint32_t* f, uint32_t tile, int n0, int k0,
                                      int lane) {
    int r = lane & 7, g = lane >> 3;
    int row = k0 + r + (g & 1) * 8;
    int bch = (n0 + (g >> 1) * 8) >> 3;
    ldm4t(f, tile + row * 128 + (((bch ^ (row & 7)) & 7) << 4));
}
__device__ __forceinline__ void split2(float a, float b, uint32_t& hi,
                                       uint32_t& lo) {
    __nv_bfloat16 ah = __float2bfloat16(a), bh = __float2bfloat16(b);
    __nv_bfloat16 al = __float2bfloat16(a - __bfloat162float(ah));
    __nv_bfloat16 bl = __float2bfloat16(b - __bfloat162float(bh));
    hi = (uint32_t)*(uint16_t*)&ah | ((uint32_t)*(uint16_t*)&bh << 16);
    lo = (uint32_t)*(uint16_t*)&al | ((uint32_t)*(uint16_t*)&bl << 16);
}
__device__ __forceinline__ void write8(__nv_bfloat16* ph, __nv_bfloat16* pl,
                                       const float* f) {
    uint32_t hw[4], lw[4];
#pragma unroll
    for (int i = 0; i < 4; i++) split2(f[2 * i], f[2 * i + 1], hw[i], lw[i]);
    *(uint4*)ph = *(uint4*)hw;
    *(uint4*)pl = *(uint4*)lw;
}
#define CP16(dst, src)                                                         \
    asm volatile("cp.async.cg.shared.global [%0], [%1], 16;"                   \
                 :: "r"(dst), "l"(src) : "memory")

// ---------------- split fp32 -> bf16 hi/lo (projection GEMM inputs) --------
__global__ __launch_bounds__(256) void split_bf16(const float4* __restrict__ x,
                                                  __nv_bfloat16* __restrict__ h,
                                                  __nv_bfloat16* __restrict__ l,
                                                  int n4)
{
    int i = blockIdx.x * 256 + threadIdx.x;
    if (i >= n4) return;
    float4 v = x[i];
    uint32_t h0, l0, h1, l1;
    split2(v.x, v.y, h0, l0);
    split2(v.z, v.w, h1, l1);
    uint32_t* H = (uint32_t*)h;
    uint32_t* L = (uint32_t*)l;
    H[2 * i] = h0; H[2 * i + 1] = h1;
    L[2 * i] = l0; L[2 * i + 1] = l1;
}

// ---------------- per-head split kernels for flash -------------------------
__global__ __launch_bounds__(256) void split_heads_qkv(
    const float* __restrict__ u_vec, const float* __restrict__ v_vec)
{
    int idx = blockIdx.x * 256 + threadIdx.x;     // NH*S_LEN*8 total
    int h = idx >> 14, rem = idx & 16383;
    int s = rem >> 3, d0 = (rem & 7) * 8;
    const float* qp = g_qkv + (size_t)s * QKV_LD + h * HD + d0;
    float q[8], k[8], vv[8], t[8];
    *(float4*)&q[0]  = *(const float4*)qp;
    *(float4*)&q[4]  = *(const float4*)(qp + 4);
    *(float4*)&k[0]  = *(const float4*)(qp + V_DIM);
    *(float4*)&k[4]  = *(const float4*)(qp + V_DIM + 4);
    *(float4*)&vv[0] = *(const float4*)(qp + 2 * V_DIM);
    *(float4*)&vv[4] = *(const float4*)(qp + 2 * V_DIM + 4);
    const float* up = u_vec + h * HD + d0;
    const float* vp = v_vec + h * HD + d0;
    size_t o = ((size_t)h * S_LEN + s) * HD + d0;
#pragma unroll
    for (int i = 0; i < 8; i++) t[i] = q[i] + up[i];
    write8(g_quh + o, g_qul + o, t);
#pragma unroll
    for (int i = 0; i < 8; i++) t[i] = q[i] + vp[i];
    write8(g_qvh + o, g_qvl + o, t);
    write8(g_kh + o, g_kl + o, k);
    write8(g_vh + o, g_vl + o, vv);
}

__global__ __launch_bounds__(256) void split_heads_pos()
{
    int idx = blockIdx.x * 256 + threadIdx.x;
    int h = idx >> 14, rem = idx & 16383;
    int s = rem >> 3, d0 = (rem & 7) * 8;
    const float* pp = g_pos + (size_t)s * V_DIM + h * HD + d0;
    float r[8];
    *(float4*)&r[0] = *(const float4*)pp;
    *(float4*)&r[4] = *(const float4*)(pp + 4);
    size_t o = ((size_t)h * S_LEN + s) * HD + d0;
    write8(g_rph + o, g_rpl + o, r);
}

// ---------------------------------------------------------------------------
// C[M,N] = A[M,K] * B[N,K]^T  via mma.sync bf16, x3 split (fp32 accuracy).
// ---------------------------------------------------------------------------
#define GEMM_SMEM (2 * 65536 + 1024)

__global__ __launch_bounds__(256, 1) void gemm_bf16x3(
    const __nv_bfloat16* __restrict__ Ah, const __nv_bfloat16* __restrict__ Al,
    const __nv_bfloat16* __restrict__ Bh, const __nv_bfloat16* __restrict__ Bl,
    float* __restrict__ C, int M, int N, int K)
{
    extern __shared__ char smem[];
    uint32_t tiles = (s2u(smem) + 1023u) & ~1023u;
    const int tid = threadIdx.x;
    const int lane = tid & 31, wid = tid >> 5;
    const int wm = wid & 3, wn = wid >> 2;
    const int bn = blockIdx.x * 128, bm = blockIdx.y * 128;

    const __nv_bfloat16* gsrc[16];
    uint32_t sdst[16];
#pragma unroll
    for (int u = 0; u < 16; u++) {
        int idx = u * 256 + tid;
        int tile = idx >> 10, row = (idx >> 3) & 127, cc = idx & 7;
        const __nv_bfloat16* bp = (tile == 0) ? Ah : (tile == 1) ? Al
                                 : (tile == 2) ? Bh : Bl;
        int gr = ((tile < 2) ? bm : bn) + row;
        gsrc[u] = bp + (size_t)gr * K + cc * 8;
        sdst[u] = tiles + tile * 16384u + row * 128u
                + (uint32_t)((cc ^ (row & 7)) << 4);
    }
    const int NC = K >> 6;

    float acc[2][8][4];
#pragma unroll
    for (int mi = 0; mi < 2; mi++)
#pragma unroll
        for (int ni = 0; ni < 8; ni++)
#pragma unroll
            for (int q = 0; q < 4; q++) acc[mi][ni][q] = 0.f;

#pragma unroll
    for (int u = 0; u < 16; u++) CP16(sdst[u], gsrc[u]);
    asm volatile("cp.async.commit_group;" ::: "memory");

    for (int c = 0; c < NC; c++) {
        if (c + 1 < NC) {
            uint32_t nst = (uint32_t)((c + 1) & 1) * 65536u;
            int ke = (c + 1) << 6;
#pragma unroll
            for (int u = 0; u < 16; u++) CP16(sdst[u] + nst, gsrc[u] + ke);
            asm volatile("cp.async.commit_group;" ::: "memory");
            asm volatile("cp.async.wait_group 1;" ::: "memory");
        } else {
            asm volatile("cp.async.wait_group 0;" ::: "memory");
        }
        __syncthreads();

        uint32_t st = (uint32_t)(c & 1) * 65536u;
        uint32_t tAh = tiles + st, tAl = tAh + 16384u;
        uint32_t tBh = tAl + 16384u, tBl = tBh + 16384u;
#pragma unroll
        for (int ks = 0; ks < 4; ks++) {
            int k0 = ks * 16;
            uint32_t ah[8], al[8], bb[16];
#pragma unroll
            for (int mi = 0; mi < 2; mi++)
                ldsA(&ah[mi * 4], tAh, wm * 32 + mi * 16, k0, lane);
#pragma unroll
            for (int nb = 0; nb < 4; nb++)
                ldsB(&bb[nb * 4], tBh, wn * 64 + nb * 16, k0, lane);
#pragma unroll
            for (int mi = 0; mi < 2; mi++)
#pragma unroll
                for (int ni = 0; ni < 8; ni++)
                    mma_bf16(acc[mi][ni], &ah[mi * 4], &bb[ni * 2]);
#pragma unroll
            for (int mi = 0; mi < 2; mi++)
                ldsA(&al[mi * 4], tAl, wm * 32 + mi * 16, k0, lane);
#pragma unroll
            for (int mi = 0; mi < 2; mi++)
#pragma unroll
                for (int ni = 0; ni < 8; ni++)
                    mma_bf16(acc[mi][ni], &al[mi * 4], &bb[ni * 2]);
#pragma unroll
            for (int nb = 0; nb < 4; nb++)
                ldsB(&bb[nb * 4], tBl, wn * 64 + nb * 16, k0, lane);
#pragma unroll
            for (int mi = 0; mi < 2; mi++)
#pragma unroll
                for (int ni = 0; ni < 8; ni++)
                    mma_bf16(acc[mi][ni], &ah[mi * 4], &bb[ni * 2]);
        }
        __syncthreads();
    }

    const int r0 = lane >> 2, c0 = (lane & 3) * 2;
#pragma unroll
    for (int mi = 0; mi < 2; mi++) {
        int gm = bm + wm * 32 + mi * 16;
#pragma unroll
        for (int ni = 0; ni < 8; ni++) {
            int gn = bn + wn * 64 + ni * 8;
            float* p0 = C + (size_t)(gm + r0) * N + gn + c0;
            float* p1 = C + (size_t)(gm + r0 + 8) * N + gn + c0;
            *(float2*)p0 = make_float2(acc[mi][ni][0], acc[mi][ni][1]);
            *(float2*)p1 = make_float2(acc[mi][ni][2], acc[mi][ni][3]);
        }
    }
}

// ---------------------------------------------------------------------------
// Fused flash-attention, Transformer-XL shift, tensor-core + cp.async.
// Grid (32, 16), 256 threads (8 warps). smem ~193 KB, 1 CTA/SM.
// ---------------------------------------------------------------------------
#define oQUh 0
#define oQUl 8192
#define oQVh 16384
#define oQVl 24576
#define oST  32768          /* 2 stages x 65536: Kh,Kl,Vh,Vl(8K each),Rh,Rl(16K) */
#define oS   163840         /* fp32 [64][66] = 16896 B */
#define oPh  180736
#define oPl  188928
#define oRow 197120
#define FL_SMEM (197120 + 768)

__global__ __launch_bounds__(256, 1) void flash_xl_mma()
{
    extern __shared__ char fsm[];
    const uint32_t base = s2u(fsm);
    float* sS   = (float*)(fsm + oS);
    float* rowM = (float*)(fsm + oRow);
    float* rowL = rowM + 64;
    float* rowC = rowL + 64;

    const int h   = blockIdx.y;
    const int i0  = (int)(gridDim.x - 1 - blockIdx.x) * 64;  // heavy tiles first
    const int tid = threadIdx.x;
    const int lane = tid & 31, wid = tid >> 5;
    const int m0 = (wid >> 1) * 16;
    const int nh = wid & 1;
    const int fr = lane >> 2, fc = (lane & 3) * 2;

    const size_t hb = (size_t)h * (S_LEN * HD);
    const __nv_bfloat16* pQUh = g_quh + hb + (size_t)i0 * HD;
    const __nv_bfloat16* pQUl = g_qul + hb + (size_t)i0 * HD;
    const __nv_bfloat16* pQVh = g_qvh + hb + (size_t)i0 * HD;
    const __nv_bfloat16* pQVl = g_qvl + hb + (size_t)i0 * HD;
    const __nv_bfloat16* pKh  = g_kh  + hb;
    const __nv_bfloat16* pKl  = g_kl  + hb;
    const __nv_bfloat16* pVh  = g_vh  + hb;
    const __nv_bfloat16* pVl  = g_vl  + hb;
    const __nv_bfloat16* pRh  = g_rph + hb;
    const __nv_bfloat16* pRl  = g_rpl + hb;

    auto fill_kvr = [&](int jj0, int stg) {
        uint32_t so = base + oST + (uint32_t)stg * 65536u;
#pragma unroll
        for (int w = 0; w < 8; w++) {
            int t = w * 256 + tid;
            int tile = t >> 9;            // Kh,Kl,Vh,Vl
            int r = (t >> 3) & 63, c = t & 7;
            const __nv_bfloat16* gb =
                ((tile == 0) ? pKh : (tile == 1) ? pKl : (tile == 2) ? pVh : pVl)
                + (size_t)(jj0 + r) * HD + c * 8;
            uint32_t dst = so + (uint32_t)tile * 8192u
                         + (uint32_t)(r * 128 + (((c ^ (r & 7)) & 7) << 4));
            CP16(dst, gb);
        }
        int mb = jj0 - i0 + S_LEN - 64;
#pragma unroll
        for (int w = 0; w < 8; w++) {
            int t = w * 256 + tid;
            int tile = t >> 10;           // Rh, Rl
            int r = (t >> 3) & 127, c = t & 7;
            int m = mb + r; if (m >= S_LEN) m -= S_LEN;
            const __nv_bfloat16* gb = (tile ? pRl : pRh) + (size_t)m * HD + c * 8;
            uint32_t dst = so + 32768u + (uint32_t)tile * 16384u
                         + (uint32_t)(r * 128 + (((c ^ (r & 7)) & 7) << 4));
            CP16(dst, gb);
        }
    };

    // prologue: Q tiles + first K/V/R stage
#pragma unroll
    for (int w = 0; w < 8; w++) {
        int t = w * 256 + tid;
        int tile = t >> 9;               // QUh,QUl,QVh,QVl
        int r = (t >> 3) & 63, c = t & 7;
        const __nv_bfloat16* gb =
            ((tile == 0) ? pQUh : (tile == 1) ? pQUl : (tile == 2) ? pQVh : pQVl)
            + (size_t)r * HD + c * 8;
        uint32_t dst = base + (uint32_t)tile * 8192u
                     + (uint32_t)(r * 128 + (((c ^ (r & 7)) & 7) << 4));
        CP16(dst, gb);
    }
    fill_kvr(0, 0);
    asm volatile("cp.async.commit_group;" ::: "memory");

    if (tid < 64) { rowM[tid] = -1e30f; rowL[tid] = 0.f; }

    float o[4][4];
#pragma unroll
    for (int nd = 0; nd < 4; nd++)
#pragma unroll
        for (int q = 0; q < 4; q++) o[nd][q] = 0.f;

    const int nIt = i0 / 64 + 1;
    for (int c = 0; c < nIt; c++) {
        const int j0 = c * 64;
        if (c + 1 < nIt) {
            fill_kvr(j0 + 64, (c + 1) & 1);
            asm volatile("cp.async.commit_group;" ::: "memory");
            asm volatile("cp.async.wait_group 1;" ::: "memory");
        } else {
            asm volatile("cp.async.wait_group 0;" ::: "memory");
        }
        __syncthreads();   // (B) current tiles ready

        const uint32_t so = base + oST + (uint32_t)(c & 1) * 65536u;
        const uint32_t tKh = so,           tKl = so + 8192u;
        const uint32_t tVh = so + 16384u,  tVl = so + 24576u;
        const uint32_t tRh = so + 32768u,  tRl = so + 49152u;

        // ---- GEMM1: content scores (warp: 16 rows x 32 cols) --------------
        {
            float aS[2][2][4];
#pragma unroll
            for (int nb = 0; nb < 2; nb++)
#pragma unroll
                for (int hf = 0; hf < 2; hf++)
#pragma unroll
                    for (int q = 0; q < 4; q++) aS[nb][hf][q] = 0.f;
#pragma unroll
            for (int ks = 0; ks < 4; ks++) {
                int k0 = ks * 16;
                uint32_t ah[4], al[4];
                ldsA(ah, base + oQUh, m0, k0, lane);
                ldsA(al, base + oQUl, m0, k0, lane);
#pragma unroll
                for (int nb = 0; nb < 2; nb++) {
                    int n0 = nh * 32 + nb * 16;
                    uint32_t bh[4], bl[4];
                    ldsB(bh, tKh, n0, k0, lane);
                    ldsB(bl, tKl, n0, k0, lane);
                    mma_bf16(aS[nb][0], ah, bh); mma_bf16(aS[nb][1], ah, bh + 2);
                    mma_bf16(aS[nb][0], al, bh); mma_bf16(aS[nb][1], al, bh + 2);
                    mma_bf16(aS[nb][0], ah, bl); mma_bf16(aS[nb][1], ah, bl + 2);
                }
            }
#pragma unroll
            for (int nb = 0; nb < 2; nb++)
#pragma unroll
                for (int hf = 0; hf < 2; hf++)
#pragma unroll
                    for (int q = 0; q < 4; q++) {
                        int row = m0 + fr + (q >> 1) * 8;
                        int col = nh * 32 + nb * 16 + hf * 8 + fc + (q & 1);
                        sS[row * 66 + col] = aS[nb][hf][q] * SCALE;
                    }
        }

        // ---- GEMM2: position band, dead-block skipped ----------------------
        // valid t for this warp's rows: [48-m0, 126-m0]
        float aT[4][2][4];
#pragma unroll
        for (int nb = 0; nb < 4; nb++)
#pragma unroll
            for (int hf = 0; hf < 2; hf++)
#pragma unroll
                for (int q = 0; q < 4; q++) aT[nb][hf][q] = 0.f;
#pragma unroll
        for (int ks = 0; ks < 4; ks++) {
            int k0 = ks * 16;
            uint32_t ah[4], al[4];
            ldsA(ah, base + oQVh, m0, k0, lane);
            ldsA(al, base + oQVl, m0, k0, lane);
#pragma unroll
            for (int nb = 0; nb < 4; nb++) {
                int T0 = nh * 64 + nb * 16;
                if (T0 + 15 < 48 - m0 || T0 > 126 - m0) continue;
                uint32_t bh[4], bl[4];
                ldsB(bh, tRh, T0, k0, lane);
                ldsB(bl, tRl, T0, k0, lane);
                mma_bf16(aT[nb][0], ah, bh); mma_bf16(aT[nb][1], ah, bh + 2);
                mma_bf16(aT[nb][0], al, bh); mma_bf16(aT[nb][1], al, bh + 2);
                mma_bf16(aT[nb][0], ah, bl); mma_bf16(aT[nb][1], ah, bl + 2);
            }
        }
        __syncthreads();   // (C) sS fully written

        // scatter band -> scores: j = t + i - 63
#pragma unroll
        for (int nb = 0; nb < 4; nb++) {
            int T0 = nh * 64 + nb * 16;
            if (T0 + 15 < 48 - m0 || T0 > 126 - m0) continue;
#pragma unroll
            for (int hf = 0; hf < 2; hf++)
#pragma unroll
                for (int q = 0; q < 4; q++) {
                    int il = m0 + fr + (q >> 1) * 8;
                    int t  = T0 + hf * 8 + fc + (q & 1);
                    int j  = t + il - 63;
                    if ((unsigned)j < 64u)
                        sS[il * 66 + j] += aT[nb][hf][q] * SCALE;
                }
        }
        __syncthreads();   // (D) scatter complete

        // ---- online softmax: 4 threads per row ----------------------------
        {
            const int il = tid >> 2, sub = tid & 3;
            const int jmax = (j0 == i0) ? il : 63;
            const float* srow = sS + il * 66;
            float mOld = rowM[il], mNew = mOld;
#pragma unroll
            for (int jj = 0; jj < 16; jj++) {
                int j = sub * 16 + jj;
                if (j <= jmax) mNew = fmaxf(mNew, srow[j]);
            }
            mNew = fmaxf(mNew, __shfl_xor_sync(0xffffffffu, mNew, 1));
            mNew = fmaxf(mNew, __shfl_xor_sync(0xffffffffu, mNew, 2));
            float lsum = 0.f;
#pragma unroll
            for (int cc = 0; cc < 2; cc++) {
                int chunk = sub * 2 + cc;
                uint32_t hpk[4], lpk[4];
#pragma unroll
                for (int pr = 0; pr < 4; pr++) {
                    int j = chunk * 8 + pr * 2;
                    float p0 = (j     <= jmax) ? __expf(srow[j]     - mNew) : 0.f;
                    float p1 = (j + 1 <= jmax) ? __expf(srow[j + 1] - mNew) : 0.f;
                    lsum += p0 + p1;
                    split2(p0, p1, hpk[pr], lpk[pr]);
                }
                uint32_t off = (uint32_t)(il * 128 + (((chunk ^ (il & 7)) & 7) << 4));
                *(uint4*)(fsm + oPh + off) = *(uint4*)hpk;
                *(uint4*)(fsm + oPl + off) = *(uint4*)lpk;
            }
            lsum += __shfl_xor_sync(0xffffffffu, lsum, 1);
            lsum += __shfl_xor_sync(0xffffffffu, lsum, 2);
            if (sub == 0) {
                float corr = __expf(mOld - mNew);
                rowC[il] = corr;
                rowL[il] = rowL[il] * corr + lsum;
                rowM[il] = mNew;
            }
        }
        __syncthreads();   // (E) P + rowC ready

        // ---- rescale O, GEMM3: O += P * V ---------------------------------
        {
            float cr0 = rowC[m0 + fr], cr1 = rowC[m0 + fr + 8];
#pragma unroll
            for (int nd = 0; nd < 4; nd++) {
                o[nd][0] *= cr0; o[nd][1] *= cr0;
                o[nd][2] *= cr1; o[nd][3] *= cr1;
            }
#pragma unroll
            for (int ks = 0; ks < 4; ks++) {
                int k0 = ks * 16;
                uint32_t ah[4], al[4];
                ldsA(ah, base + oPh, m0, k0, lane);
                ldsA(al, base + oPl, m0, k0, lane);
#pragma unroll
                for (int nb = 0; nb < 2; nb++) {
                    int n0 = nh * 32 + nb * 16;
                    uint32_t bh[4], bl[4];
                    ldsBT(bh, tVh, n0, k0, lane);
                    ldsBT(bl, tVl, n0, k0, lane);
                    float* o0 = o[nb * 2 + 0];
                    float* o1 = o[nb * 2 + 1];
                    mma_bf16(o0, ah, bh); mma_bf16(o1, ah, bh + 2);
                    mma_bf16(o0, al, bh); mma_bf16(o1, al, bh + 2);
                    mma_bf16(o0, ah, bl); mma_bf16(o1, ah, bl + 2);
                }
            }
        }
        __syncthreads();   // (F) stage free for prefetch issued next iter
    }

    // ---- epilogue: normalize and store ------------------------------------
    {
        int il0 = m0 + fr, il1 = il0 + 8;
        float inv0 = 1.f / rowL[il0];
        float inv1 = 1.f / rowL[il1];
#pragma unroll
        for (int nd = 0; nd < 4; nd++) {
            int col = h * HD + nh * 32 + nd * 8 + fc;
            *(float2*)&g_attn[(size_t)(i0 + il0) * V_DIM + col] =
                make_float2(o[nd][0] * inv0, o[nd][1] * inv0);
            *(float2*)&g_attn[(size_t)(i0 + il1) * V_DIM + col] =
                make_float2(o[nd][2] * inv1, o[nd][3] * inv1);
        }
    }
}

// ---------------------------------------------------------------------------
extern "C" void kernel_launch(void* const* d_in, const int* in_sizes, int n_in,
                              void* d_out, int out_size)
{
    const float* x    = (const float*)d_in[0];
    const float* Wqkv = (const float*)d_in[1];
    const float* Wout = (const float*)d_in[2];
    const float* Wpos = (const float*)d_in[3];
    const float* u    = (const float*)d_in[4];
    const float* v    = (const float*)d_in[5];
    const float* rel  = (const float*)d_in[6];
    float* out = (float*)d_out;

    void *pqkv, *ppos, *pattn;
    cudaGetSymbolAddress(&pqkv,  g_qkv);
    cudaGetSymbolAddress(&ppos,  g_pos);
    cudaGetSymbolAddress(&pattn, g_attn);
    void *xh, *xl, *wqh, *wql, *rh, *rl, *wph, *wpl, *ah, *al, *woh, *wol;
    cudaGetSymbolAddress(&xh,  g_xh);  cudaGetSymbolAddress(&xl,  g_xl);
    cudaGetSymbolAddress(&wqh, g_wqh); cudaGetSymbolAddress(&wql, g_wql);
    cudaGetSymbolAddress(&rh,  g_rh);  cudaGetSymbolAddress(&rl,  g_rl);
    cudaGetSymbolAddress(&wph, g_wph); cudaGetSymbolAddress(&wpl, g_wpl);
    cudaGetSymbolAddress(&ah,  g_ah);  cudaGetSymbolAddress(&al,  g_al);
    cudaGetSymbolAddress(&woh, g_woh); cudaGetSymbolAddress(&wol, g_wol);

    cudaFuncSetAttribute(flash_xl_mma,
                         cudaFuncAttributeMaxDynamicSharedMemorySize, FL_SMEM);
    cudaFuncSetAttribute(gemm_bf16x3,
                         cudaFuncAttributeMaxDynamicSharedMemorySize, GEMM_SMEM);

    const int n_x  = S_LEN * V_DIM  / 4;
    const int n_wq = QKV_LD * V_DIM / 4;
    const int n_w  = V_DIM * V_DIM  / 4;

    split_bf16<<<(n_x  + 255) / 256, 256>>>((const float4*)x,    (__nv_bfloat16*)xh,  (__nv_bfloat16*)xl,  n_x);
    split_bf16<<<(n_wq + 255) / 256, 256>>>((const float4*)Wqkv, (__nv_bfloat16*)wqh, (__nv_bfloat16*)wql, n_wq);
    split_bf16<<<(n_x  + 255) / 256, 256>>>((const float4*)rel,  (__nv_bfloat16*)rh,  (__nv_bfloat16*)rl,  n_x);
    split_bf16<<<(n_w  + 255) / 256, 256>>>((const float4*)Wpos, (__nv_bfloat16*)wph, (__nv_bfloat16*)wpl, n_w);
    split_bf16<<<(n_w  + 255) / 256, 256>>>((const float4*)Wout, (__nv_bfloat16*)woh, (__nv_bfloat16*)wol, n_w);

    gemm_bf16x3<<<dim3(QKV_LD / 128, S_LEN / 128), 256, GEMM_SMEM>>>(
        (const __nv_bfloat16*)xh, (const __nv_bfloat16*)xl,
        (const __nv_bfloat16*)wqh, (const __nv_bfloat16*)wql,
        (float*)pqkv, S_LEN, QKV_LD, V_DIM);
    gemm_bf16x3<<<dim3(V_DIM / 128, S_LEN / 128), 256, GEMM_SMEM>>>(
        (const __nv_bfloat16*)rh, (const __nv_bfloat16*)rl,
        (const __nv_bfloat16*)wph, (const __nv_bfloat16*)wpl,
        (float*)ppos, S_LEN, V_DIM, V_DIM);

    // per-head bf16 hi/lo tensors for flash
    split_heads_qkv<<<NH * S_LEN * 8 / 256, 256>>>(u, v);
    split_heads_pos<<<NH * S_LEN * 8 / 256, 256>>>();

    flash_xl_mma<<<dim3(S_LEN / 64, NH), 256, FL_SMEM>>>();

    split_bf16<<<(n_x + 255) / 256, 256>>>((const float4*)pattn,
                                           (__nv_bfloat16*)ah, (__nv_bfloat16*)al, n_x);
    gemm_bf16x3<<<dim3(V_DIM / 128, S_LEN / 128), 256, GEMM_SMEM>>>(
        (const __nv_bfloat16*)ah, (const __nv_bfloat16*)al,
        (const __nv_bfloat16*)woh, (const __nv_bfloat16*)wol,
        out, S_LEN, V_DIM, V_DIM);
}

// round 6
// speedup vs baseline: 4.0309x; 1.2046x over previous
#include <cuda_runtime.h>
#include <cuda_bf16.h>
#include <cstdint>

#define S_LEN 2048
#define V_DIM 1024
#define NH    16
#define HD    64
#define QKV_LD 3072
#define SCALE 0.125f

// ---------------- scratch (__device__ globals; no allocation allowed) ------
__device__ float g_qkv[S_LEN * QKV_LD];   // [S][3V]: q | k | v
__device__ float g_pos[S_LEN * V_DIM];    // rel_embed @ W_pos^T

// bf16 split buffers (hi/lo) for projection GEMMs
__device__ __nv_bfloat16 g_xh[S_LEN * V_DIM],  g_xl[S_LEN * V_DIM];
__device__ __nv_bfloat16 g_wqh[QKV_LD * V_DIM], g_wql[QKV_LD * V_DIM];
__device__ __nv_bfloat16 g_rh[S_LEN * V_DIM],  g_rl[S_LEN * V_DIM];
__device__ __nv_bfloat16 g_wph[V_DIM * V_DIM], g_wpl[V_DIM * V_DIM];
__device__ __nv_bfloat16 g_ah[S_LEN * V_DIM],  g_al[S_LEN * V_DIM];
__device__ __nv_bfloat16 g_woh[V_DIM * V_DIM], g_wol[V_DIM * V_DIM];

// per-head bf16 hi/lo tensors for flash: layout [H][S][64]
#define HSD (NH * S_LEN * HD)
__device__ __nv_bfloat16 g_quh[HSD], g_qul[HSD];   // q + u
__device__ __nv_bfloat16 g_qvh[HSD], g_qvl[HSD];   // q + v
__device__ __nv_bfloat16 g_kh[HSD],  g_kl[HSD];
__device__ __nv_bfloat16 g_vh[HSD],  g_vl[HSD];
__device__ __nv_bfloat16 g_rph[HSD], g_rpl[HSD];   // pos

// ---------------- helpers ---------------------------------------------------
__device__ __forceinline__ uint32_t s2u(const void* p) {
    uint32_t a;
    asm("{ .reg .u64 t; cvta.to.shared.u64 t, %1; cvt.u32.u64 %0, t; }"
        : "=r"(a) : "l"(p));
    return a;
}
__device__ __forceinline__ void ldm4(uint32_t* f, uint32_t addr) {
    asm volatile("ldmatrix.sync.aligned.m8n8.x4.shared.b16 {%0,%1,%2,%3}, [%4];"
                 : "=r"(f[0]), "=r"(f[1]), "=r"(f[2]), "=r"(f[3]) : "r"(addr));
}
__device__ __forceinline__ void ldm4t(uint32_t* f, uint32_t addr) {
    asm volatile("ldmatrix.sync.aligned.m8n8.x4.trans.shared.b16 {%0,%1,%2,%3}, [%4];"
                 : "=r"(f[0]), "=r"(f[1]), "=r"(f[2]), "=r"(f[3]) : "r"(addr));
}
__device__ __forceinline__ void mma_bf16(float* d, const uint32_t* a,
                                         const uint32_t* b) {
    asm volatile(
        "mma.sync.aligned.m16n8k16.row.col.f32.bf16.bf16.f32 "
        "{%0,%1,%2,%3}, {%4,%5,%6,%7}, {%8,%9}, {%0,%1,%2,%3};"
        : "+f"(d[0]), "+f"(d[1]), "+f"(d[2]), "+f"(d[3])
        : "r"(a[0]), "r"(a[1]), "r"(a[2]), "r"(a[3]), "r"(b[0]), "r"(b[1]));
}
__device__ __forceinline__ void ldsA(uint32_t* f, uint32_t tile, int m0, int k0,
                                     int lane) {
    int r = lane & 7, g = lane >> 3;
    int row = m0 + r + (g & 1) * 8;
    int kch = (k0 >> 3) + (g >> 1);
    ldm4(f, tile + row * 128 + (((kch ^ (row & 7)) & 7) << 4));
}
__device__ __forceinline__ void ldsB(uint32_t* f, uint32_t tile, int n0, int k0,
                                     int lane) {
    int r = lane & 7, g = lane >> 3;
    int row = n0 + r + (g >> 1) * 8;
    int kch = (k0 >> 3) + (g & 1);
    ldm4(f, tile + row * 128 + (((kch ^ (row & 7)) & 7) << 4));
}
__device__ __forceinline__ void ldsBT(uint32_t* f, uint32_t tile, int n0, int k0,
                                      int lane) {
    int r = lane & 7, g = lane >> 3;
    int row = k0 + r + (g & 1) * 8;
    int bch = (n0 + (g >> 1) * 8) >> 3;
    ldm4t(f, tile + row * 128 + (((bch ^ (row & 7)) & 7) << 4));
}
__device__ __forceinline__ void split2(float a, float b, uint32_t& hi,
                                       uint32_t& lo) {
    __nv_bfloat16 ah = __float2bfloat16(a), bh = __float2bfloat16(b);
    __nv_bfloat16 al = __float2bfloat16(a - __bfloat162float(ah));
    __nv_bfloat16 bl = __float2bfloat16(b - __bfloat162float(bh));
    hi = (uint32_t)*(uint16_t*)&ah | ((uint32_t)*(uint16_t*)&bh << 16);
    lo = (uint32_t)*(uint16_t*)&al | ((uint32_t)*(uint16_t*)&bl << 16);
}
__device__ __forceinline__ void write8(__nv_bfloat16* ph, __nv_bfloat16* pl,
                                       const float* f) {
    uint32_t hw[4], lw[4];
#pragma unroll
    for (int i = 0; i < 4; i++) split2(f[2 * i], f[2 * i + 1], hw[i], lw[i]);
    *(uint4*)ph = *(uint4*)hw;
    *(uint4*)pl = *(uint4*)lw;
}
#define CP16(dst, src)                                                         \
    asm volatile("cp.async.cg.shared.global [%0], [%1], 16;"                   \
                 :: "r"(dst), "l"(src) : "memory")
#define PAIR_BAR(id)                                                           \
    asm volatile("bar.sync %0, 64;" :: "r"(id) : "memory")

// ---------------- split fp32 -> bf16 hi/lo (projection GEMM inputs) --------
__global__ __launch_bounds__(256) void split_bf16(const float4* __restrict__ x,
                                                  __nv_bfloat16* __restrict__ h,
                                                  __nv_bfloat16* __restrict__ l,
                                                  int n4)
{
    int i = blockIdx.x * 256 + threadIdx.x;
    if (i >= n4) return;
    float4 v = x[i];
    uint32_t h0, l0, h1, l1;
    split2(v.x, v.y, h0, l0);
    split2(v.z, v.w, h1, l1);
    uint32_t* H = (uint32_t*)h;
    uint32_t* L = (uint32_t*)l;
    H[2 * i] = h0; H[2 * i + 1] = h1;
    L[2 * i] = l0; L[2 * i + 1] = l1;
}

// ---------------- per-head split kernels for flash -------------------------
__global__ __launch_bounds__(256) void split_heads_qkv(
    const float* __restrict__ u_vec, const float* __restrict__ v_vec)
{
    int idx = blockIdx.x * 256 + threadIdx.x;
    int h = idx >> 14, rem = idx & 16383;
    int s = rem >> 3, d0 = (rem & 7) * 8;
    const float* qp = g_qkv + (size_t)s * QKV_LD + h * HD + d0;
    float q[8], k[8], vv[8], t[8];
    *(float4*)&q[0]  = *(const float4*)qp;
    *(float4*)&q[4]  = *(const float4*)(qp + 4);
    *(float4*)&k[0]  = *(const float4*)(qp + V_DIM);
    *(float4*)&k[4]  = *(const float4*)(qp + V_DIM + 4);
    *(float4*)&vv[0] = *(const float4*)(qp + 2 * V_DIM);
    *(float4*)&vv[4] = *(const float4*)(qp + 2 * V_DIM + 4);
    const float* up = u_vec + h * HD + d0;
    const float* vp = v_vec + h * HD + d0;
    size_t o = ((size_t)h * S_LEN + s) * HD + d0;
#pragma unroll
    for (int i = 0; i < 8; i++) t[i] = q[i] + up[i];
    write8(g_quh + o, g_qul + o, t);
#pragma unroll
    for (int i = 0; i < 8; i++) t[i] = q[i] + vp[i];
    write8(g_qvh + o, g_qvl + o, t);
    write8(g_kh + o, g_kl + o, k);
    write8(g_vh + o, g_vl + o, vv);
}

__global__ __launch_bounds__(256) void split_heads_pos()
{
    int idx = blockIdx.x * 256 + threadIdx.x;
    int h = idx >> 14, rem = idx & 16383;
    int s = rem >> 3, d0 = (rem & 7) * 8;
    const float* pp = g_pos + (size_t)s * V_DIM + h * HD + d0;
    float r[8];
    *(float4*)&r[0] = *(const float4*)pp;
    *(float4*)&r[4] = *(const float4*)(pp + 4);
    size_t o = ((size_t)h * S_LEN + s) * HD + d0;
    write8(g_rph + o, g_rpl + o, r);
}

// ---------------------------------------------------------------------------
// C[M,N] = A[M,K] * B[N,K]^T  via mma.sync bf16, x3 split (fp32 accuracy).
// ---------------------------------------------------------------------------
#define GEMM_SMEM (2 * 65536 + 1024)

__global__ __launch_bounds__(256, 1) void gemm_bf16x3(
    const __nv_bfloat16* __restrict__ Ah, const __nv_bfloat16* __restrict__ Al,
    const __nv_bfloat16* __restrict__ Bh, const __nv_bfloat16* __restrict__ Bl,
    float* __restrict__ C, int M, int N, int K)
{
    extern __shared__ char smem[];
    uint32_t tiles = (s2u(smem) + 1023u) & ~1023u;
    const int tid = threadIdx.x;
    const int lane = tid & 31, wid = tid >> 5;
    const int wm = wid & 3, wn = wid >> 2;
    const int bn = blockIdx.x * 128, bm = blockIdx.y * 128;

    const __nv_bfloat16* gsrc[16];
    uint32_t sdst[16];
#pragma unroll
    for (int u = 0; u < 16; u++) {
        int idx = u * 256 + tid;
        int tile = idx >> 10, row = (idx >> 3) & 127, cc = idx & 7;
        const __nv_bfloat16* bp = (tile == 0) ? Ah : (tile == 1) ? Al
                                 : (tile == 2) ? Bh : Bl;
        int gr = ((tile < 2) ? bm : bn) + row;
        gsrc[u] = bp + (size_t)gr * K + cc * 8;
        sdst[u] = tiles + tile * 16384u + row * 128u
                + (uint32_t)((cc ^ (row & 7)) << 4);
    }
    const int NC = K >> 6;

    float acc[2][8][4];
#pragma unroll
    for (int mi = 0; mi < 2; mi++)
#pragma unroll
        for (int ni = 0; ni < 8; ni++)
#pragma unroll
            for (int q = 0; q < 4; q++) acc[mi][ni][q] = 0.f;

#pragma unroll
    for (int u = 0; u < 16; u++) CP16(sdst[u], gsrc[u]);
    asm volatile("cp.async.commit_group;" ::: "memory");

    for (int c = 0; c < NC; c++) {
        if (c + 1 < NC) {
            uint32_t nst = (uint32_t)((c + 1) & 1) * 65536u;
            int ke = (c + 1) << 6;
#pragma unroll
            for (int u = 0; u < 16; u++) CP16(sdst[u] + nst, gsrc[u] + ke);
            asm volatile("cp.async.commit_group;" ::: "memory");
            asm volatile("cp.async.wait_group 1;" ::: "memory");
        } else {
            asm volatile("cp.async.wait_group 0;" ::: "memory");
        }
        __syncthreads();

        uint32_t st = (uint32_t)(c & 1) * 65536u;
        uint32_t tAh = tiles + st, tAl = tAh + 16384u;
        uint32_t tBh = tAl + 16384u, tBl = tBh + 16384u;
#pragma unroll
        for (int ks = 0; ks < 4; ks++) {
            int k0 = ks * 16;
            uint32_t ah[8], al[8], bb[16];
#pragma unroll
            for (int mi = 0; mi < 2; mi++)
                ldsA(&ah[mi * 4], tAh, wm * 32 + mi * 16, k0, lane);
#pragma unroll
            for (int nb = 0; nb < 4; nb++)
                ldsB(&bb[nb * 4], tBh, wn * 64 + nb * 16, k0, lane);
#pragma unroll
            for (int mi = 0; mi < 2; mi++)
#pragma unroll
                for (int ni = 0; ni < 8; ni++)
                    mma_bf16(acc[mi][ni], &ah[mi * 4], &bb[ni * 2]);
#pragma unroll
            for (int mi = 0; mi < 2; mi++)
                ldsA(&al[mi * 4], tAl, wm * 32 + mi * 16, k0, lane);
#pragma unroll
            for (int mi = 0; mi < 2; mi++)
#pragma unroll
                for (int ni = 0; ni < 8; ni++)
                    mma_bf16(acc[mi][ni], &al[mi * 4], &bb[ni * 2]);
#pragma unroll
            for (int nb = 0; nb < 4; nb++)
                ldsB(&bb[nb * 4], tBl, wn * 64 + nb * 16, k0, lane);
#pragma unroll
            for (int mi = 0; mi < 2; mi++)
#pragma unroll
                for (int ni = 0; ni < 8; ni++)
                    mma_bf16(acc[mi][ni], &ah[mi * 4], &bb[ni * 2]);
        }
        __syncthreads();
    }

    const int r0 = lane >> 2, c0 = (lane & 3) * 2;
#pragma unroll
    for (int mi = 0; mi < 2; mi++) {
        int gm = bm + wm * 32 + mi * 16;
#pragma unroll
        for (int ni = 0; ni < 8; ni++) {
            int gn = bn + wn * 64 + ni * 8;
            float* p0 = C + (size_t)(gm + r0) * N + gn + c0;
            float* p1 = C + (size_t)(gm + r0 + 8) * N + gn + c0;
            *(float2*)p0 = make_float2(acc[mi][ni][0], acc[mi][ni][1]);
            *(float2*)p1 = make_float2(acc[mi][ni][2], acc[mi][ni][3]);
        }
    }
}

// ---------------------------------------------------------------------------
// Fused flash-attention, Transformer-XL shift — register-resident pipeline.
// Grid (32, 16), 256 threads (8 warps). smem ~210.5 KB, 1 CTA/SM.
// Warp (strip = wid>>1, nh = wid&1): rows strip*16..+15, j/d-half nh.
// ---------------------------------------------------------------------------
#define oQUh 0
#define oQUl 8192
#define oQVh 16384
#define oQVl 24576
#define oST  32768          /* 2 stages x 65536: Kh,Kl,Vh,Vl(8K),Rh,Rl(16K) */
#define oT   163840         /* band fp32 [64][132] = 33792 B */
#define oPex 197632         /* P frag exchange: 8 warps x 2 KB */
#define oRow 214016         /* rowM[64] rowL[64] halfMax[128] halfSum[128] */
#define FL_SMEM 215552

__global__ __launch_bounds__(256, 1) void flash_xl_mma()
{
    extern __shared__ char fsm[];
    const uint32_t base = s2u(fsm);
    float* sT      = (float*)(fsm + oT);
    float* rowM    = (float*)(fsm + oRow);
    float* rowL    = rowM + 64;
    float* halfMax = rowL + 64;      // [2][64]
    float* halfSum = halfMax + 128;  // [2][64]

    const int h   = blockIdx.y;
    const int i0  = (int)(gridDim.x - 1 - blockIdx.x) * 64;  // heavy tiles first
    const int tid = threadIdx.x;
    const int lane = tid & 31, wid = tid >> 5;
    const int strip = wid >> 1, m0 = strip * 16;
    const int nh = wid & 1;
    const int fr = lane >> 2, fc = (lane & 3) * 2;
    const int il0 = m0 + fr, il1 = il0 + 8;
    const int barid = 1 + strip;

    const size_t hb = (size_t)h * (S_LEN * HD);
    const __nv_bfloat16* pQUh = g_quh + hb + (size_t)i0 * HD;
    const __nv_bfloat16* pQUl = g_qul + hb + (size_t)i0 * HD;
    const __nv_bfloat16* pQVh = g_qvh + hb + (size_t)i0 * HD;
    const __nv_bfloat16* pQVl = g_qvl + hb + (size_t)i0 * HD;
    const __nv_bfloat16* pKh  = g_kh  + hb;
    const __nv_bfloat16* pKl  = g_kl  + hb;
    const __nv_bfloat16* pVh  = g_vh  + hb;
    const __nv_bfloat16* pVl  = g_vl  + hb;
    const __nv_bfloat16* pRh  = g_rph + hb;
    const __nv_bfloat16* pRl  = g_rpl + hb;

    auto fill_kvr = [&](int jj0, int stg) {
        uint32_t so = base + oST + (uint32_t)stg * 65536u;
#pragma unroll
        for (int w = 0; w < 8; w++) {
            int t = w * 256 + tid;
            int tile = t >> 9;            // Kh,Kl,Vh,Vl
            int r = (t >> 3) & 63, c = t & 7;
            const __nv_bfloat16* gb =
                ((tile == 0) ? pKh : (tile == 1) ? pKl : (tile == 2) ? pVh : pVl)
                + (size_t)(jj0 + r) * HD + c * 8;
            uint32_t dst = so + (uint32_t)tile * 8192u
                         + (uint32_t)(r * 128 + (((c ^ (r & 7)) & 7) << 4));
            CP16(dst, gb);
        }
        int mb = jj0 - i0 + S_LEN - 64;
#pragma unroll
        for (int w = 0; w < 8; w++) {
            int t = w * 256 + tid;
            int tile = t >> 10;           // Rh, Rl
            int r = (t >> 3) & 127, c = t & 7;
            int m = mb + r; if (m >= S_LEN) m -= S_LEN;
            const __nv_bfloat16* gb = (tile ? pRl : pRh) + (size_t)m * HD + c * 8;
            uint32_t dst = so + 32768u + (uint32_t)tile * 16384u
                         + (uint32_t)(r * 128 + (((c ^ (r & 7)) & 7) << 4));
            CP16(dst, gb);
        }
    };

    // prologue: Q tiles + first K/V/R stage
#pragma unroll
    for (int w = 0; w < 8; w++) {
        int t = w * 256 + tid;
        int tile = t >> 9;               // QUh,QUl,QVh,QVl
        int r = (t >> 3) & 63, c = t & 7;
        const __nv_bfloat16* gb =
            ((tile == 0) ? pQUh : (tile == 1) ? pQUl : (tile == 2) ? pQVh : pQVl)
            + (size_t)r * HD + c * 8;
        uint32_t dst = base + (uint32_t)tile * 8192u
                     + (uint32_t)(r * 128 + (((c ^ (r & 7)) & 7) << 4));
        CP16(dst, gb);
    }
    fill_kvr(0, 0);
    asm volatile("cp.async.commit_group;" ::: "memory");

    if (tid < 64) { rowM[tid] = -1e30f; rowL[tid] = 0.f; }

    float o[4][4];
#pragma unroll
    for (int nd = 0; nd < 4; nd++)
#pragma unroll
        for (int q = 0; q < 4; q++) o[nd][q] = 0.f;

    const int nIt = i0 / 64 + 1;
    for (int c = 0; c < nIt; c++) {
        const int j0 = c * 64;
        if (c + 1 < nIt) {
            fill_kvr(j0 + 64, (c + 1) & 1);
            asm volatile("cp.async.commit_group;" ::: "memory");
            asm volatile("cp.async.wait_group 1;" ::: "memory");
        } else {
            asm volatile("cp.async.wait_group 0;" ::: "memory");
        }
        __syncthreads();   // (B) tiles ready + previous-iter readers done

        const uint32_t so = base + oST + (uint32_t)(c & 1) * 65536u;
        const uint32_t tKh = so,           tKl = so + 8192u;
        const uint32_t tVh = so + 16384u,  tVl = so + 24576u;
        const uint32_t tRh = so + 32768u,  tRl = so + 49152u;

        // ---- GEMM2: position band -> sT (fp32, no SCALE yet) ---------------
        {
            float aT[4][2][4];
#pragma unroll
            for (int nb = 0; nb < 4; nb++)
#pragma unroll
                for (int hf = 0; hf < 2; hf++)
#pragma unroll
                    for (int q = 0; q < 4; q++) aT[nb][hf][q] = 0.f;
#pragma unroll
            for (int ks = 0; ks < 4; ks++) {
                int k0 = ks * 16;
                uint32_t ah[4], al[4];
                ldsA(ah, base + oQVh, m0, k0, lane);
                ldsA(al, base + oQVl, m0, k0, lane);
#pragma unroll
                for (int nb = 0; nb < 4; nb++) {
                    int T0 = nh * 64 + nb * 16;
                    if (T0 + 15 < 48 - m0 || T0 > 126 - m0) continue;
                    uint32_t bh[4], bl[4];
                    ldsB(bh, tRh, T0, k0, lane);
                    ldsB(bl, tRl, T0, k0, lane);
                    mma_bf16(aT[nb][0], ah, bh); mma_bf16(aT[nb][1], ah, bh + 2);
                    mma_bf16(aT[nb][0], al, bh); mma_bf16(aT[nb][1], al, bh + 2);
                    mma_bf16(aT[nb][0], ah, bl); mma_bf16(aT[nb][1], ah, bl + 2);
                }
            }
#pragma unroll
            for (int nb = 0; nb < 4; nb++) {
                int T0 = nh * 64 + nb * 16;
                if (T0 + 15 < 48 - m0 || T0 > 126 - m0) continue;
#pragma unroll
                for (int hf = 0; hf < 2; hf++) {
                    int tc = T0 + hf * 8 + fc;
                    *(float2*)&sT[il0 * 132 + tc] =
                        make_float2(aT[nb][hf][0], aT[nb][hf][1]);
                    *(float2*)&sT[il1 * 132 + tc] =
                        make_float2(aT[nb][hf][2], aT[nb][hf][3]);
                }
            }
        }

        // ---- GEMM1: content scores -> registers ----------------------------
        float sF[2][2][4];
#pragma unroll
        for (int nb = 0; nb < 2; nb++)
#pragma unroll
            for (int hf = 0; hf < 2; hf++)
#pragma unroll
                for (int q = 0; q < 4; q++) sF[nb][hf][q] = 0.f;
#pragma unroll
        for (int ks = 0; ks < 4; ks++) {
            int k0 = ks * 16;
            uint32_t ah[4], al[4];
            ldsA(ah, base + oQUh, m0, k0, lane);
            ldsA(al, base + oQUl, m0, k0, lane);
#pragma unroll
            for (int nb = 0; nb < 2; nb++) {
                int n0 = nh * 32 + nb * 16;
                uint32_t bh[4], bl[4];
                ldsB(bh, tKh, n0, k0, lane);
                ldsB(bl, tKl, n0, k0, lane);
                mma_bf16(sF[nb][0], ah, bh); mma_bf16(sF[nb][1], ah, bh + 2);
                mma_bf16(sF[nb][0], al, bh); mma_bf16(sF[nb][1], al, bh + 2);
                mma_bf16(sF[nb][0], ah, bl); mma_bf16(sF[nb][1], ah, bl + 2);
            }
        }

        PAIR_BAR(barid);   // sT ready for this strip

        // ---- softmax (register scores + band LDS) --------------------------
        float mOld0 = rowM[il0], mOld1 = rowM[il1];
        float sv0[8], sv1[8];
        float mx0 = -1e30f, mx1 = -1e30f;
#pragma unroll
        for (int nb = 0; nb < 2; nb++)
#pragma unroll
            for (int hf = 0; hf < 2; hf++)
#pragma unroll
                for (int e = 0; e < 2; e++) {
                    int jc = nh * 32 + nb * 16 + hf * 8 + fc + e;
                    int idx = nb * 4 + hf * 2 + e;
                    float s0 = (sF[nb][hf][e]     + sT[il0 * 132 + jc - il0 + 63]) * SCALE;
                    float s1 = (sF[nb][hf][2 + e] + sT[il1 * 132 + jc - il1 + 63]) * SCALE;
                    if (j0 + jc > i0 + il0) s0 = -1e30f;
                    if (j0 + jc > i0 + il1) s1 = -1e30f;
                    sv0[idx] = s0; sv1[idx] = s1;
                    mx0 = fmaxf(mx0, s0); mx1 = fmaxf(mx1, s1);
                }
        mx0 = fmaxf(mx0, __shfl_xor_sync(0xffffffffu, mx0, 1));
        mx0 = fmaxf(mx0, __shfl_xor_sync(0xffffffffu, mx0, 2));
        mx1 = fmaxf(mx1, __shfl_xor_sync(0xffffffffu, mx1, 1));
        mx1 = fmaxf(mx1, __shfl_xor_sync(0xffffffffu, mx1, 2));
        if ((lane & 3) == 0) {
            halfMax[nh * 64 + il0] = mx0;
            halfMax[nh * 64 + il1] = mx1;
        }
        PAIR_BAR(barid);
        float mNew0 = fmaxf(mOld0, fmaxf(halfMax[il0], halfMax[64 + il0]));
        float mNew1 = fmaxf(mOld1, fmaxf(halfMax[il1], halfMax[64 + il1]));
        float corr0 = __expf(mOld0 - mNew0), corr1 = __expf(mOld1 - mNew1);
        float pv0[8], pv1[8];
        float rs0 = 0.f, rs1 = 0.f;
#pragma unroll
        for (int i = 0; i < 8; i++) {
            pv0[i] = __expf(sv0[i] - mNew0); rs0 += pv0[i];
            pv1[i] = __expf(sv1[i] - mNew1); rs1 += pv1[i];
        }
        uint32_t ph[2][4], pl[2][4];
#pragma unroll
        for (int nb = 0; nb < 2; nb++) {
            split2(pv0[nb * 4 + 0], pv0[nb * 4 + 1], ph[nb][0], pl[nb][0]);
            split2(pv1[nb * 4 + 0], pv1[nb * 4 + 1], ph[nb][1], pl[nb][1]);
            split2(pv0[nb * 4 + 2], pv0[nb * 4 + 3], ph[nb][2], pl[nb][2]);
            split2(pv1[nb * 4 + 2], pv1[nb * 4 + 3], ph[nb][3], pl[nb][3]);
        }
        rs0 += __shfl_xor_sync(0xffffffffu, rs0, 1);
        rs0 += __shfl_xor_sync(0xffffffffu, rs0, 2);
        rs1 += __shfl_xor_sync(0xffffffffu, rs1, 1);
        rs1 += __shfl_xor_sync(0xffffffffu, rs1, 2);
        if ((lane & 3) == 0) {
            halfSum[nh * 64 + il0] = rs0;
            halfSum[nh * 64 + il1] = rs1;
        }
        // publish my P-half frags for the pair partner
        {
            char* pw = fsm + oPex + (strip * 2 + nh) * 2048 + lane * 16;
            *(uint4*)(pw)        = *(uint4*)ph[0];
            *(uint4*)(pw + 512)  = *(uint4*)ph[1];
            *(uint4*)(pw + 1024) = *(uint4*)pl[0];
            *(uint4*)(pw + 1536) = *(uint4*)pl[1];
        }
        PAIR_BAR(barid);
        if (nh == 0 && (lane & 3) == 0) {
            rowM[il0] = mNew0;
            rowM[il1] = mNew1;
            rowL[il0] = rowL[il0] * corr0 + halfSum[il0] + halfSum[64 + il0];
            rowL[il1] = rowL[il1] * corr1 + halfSum[il1] + halfSum[64 + il1];
        }
        uint32_t qh[2][4], ql[2][4];
        {
            const char* pr = fsm + oPex + (strip * 2 + (nh ^ 1)) * 2048 + lane * 16;
            *(uint4*)qh[0] = *(const uint4*)(pr);
            *(uint4*)qh[1] = *(const uint4*)(pr + 512);
            *(uint4*)ql[0] = *(const uint4*)(pr + 1024);
            *(uint4*)ql[1] = *(const uint4*)(pr + 1536);
        }

        // ---- GEMM3: O = O*corr + P*V  (A frags from registers) -------------
#pragma unroll
        for (int nd = 0; nd < 4; nd++) {
            o[nd][0] *= corr0; o[nd][1] *= corr0;
            o[nd][2] *= corr1; o[nd][3] *= corr1;
        }
        auto chunk = [&](const uint32_t* ah, const uint32_t* al, int k0) {
#pragma unroll
            for (int nb2 = 0; nb2 < 2; nb2++) {
                uint32_t bh[4], bl[4];
                ldsBT(bh, tVh, nh * 32 + nb2 * 16, k0, lane);
                ldsBT(bl, tVl, nh * 32 + nb2 * 16, k0, lane);
                float* o0 = o[nb2 * 2 + 0];
                float* o1 = o[nb2 * 2 + 1];
                mma_bf16(o0, ah, bh); mma_bf16(o1, ah, bh + 2);
                mma_bf16(o0, al, bh); mma_bf16(o1, al, bh + 2);
                mma_bf16(o0, ah, bl); mma_bf16(o1, ah, bl + 2);
            }
        };
        if (nh == 0) {
            chunk(ph[0], pl[0], 0);  chunk(ph[1], pl[1], 16);
            chunk(qh[0], ql[0], 32); chunk(qh[1], ql[1], 48);
        } else {
            chunk(qh[0], ql[0], 0);  chunk(qh[1], ql[1], 16);
            chunk(ph[0], pl[0], 32); chunk(ph[1], pl[1], 48);
        }
        __syncthreads();   // (F) stage + sT free
    }

    // ---- epilogue: normalize, split to bf16 hi/lo, store -------------------
    {
        float inv0 = 1.f / rowL[il0];
        float inv1 = 1.f / rowL[il1];
#pragma unroll
        for (int nd = 0; nd < 4; nd++) {
            int col = h * HD + nh * 32 + nd * 8 + fc;
            uint32_t hh, ll;
            split2(o[nd][0] * inv0, o[nd][1] * inv0, hh, ll);
            size_t w = ((size_t)(i0 + il0) * V_DIM + col) >> 1;
            ((uint32_t*)g_ah)[w] = hh; ((uint32_t*)g_al)[w] = ll;
            split2(o[nd][2] * inv1, o[nd][3] * inv1, hh, ll);
            w = ((size_t)(i0 + il1) * V_DIM + col) >> 1;
            ((uint32_t*)g_ah)[w] = hh; ((uint32_t*)g_al)[w] = ll;
        }
    }
}

// ---------------------------------------------------------------------------
extern "C" void kernel_launch(void* const* d_in, const int* in_sizes, int n_in,
                              void* d_out, int out_size)
{
    const float* x    = (const float*)d_in[0];
    const float* Wqkv = (const float*)d_in[1];
    const float* Wout = (const float*)d_in[2];
    const float* Wpos = (const float*)d_in[3];
    const float* u    = (const float*)d_in[4];
    const float* v    = (const float*)d_in[5];
    const float* rel  = (const float*)d_in[6];
    float* out = (float*)d_out;

    void *pqkv, *ppos;
    cudaGetSymbolAddress(&pqkv, g_qkv);
    cudaGetSymbolAddress(&ppos, g_pos);
    void *xh, *xl, *wqh, *wql, *rh, *rl, *wph, *wpl, *ah, *al, *woh, *wol;
    cudaGetSymbolAddress(&xh,  g_xh);  cudaGetSymbolAddress(&xl,  g_xl);
    cudaGetSymbolAddress(&wqh, g_wqh); cudaGetSymbolAddress(&wql, g_wql);
    cudaGetSymbolAddress(&rh,  g_rh);  cudaGetSymbolAddress(&rl,  g_rl);
    cudaGetSymbolAddress(&wph, g_wph); cudaGetSymbolAddress(&wpl, g_wpl);
    cudaGetSymbolAddress(&ah,  g_ah);  cudaGetSymbolAddress(&al,  g_al);
    cudaGetSymbolAddress(&woh, g_woh); cudaGetSymbolAddress(&wol, g_wol);

    cudaFuncSetAttribute(flash_xl_mma,
                         cudaFuncAttributeMaxDynamicSharedMemorySize, FL_SMEM);
    cudaFuncSetAttribute(gemm_bf16x3,
                         cudaFuncAttributeMaxDynamicSharedMemorySize, GEMM_SMEM);

    const int n_x  = S_LEN * V_DIM  / 4;
    const int n_wq = QKV_LD * V_DIM / 4;
    const int n_w  = V_DIM * V_DIM  / 4;

    split_bf16<<<(n_x  + 255) / 256, 256>>>((const float4*)x,    (__nv_bfloat16*)xh,  (__nv_bfloat16*)xl,  n_x);
    split_bf16<<<(n_wq + 255) / 256, 256>>>((const float4*)Wqkv, (__nv_bfloat16*)wqh, (__nv_bfloat16*)wql, n_wq);
    split_bf16<<<(n_x  + 255) / 256, 256>>>((const float4*)rel,  (__nv_bfloat16*)rh,  (__nv_bfloat16*)rl,  n_x);
    split_bf16<<<(n_w  + 255) / 256, 256>>>((const float4*)Wpos, (__nv_bfloat16*)wph, (__nv_bfloat16*)wpl, n_w);
    split_bf16<<<(n_w  + 255) / 256, 256>>>((const float4*)Wout, (__nv_bfloat16*)woh, (__nv_bfloat16*)wol, n_w);

    gemm_bf16x3<<<dim3(QKV_LD / 128, S_LEN / 128), 256, GEMM_SMEM>>>(
        (const __nv_bfloat16*)xh, (const __nv_bfloat16*)xl,
        (const __nv_bfloat16*)wqh, (const __nv_bfloat16*)wql,
        (float*)pqkv, S_LEN, QKV_LD, V_DIM);
    gemm_bf16x3<<<dim3(V_DIM / 128, S_LEN / 128), 256, GEMM_SMEM>>>(
        (const __nv_bfloat16*)rh, (const __nv_bfloat16*)rl,
        (const __nv_bfloat16*)wph, (const __nv_bfloat16*)wpl,
        (float*)ppos, S_LEN, V_DIM, V_DIM);

    split_heads_qkv<<<NH * S_LEN * 8 / 256, 256>>>(u, v);
    split_heads_pos<<<NH * S_LEN * 8 / 256, 256>>>();

    // flash writes bf16 hi/lo of attn directly into g_ah/g_al
    flash_xl_mma<<<dim3(S_LEN / 64, NH), 256, FL_SMEM>>>();

    gemm_bf16x3<<<dim3(V_DIM / 128, S_LEN / 128), 256, GEMM_SMEM>>>(
        (const __nv_bfloat16*)ah, (const __nv_bfloat16*)al,
        (const __nv_bfloat16*)woh, (const __nv_bfloat16*)wol,
        out, S_LEN, V_DIM, V_DIM);
}

// round 7
// speedup vs baseline: 4.3771x; 1.0859x over previous
#include <cuda_runtime.h>
#include <cuda_bf16.h>
#include <cstdint>

#define S_LEN 2048
#define V_DIM 1024
#define NH    16
#define HD    64
#define QKV_LD 3072
#define SCALE 0.125f

// ---------------- scratch (__device__ globals; no allocation allowed) ------
// bf16 split buffers (hi/lo) for projection GEMMs
__device__ __align__(256) __nv_bfloat16 g_xh[S_LEN * V_DIM],  g_xl[S_LEN * V_DIM];
__device__ __align__(256) __nv_bfloat16 g_wqh[QKV_LD * V_DIM], g_wql[QKV_LD * V_DIM];
__device__ __align__(256) __nv_bfloat16 g_rh[S_LEN * V_DIM],  g_rl[S_LEN * V_DIM];
__device__ __align__(256) __nv_bfloat16 g_wph[V_DIM * V_DIM], g_wpl[V_DIM * V_DIM];
__device__ __align__(256) __nv_bfloat16 g_ah[S_LEN * V_DIM],  g_al[S_LEN * V_DIM];
__device__ __align__(256) __nv_bfloat16 g_woh[V_DIM * V_DIM], g_wol[V_DIM * V_DIM];

// per-head bf16 hi/lo tensors for flash: layout [H][S][64]
#define HSD (NH * S_LEN * HD)
__device__ __align__(256) __nv_bfloat16 g_quh[HSD], g_qul[HSD];   // q + u
__device__ __align__(256) __nv_bfloat16 g_qvh[HSD], g_qvl[HSD];   // q + v
__device__ __align__(256) __nv_bfloat16 g_kh[HSD],  g_kl[HSD];
__device__ __align__(256) __nv_bfloat16 g_vh[HSD],  g_vl[HSD];
__device__ __align__(256) __nv_bfloat16 g_rph[HSD], g_rpl[HSD];   // pos

// ---------------- helpers ---------------------------------------------------
__device__ __forceinline__ uint32_t s2u(const void* p) {
    uint32_t a;
    asm("{ .reg .u64 t; cvta.to.shared.u64 t, %1; cvt.u32.u64 %0, t; }"
        : "=r"(a) : "l"(p));
    return a;
}
__device__ __forceinline__ void ldm4(uint32_t* f, uint32_t addr) {
    asm volatile("ldmatrix.sync.aligned.m8n8.x4.shared.b16 {%0,%1,%2,%3}, [%4];"
                 : "=r"(f[0]), "=r"(f[1]), "=r"(f[2]), "=r"(f[3]) : "r"(addr));
}
__device__ __forceinline__ void ldm4t(uint32_t* f, uint32_t addr) {
    asm volatile("ldmatrix.sync.aligned.m8n8.x4.trans.shared.b16 {%0,%1,%2,%3}, [%4];"
                 : "=r"(f[0]), "=r"(f[1]), "=r"(f[2]), "=r"(f[3]) : "r"(addr));
}
__device__ __forceinline__ void mma_bf16(float* d, const uint32_t* a,
                                         const uint32_t* b) {
    asm volatile(
        "mma.sync.aligned.m16n8k16.row.col.f32.bf16.bf16.f32 "
        "{%0,%1,%2,%3}, {%4,%5,%6,%7}, {%8,%9}, {%0,%1,%2,%3};"
        : "+f"(d[0]), "+f"(d[1]), "+f"(d[2]), "+f"(d[3])
        : "r"(a[0]), "r"(a[1]), "r"(a[2]), "r"(a[3]), "r"(b[0]), "r"(b[1]));
}
__device__ __forceinline__ void ldsA(uint32_t* f, uint32_t tile, int m0, int k0,
                                     int lane) {
    int r = lane & 7, g = lane >> 3;
    int row = m0 + r + (g & 1) * 8;
    int kch = (k0 >> 3) + (g >> 1);
    ldm4(f, tile + row * 128 + (((kch ^ (row & 7)) & 7) << 4));
}
__device__ __forceinline__ void ldsB(uint32_t* f, uint32_t tile, int n0, int k0,
                                     int lane) {
    int r = lane & 7, g = lane >> 3;
    int row = n0 + r + (g >> 1) * 8;
    int kch = (k0 >> 3) + (g & 1);
    ldm4(f, tile + row * 128 + (((kch ^ (row & 7)) & 7) << 4));
}
__device__ __forceinline__ void ldsBT(uint32_t* f, uint32_t tile, int n0, int k0,
                                      int lane) {
    int r = lane & 7, g = lane >> 3;
    int row = k0 + r + (g & 1) * 8;
    int bch = (n0 + (g >> 1) * 8) >> 3;
    ldm4t(f, tile + row * 128 + (((bch ^ (row & 7)) & 7) << 4));
}
__device__ __forceinline__ void split2(float a, float b, uint32_t& hi,
                                       uint32_t& lo) {
    __nv_bfloat16 ah = __float2bfloat16(a), bh = __float2bfloat16(b);
    __nv_bfloat16 al = __float2bfloat16(a - __bfloat162float(ah));
    __nv_bfloat16 bl = __float2bfloat16(b - __bfloat162float(bh));
    hi = (uint32_t)*(uint16_t*)&ah | ((uint32_t)*(uint16_t*)&bh << 16);
    lo = (uint32_t)*(uint16_t*)&al | ((uint32_t)*(uint16_t*)&bl << 16);
}
#define CP16(dst, src)                                                         \
    asm volatile("cp.async.cg.shared.global [%0], [%1], 16;"                   \
                 :: "r"(dst), "l"(src) : "memory")

// ---------------- fused input split: x | Wqkv | rel | Wpos | Wout ----------
__global__ __launch_bounds__(256) void split_all(
    const float4* __restrict__ x, const float4* __restrict__ wq,
    const float4* __restrict__ rel, const float4* __restrict__ wp,
    const float4* __restrict__ wo)
{
    int i = blockIdx.x * 256 + threadIdx.x;
    const float4* src; uint32_t* H; uint32_t* L; int li;
    if (i < 524288)       { src = x;   H = (uint32_t*)g_xh;  L = (uint32_t*)g_xl;  li = i; }
    else if (i < 1310720) { src = wq;  H = (uint32_t*)g_wqh; L = (uint32_t*)g_wql; li = i - 524288; }
    else if (i < 1835008) { src = rel; H = (uint32_t*)g_rh;  L = (uint32_t*)g_rl;  li = i - 1310720; }
    else if (i < 2097152) { src = wp;  H = (uint32_t*)g_wph; L = (uint32_t*)g_wpl; li = i - 1835008; }
    else                  { src = wo;  H = (uint32_t*)g_woh; L = (uint32_t*)g_wol; li = i - 2097152; }
    float4 v = src[li];
    uint32_t h0, l0, h1, l1;
    split2(v.x, v.y, h0, l0);
    split2(v.z, v.w, h1, l1);
    H[2 * li] = h0; H[2 * li + 1] = h1;
    L[2 * li] = l0; L[2 * li + 1] = l1;
}

// ---------------------------------------------------------------------------
// C[M,N] = A[M,K] * B[N,K]^T  via mma.sync bf16, x3 split (fp32 accuracy).
// MODE 0: write fp32 C.  MODE 1: qkv -> per-head qu/qv/k/v bf16 hi/lo.
// MODE 2: pos -> per-head rp bf16 hi/lo.
// ---------------------------------------------------------------------------
#define GEMM_SMEM (2 * 65536 + 1024)

template<int MODE>
__global__ __launch_bounds__(256, 1) void gemm_bf16x3(
    const __nv_bfloat16* __restrict__ Ah, const __nv_bfloat16* __restrict__ Al,
    const __nv_bfloat16* __restrict__ Bh, const __nv_bfloat16* __restrict__ Bl,
    float* __restrict__ C, const float* __restrict__ u_vec,
    const float* __restrict__ v_vec, int M, int N, int K)
{
    extern __shared__ char smem[];
    uint32_t tiles = (s2u(smem) + 1023u) & ~1023u;
    const int tid = threadIdx.x;
    const int lane = tid & 31, wid = tid >> 5;
    const int wm = wid & 3, wn = wid >> 2;
    const int bn = blockIdx.x * 128, bm = blockIdx.y * 128;

    const __nv_bfloat16* gsrc[16];
    uint32_t sdst[16];
#pragma unroll
    for (int u = 0; u < 16; u++) {
        int idx = u * 256 + tid;
        int tile = idx >> 10, row = (idx >> 3) & 127, cc = idx & 7;
        const __nv_bfloat16* bp = (tile == 0) ? Ah : (tile == 1) ? Al
                                 : (tile == 2) ? Bh : Bl;
        int gr = ((tile < 2) ? bm : bn) + row;
        gsrc[u] = bp + (size_t)gr * K + cc * 8;
        sdst[u] = tiles + tile * 16384u + row * 128u
                + (uint32_t)((cc ^ (row & 7)) << 4);
    }
    const int NC = K >> 6;

    float acc[2][8][4];
#pragma unroll
    for (int mi = 0; mi < 2; mi++)
#pragma unroll
        for (int ni = 0; ni < 8; ni++)
#pragma unroll
            for (int q = 0; q < 4; q++) acc[mi][ni][q] = 0.f;

#pragma unroll
    for (int u = 0; u < 16; u++) CP16(sdst[u], gsrc[u]);
    asm volatile("cp.async.commit_group;" ::: "memory");

    for (int c = 0; c < NC; c++) {
        if (c + 1 < NC) {
            uint32_t nst = (uint32_t)((c + 1) & 1) * 65536u;
            int ke = (c + 1) << 6;
#pragma unroll
            for (int u = 0; u < 16; u++) CP16(sdst[u] + nst, gsrc[u] + ke);
            asm volatile("cp.async.commit_group;" ::: "memory");
            asm volatile("cp.async.wait_group 1;" ::: "memory");
        } else {
            asm volatile("cp.async.wait_group 0;" ::: "memory");
        }
        __syncthreads();

        uint32_t st = (uint32_t)(c & 1) * 65536u;
        uint32_t tAh = tiles + st, tAl = tAh + 16384u;
        uint32_t tBh = tAl + 16384u, tBl = tBh + 16384u;
#pragma unroll
        for (int ks = 0; ks < 4; ks++) {
            int k0 = ks * 16;
            uint32_t ah[8], al[8], bb[16];
#pragma unroll
            for (int mi = 0; mi < 2; mi++)
                ldsA(&ah[mi * 4], tAh, wm * 32 + mi * 16, k0, lane);
#pragma unroll
            for (int nb = 0; nb < 4; nb++)
                ldsB(&bb[nb * 4], tBh, wn * 64 + nb * 16, k0, lane);
#pragma unroll
            for (int mi = 0; mi < 2; mi++)
#pragma unroll
                for (int ni = 0; ni < 8; ni++)
                    mma_bf16(acc[mi][ni], &ah[mi * 4], &bb[ni * 2]);
#pragma unroll
            for (int mi = 0; mi < 2; mi++)
                ldsA(&al[mi * 4], tAl, wm * 32 + mi * 16, k0, lane);
#pragma unroll
            for (int mi = 0; mi < 2; mi++)
#pragma unroll
                for (int ni = 0; ni < 8; ni++)
                    mma_bf16(acc[mi][ni], &al[mi * 4], &bb[ni * 2]);
#pragma unroll
            for (int nb = 0; nb < 4; nb++)
                ldsB(&bb[nb * 4], tBl, wn * 64 + nb * 16, k0, lane);
#pragma unroll
            for (int mi = 0; mi < 2; mi++)
#pragma unroll
                for (int ni = 0; ni < 8; ni++)
                    mma_bf16(acc[mi][ni], &ah[mi * 4], &bb[ni * 2]);
        }
        __syncthreads();
    }

    const int r0 = lane >> 2, c0 = (lane & 3) * 2;
#pragma unroll
    for (int mi = 0; mi < 2; mi++) {
        int gm = bm + wm * 32 + mi * 16;
#pragma unroll
        for (int ni = 0; ni < 8; ni++) {
            int gn = bn + wn * 64 + ni * 8 + c0;
            if (MODE == 0) {
                float* p0 = C + (size_t)(gm + r0) * N + gn;
                float* p1 = C + (size_t)(gm + r0 + 8) * N + gn;
                *(float2*)p0 = make_float2(acc[mi][ni][0], acc[mi][ni][1]);
                *(float2*)p1 = make_float2(acc[mi][ni][2], acc[mi][ni][3]);
            } else if (MODE == 2) {
                int hd_ = gn & 1023;
                size_t w0 = (((size_t)(hd_ >> 6) * S_LEN + gm + r0) * HD
                             + (hd_ & 63)) >> 1;
                size_t w1 = w0 + 256;           // +8 rows
                uint32_t hh, ll;
                split2(acc[mi][ni][0], acc[mi][ni][1], hh, ll);
                ((uint32_t*)g_rph)[w0] = hh; ((uint32_t*)g_rpl)[w0] = ll;
                split2(acc[mi][ni][2], acc[mi][ni][3], hh, ll);
                ((uint32_t*)g_rph)[w1] = hh; ((uint32_t*)g_rpl)[w1] = ll;
            } else {
                int sec = gn >> 10;
                int hd_ = gn & 1023;
                size_t w0 = (((size_t)(hd_ >> 6) * S_LEN + gm + r0) * HD
                             + (hd_ & 63)) >> 1;
                size_t w1 = w0 + 256;
                uint32_t hh, ll;
                if (sec == 0) {
                    float2 uu = *(const float2*)&u_vec[hd_];
                    float2 vv = *(const float2*)&v_vec[hd_];
                    split2(acc[mi][ni][0] + uu.x, acc[mi][ni][1] + uu.y, hh, ll);
                    ((uint32_t*)g_quh)[w0] = hh; ((uint32_t*)g_qul)[w0] = ll;
                    split2(acc[mi][ni][2] + uu.x, acc[mi][ni][3] + uu.y, hh, ll);
                    ((uint32_t*)g_quh)[w1] = hh; ((uint32_t*)g_qul)[w1] = ll;
                    split2(acc[mi][ni][0] + vv.x, acc[mi][ni][1] + vv.y, hh, ll);
                    ((uint32_t*)g_qvh)[w0] = hh; ((uint32_t*)g_qvl)[w0] = ll;
                    split2(acc[mi][ni][2] + vv.x, acc[mi][ni][3] + vv.y, hh, ll);
                    ((uint32_t*)g_qvh)[w1] = hh; ((uint32_t*)g_qvl)[w1] = ll;
                } else if (sec == 1) {
                    split2(acc[mi][ni][0], acc[mi][ni][1], hh, ll);
                    ((uint32_t*)g_kh)[w0] = hh; ((uint32_t*)g_kl)[w0] = ll;
                    split2(acc[mi][ni][2], acc[mi][ni][3], hh, ll);
                    ((uint32_t*)g_kh)[w1] = hh; ((uint32_t*)g_kl)[w1] = ll;
                } else {
                    split2(acc[mi][ni][0], acc[mi][ni][1], hh, ll);
                    ((uint32_t*)g_vh)[w0] = hh; ((uint32_t*)g_vl)[w0] = ll;
                    split2(acc[mi][ni][2], acc[mi][ni][3], hh, ll);
                    ((uint32_t*)g_vh)[w1] = hh; ((uint32_t*)g_vl)[w1] = ll;
                }
            }
        }
    }
}

// ---------------------------------------------------------------------------
// Flash-attention, Transformer-XL shift — communication-free warps.
// Grid (16, 16): CTA = 128 i-rows x 1 head. 8 warps; warp owns 16 rows,
// all 64 j, all 64 d. R band kept in a 256-row ring (64 new rows/iter).
// smem 230400 B, 1 CTA/SM. One __syncthreads per j-iter.
// ---------------------------------------------------------------------------
#define oKV 65536           /* stage*32768: Kh,Kl,Vh,Vl @8192 */
#define oR  131072          /* Rh @0, Rl @32768; 256-row ring  */
#define oS  196608          /* fp32 [128][66] warp-private strips */
#define FL_SMEM 230400

__global__ __launch_bounds__(256, 1) void flash_xl_mma()
{
    extern __shared__ char fsm[];
    const uint32_t base = s2u(fsm);
    float* sS = (float*)(fsm + oS);

    const int h   = blockIdx.y;
    const int i0  = 128 * (int)(gridDim.x - 1 - blockIdx.x);  // heavy first
    const int tid = threadIdx.x;
    const int lane = tid & 31, wid = tid >> 5;
    const int m0 = wid * 16;
    const int fr = lane >> 2, fc = (lane & 3) * 2;
    const int il0 = m0 + fr, il1 = il0 + 8;

    const size_t hb = (size_t)h * (S_LEN * HD);
    const __nv_bfloat16* pQUh = g_quh + hb + (size_t)i0 * HD;
    const __nv_bfloat16* pQUl = g_qul + hb + (size_t)i0 * HD;
    const __nv_bfloat16* pQVh = g_qvh + hb + (size_t)i0 * HD;
    const __nv_bfloat16* pQVl = g_qvl + hb + (size_t)i0 * HD;
    const __nv_bfloat16* pKh  = g_kh  + hb;
    const __nv_bfloat16* pKl  = g_kl  + hb;
    const __nv_bfloat16* pVh  = g_vh  + hb;
    const __nv_bfloat16* pVl  = g_vl  + hb;
    const __nv_bfloat16* pRh  = g_rph + hb;
    const __nv_bfloat16* pRl  = g_rpl + hb;

    auto fill_kv = [&](int j0, int stg) {
        uint32_t so = base + oKV + (uint32_t)stg * 32768u;
#pragma unroll
        for (int w = 0; w < 8; w++) {
            int t = w * 256 + tid;
            int tile = t >> 9, r = (t >> 3) & 63, ch = t & 7;
            const __nv_bfloat16* gb =
                ((tile == 0) ? pKh : (tile == 1) ? pKl : (tile == 2) ? pVh : pVl)
                + (size_t)(j0 + r) * HD + ch * 8;
            uint32_t dst = so + (uint32_t)tile * 8192u + (uint32_t)r * 128u
                         + (uint32_t)(((ch ^ (r & 7)) & 7) << 4);
            CP16(dst, gb);
        }
    };
    auto fill_r64 = [&](int Bst) {          // 64 band rows m=(Bst+r)&2047
        int ringb = Bst & 255;
#pragma unroll
        for (int w = 0; w < 4; w++) {
            int t = w * 256 + tid;
            int tile = t >> 9, r = (t >> 3) & 63, ch = t & 7;
            int m = (Bst + r) & 2047;
            int rr = ringb + r;
            const __nv_bfloat16* gb = (tile ? pRl : pRh) + (size_t)m * HD + ch * 8;
            uint32_t dst = base + oR + (uint32_t)tile * 32768u
                         + (uint32_t)rr * 128u
                         + (uint32_t)(((ch ^ (rr & 7)) & 7) << 4);
            CP16(dst, gb);
        }
    };

    // prologue: Q (128 rows x 4 tiles), KV_0, band rows t in [0,192)
#pragma unroll
    for (int w = 0; w < 16; w++) {
        int t = w * 256 + tid;
        int tile = t >> 10, r = (t >> 3) & 127, ch = t & 7;
        const __nv_bfloat16* gb =
            ((tile == 0) ? pQUh : (tile == 1) ? pQUl : (tile == 2) ? pQVh : pQVl)
            + (size_t)r * HD + ch * 8;
        uint32_t dst = base + (uint32_t)tile * 16384u + (uint32_t)r * 128u
                     + (uint32_t)(((ch ^ (r & 7)) & 7) << 4);
        CP16(dst, gb);
    }
    const int B0 = -i0 - 128 + 4096;        // band origin (mod-2048 safe)
    fill_kv(0, 0);
    fill_r64(B0); fill_r64(B0 + 64); fill_r64(B0 + 128);
    asm volatile("cp.async.commit_group;" ::: "memory");

    float mR0 = -1e30f, mR1 = -1e30f, lR0 = 0.f, lR1 = 0.f;
    float o[8][4];
#pragma unroll
    for (int nd = 0; nd < 8; nd++)
#pragma unroll
        for (int q = 0; q < 4; q++) o[nd][q] = 0.f;

    const int nIt = i0 / 64 + 2;
    for (int c = 0; c < nIt; c++) {
        const int j0 = c * 64;
        const int Bc = 64 * c + B0;
        asm volatile("cp.async.wait_group 0;" ::: "memory");
        __syncthreads();   // stage/ring visible; prev-iter readers done
        if (c + 1 < nIt) {
            fill_kv(j0 + 64, (c + 1) & 1);
            fill_r64(Bc + 192);
            asm volatile("cp.async.commit_group;" ::: "memory");
        }

        const bool act = (j0 <= i0 + m0 + 15);
        const uint32_t kst = base + oKV + (uint32_t)(c & 1) * 32768u;
        const uint32_t tKh = kst,           tKl = kst + 8192u;
        const uint32_t tVh = kst + 16384u,  tVl = kst + 24576u;

        float sF[8][4];
        if (act) {
            // ---- GEMM2: band (own 16 rows x valid t) -> warp-private sS ----
            float aT[5][2][4];
#pragma unroll
            for (int b = 0; b < 5; b++)
#pragma unroll
                for (int hf = 0; hf < 2; hf++)
#pragma unroll
                    for (int q = 0; q < 4; q++) aT[b][hf][q] = 0.f;
#pragma unroll
            for (int ks = 0; ks < 4; ks++) {
                int k0 = ks * 16;
                uint32_t ah[4], al[4];
                ldsA(ah, base + 32768u, m0, k0, lane);   // QVh
                ldsA(al, base + 49152u, m0, k0, lane);   // QVl
#pragma unroll
                for (int b = 0; b < 5; b++) {
                    int rT0 = (Bc + 112 - m0 + b * 16) & 255;
                    uint32_t bh[4], bl[4];
                    ldsB(bh, base + oR, rT0, k0, lane);
                    ldsB(bl, base + oR + 32768u, rT0, k0, lane);
                    mma_bf16(aT[b][0], ah, bh); mma_bf16(aT[b][1], ah, bh + 2);
                    mma_bf16(aT[b][0], al, bh); mma_bf16(aT[b][1], al, bh + 2);
                    mma_bf16(aT[b][0], ah, bl); mma_bf16(aT[b][1], ah, bl + 2);
                }
            }
            // store at target j (j = b*16 + hf*8 + fc + fr - 15, row il0;
            // +8 for row il1); warp-private rows -> __syncwarp only
#pragma unroll
            for (int b = 0; b < 5; b++)
#pragma unroll
                for (int hf = 0; hf < 2; hf++) {
                    int j0e = b * 16 + hf * 8 + fc + fr - 15;
                    if ((unsigned)j0e < 64u)       sS[il0 * 66 + j0e]     = aT[b][hf][0];
                    if ((unsigned)(j0e + 1) < 64u) sS[il0 * 66 + j0e + 1] = aT[b][hf][1];
                    int j1e = j0e + 8;
                    if ((unsigned)j1e < 64u)       sS[il1 * 66 + j1e]     = aT[b][hf][2];
                    if ((unsigned)(j1e + 1) < 64u) sS[il1 * 66 + j1e + 1] = aT[b][hf][3];
                }

            // ---- GEMM1: content scores (16 rows x 64 j) -> registers -------
#pragma unroll
            for (int f = 0; f < 8; f++)
#pragma unroll
                for (int q = 0; q < 4; q++) sF[f][q] = 0.f;
#pragma unroll
            for (int ks = 0; ks < 4; ks++) {
                int k0 = ks * 16;
                uint32_t ah[4], al[4];
                ldsA(ah, base + 0u,      m0, k0, lane);  // QUh
                ldsA(al, base + 16384u,  m0, k0, lane);  // QUl
#pragma unroll
                for (int nb = 0; nb < 4; nb++) {
                    uint32_t bh[4], bl[4];
                    ldsB(bh, tKh, nb * 16, k0, lane);
                    ldsB(bl, tKl, nb * 16, k0, lane);
                    mma_bf16(sF[nb * 2], ah, bh); mma_bf16(sF[nb * 2 + 1], ah, bh + 2);
                    mma_bf16(sF[nb * 2], al, bh); mma_bf16(sF[nb * 2 + 1], al, bh + 2);
                    mma_bf16(sF[nb * 2], ah, bl); mma_bf16(sF[nb * 2 + 1], ah, bl + 2);
                }
            }
            __syncwarp();

            // ---- softmax: fully quad-local --------------------------------
            float sv0[8][2], sv1[8][2];
            float mx0 = -1e30f, mx1 = -1e30f;
#pragma unroll
            for (int f = 0; f < 8; f++) {
                float2 b0 = *(float2*)&sS[il0 * 66 + f * 8 + fc];
                float2 b1 = *(float2*)&sS[il1 * 66 + f * 8 + fc];
                int jc = f * 8 + fc;
                float s00 = (sF[f][0] + b0.x) * SCALE;
                float s01 = (sF[f][1] + b0.y) * SCALE;
                float s10 = (sF[f][2] + b1.x) * SCALE;
                float s11 = (sF[f][3] + b1.y) * SCALE;
                if (j0 + jc     > i0 + il0) s00 = -1e30f;
                if (j0 + jc + 1 > i0 + il0) s01 = -1e30f;
                if (j0 + jc     > i0 + il1) s10 = -1e30f;
                if (j0 + jc + 1 > i0 + il1) s11 = -1e30f;
                sv0[f][0] = s00; sv0[f][1] = s01;
                sv1[f][0] = s10; sv1[f][1] = s11;
                mx0 = fmaxf(mx0, fmaxf(s00, s01));
                mx1 = fmaxf(mx1, fmaxf(s10, s11));
            }
            mx0 = fmaxf(mx0, __shfl_xor_sync(0xffffffffu, mx0, 1));
            mx0 = fmaxf(mx0, __shfl_xor_sync(0xffffffffu, mx0, 2));
            mx1 = fmaxf(mx1, __shfl_xor_sync(0xffffffffu, mx1, 1));
            mx1 = fmaxf(mx1, __shfl_xor_sync(0xffffffffu, mx1, 2));
            float mNew0 = fmaxf(mR0, mx0), mNew1 = fmaxf(mR1, mx1);
            float corr0 = __expf(mR0 - mNew0), corr1 = __expf(mR1 - mNew1);
            mR0 = mNew0; mR1 = mNew1;
            float rs0 = 0.f, rs1 = 0.f;
            float pv0[8][2], pv1[8][2];
#pragma unroll
            for (int f = 0; f < 8; f++) {
                pv0[f][0] = __expf(sv0[f][0] - mNew0);
                pv0[f][1] = __expf(sv0[f][1] - mNew0);
                pv1[f][0] = __expf(sv1[f][0] - mNew1);
                pv1[f][1] = __expf(sv1[f][1] - mNew1);
                rs0 += pv0[f][0] + pv0[f][1];
                rs1 += pv1[f][0] + pv1[f][1];
            }
            rs0 += __shfl_xor_sync(0xffffffffu, rs0, 1);
            rs0 += __shfl_xor_sync(0xffffffffu, rs0, 2);
            rs1 += __shfl_xor_sync(0xffffffffu, rs1, 1);
            rs1 += __shfl_xor_sync(0xffffffffu, rs1, 2);
            lR0 = lR0 * corr0 + rs0;
            lR1 = lR1 * corr1 + rs1;

            // pack P into A-frags (C-frag -> A-frag identity)
            uint32_t ph[4][4], pl[4][4];
#pragma unroll
            for (int ks = 0; ks < 4; ks++) {
                split2(pv0[2 * ks][0],     pv0[2 * ks][1],     ph[ks][0], pl[ks][0]);
                split2(pv1[2 * ks][0],     pv1[2 * ks][1],     ph[ks][1], pl[ks][1]);
                split2(pv0[2 * ks + 1][0], pv0[2 * ks + 1][1], ph[ks][2], pl[ks][2]);
                split2(pv1[2 * ks + 1][0], pv1[2 * ks + 1][1], ph[ks][3], pl[ks][3]);
            }

            // ---- GEMM3: O = O*corr + P*V (16 rows x 64 d) ------------------
#pragma unroll
            for (int nd = 0; nd < 8; nd++) {
                o[nd][0] *= corr0; o[nd][1] *= corr0;
                o[nd][2] *= corr1; o[nd][3] *= corr1;
            }
#pragma unroll
            for (int ks = 0; ks < 4; ks++) {
                int k0 = ks * 16;
#pragma unroll
                for (int nd2 = 0; nd2 < 4; nd2++) {
                    uint32_t bh[4], bl[4];
                    ldsBT(bh, tVh, nd2 * 16, k0, lane);
                    ldsBT(bl, tVl, nd2 * 16, k0, lane);
                    float* o0 = o[nd2 * 2 + 0];
                    float* o1 = o[nd2 * 2 + 1];
                    mma_bf16(o0, ph[ks], bh); mma_bf16(o1, ph[ks], bh + 2);
                    mma_bf16(o0, pl[ks], bh); mma_bf16(o1, pl[ks], bh + 2);
                    mma_bf16(o0, ph[ks], bl); mma_bf16(o1, ph[ks], bl + 2);
                }
            }
        }
    }

    // ---- epilogue: normalize, split to bf16 hi/lo, store -------------------
    {
        float inv0 = 1.f / lR0, inv1 = 1.f / lR1;
#pragma unroll
        for (int nd = 0; nd < 8; nd++) {
            int col = h * HD + nd * 8 + fc;
            uint32_t hh, ll;
            split2(o[nd][0] * inv0, o[nd][1] * inv0, hh, ll);
            size_t w = ((size_t)(i0 + il0) * V_DIM + col) >> 1;
            ((uint32_t*)g_ah)[w] = hh; ((uint32_t*)g_al)[w] = ll;
            split2(o[nd][2] * inv1, o[nd][3] * inv1, hh, ll);
            w = ((size_t)(i0 + il1) * V_DIM + col) >> 1;
            ((uint32_t*)g_ah)[w] = hh; ((uint32_t*)g_al)[w] = ll;
        }
    }
}

// ---------------------------------------------------------------------------
extern "C" void kernel_launch(void* const* d_in, const int* in_sizes, int n_in,
                              void* d_out, int out_size)
{
    const float* x    = (const float*)d_in[0];
    const float* Wqkv = (const float*)d_in[1];
    const float* Wout = (const float*)d_in[2];
    const float* Wpos = (const float*)d_in[3];
    const float* u    = (const float*)d_in[4];
    const float* v    = (const float*)d_in[5];
    const float* rel  = (const float*)d_in[6];
    float* out = (float*)d_out;

    void *xh, *xl, *wqh, *wql, *rh, *rl, *wph, *wpl, *ah, *al, *woh, *wol;
    cudaGetSymbolAddress(&xh,  g_xh);  cudaGetSymbolAddress(&xl,  g_xl);
    cudaGetSymbolAddress(&wqh, g_wqh); cudaGetSymbolAddress(&wql, g_wql);
    cudaGetSymbolAddress(&rh,  g_rh);  cudaGetSymbolAddress(&rl,  g_rl);
    cudaGetSymbolAddress(&wph, g_wph); cudaGetSymbolAddress(&wpl, g_wpl);
    cudaGetSymbolAddress(&ah,  g_ah);  cudaGetSymbolAddress(&al,  g_al);
    cudaGetSymbolAddress(&woh, g_woh); cudaGetSymbolAddress(&wol, g_wol);

    cudaFuncSetAttribute(flash_xl_mma,
                         cudaFuncAttributeMaxDynamicSharedMemorySize, FL_SMEM);
    cudaFuncSetAttribute(gemm_bf16x3<0>,
                         cudaFuncAttributeMaxDynamicSharedMemorySize, GEMM_SMEM);
    cudaFuncSetAttribute(gemm_bf16x3<1>,
                         cudaFuncAttributeMaxDynamicSharedMemorySize, GEMM_SMEM);
    cudaFuncSetAttribute(gemm_bf16x3<2>,
                         cudaFuncAttributeMaxDynamicSharedMemorySize, GEMM_SMEM);

    // 1) split all fp32 inputs to bf16 hi/lo  (total 2359296 float4s)
    split_all<<<9216, 256>>>((const float4*)x, (const float4*)Wqkv,
                             (const float4*)rel, (const float4*)Wpos,
                             (const float4*)Wout);

    // 2) qkv projection: epilogue writes per-head qu/qv/k/v bf16 hi/lo
    gemm_bf16x3<1><<<dim3(QKV_LD / 128, S_LEN / 128), 256, GEMM_SMEM>>>(
        (const __nv_bfloat16*)xh, (const __nv_bfloat16*)xl,
        (const __nv_bfloat16*)wqh, (const __nv_bfloat16*)wql,
        nullptr, u, v, S_LEN, QKV_LD, V_DIM);

    // 3) pos projection: epilogue writes per-head rp bf16 hi/lo
    gemm_bf16x3<2><<<dim3(V_DIM / 128, S_LEN / 128), 256, GEMM_SMEM>>>(
        (const __nv_bfloat16*)rh, (const __nv_bfloat16*)rl,
        (const __nv_bfloat16*)wph, (const __nv_bfloat16*)wpl,
        nullptr, nullptr, nullptr, S_LEN, V_DIM, V_DIM);

    // 4) fused attention -> g_ah/g_al (bf16 hi/lo)
    flash_xl_mma<<<dim3(S_LEN / 128, NH), 256, FL_SMEM>>>();

    // 5) out = attn @ Wout^T -> fp32 d_out
    gemm_bf16x3<0><<<dim3(V_DIM / 128, S_LEN / 128), 256, GEMM_SMEM>>>(
        (const __nv_bfloat16*)ah, (const __nv_bfloat16*)al,
        (const __nv_bfloat16*)woh, (const __nv_bfloat16*)wol,
        out, nullptr, nullptr, S_LEN, V_DIM, V_DIM);
}

// round 9
// speedup vs baseline: 6.8010x; 1.5538x over previous
#include <cuda_runtime.h>
#include <cuda_fp16.h>
#include <cstdint>

#define S_LEN 2048
#define V_DIM 1024
#define NH    16
#define HD    64
#define QKV_LD 3072
#define SCALE 0.125f

// ---------------- scratch (__device__ globals; no allocation allowed) ------
// fp16 x2 split: A-side tensors keep hi+lo; B-side tensors hi only.
__device__ __align__(256) __half g_xh[S_LEN * V_DIM],  g_xl[S_LEN * V_DIM];
__device__ __align__(256) __half g_wqh[QKV_LD * V_DIM];
__device__ __align__(256) __half g_rh[S_LEN * V_DIM],  g_rl[S_LEN * V_DIM];
__device__ __align__(256) __half g_wph[V_DIM * V_DIM];
__device__ __align__(256) __half g_ah[S_LEN * V_DIM],  g_al[S_LEN * V_DIM];
__device__ __align__(256) __half g_woh[V_DIM * V_DIM];

// per-head fp16 tensors for flash: layout [H][S][64]
#define HSD (NH * S_LEN * HD)
__device__ __align__(256) __half g_quh[HSD], g_qul[HSD];   // q + u (hi/lo)
__device__ __align__(256) __half g_qvh[HSD], g_qvl[HSD];   // q + v (hi/lo)
__device__ __align__(256) __half g_kh[HSD];                // k (hi only)
__device__ __align__(256) __half g_vh[HSD];                // v (hi only)
__device__ __align__(256) __half g_rph[HSD];               // pos (hi only)

// ---------------- helpers ---------------------------------------------------
__device__ __forceinline__ uint32_t s2u(const void* p) {
    uint32_t a;
    asm("{ .reg .u64 t; cvta.to.shared.u64 t, %1; cvt.u32.u64 %0, t; }"
        : "=r"(a) : "l"(p));
    return a;
}
__device__ __forceinline__ void ldm4(uint32_t* f, uint32_t addr) {
    asm volatile("ldmatrix.sync.aligned.m8n8.x4.shared.b16 {%0,%1,%2,%3}, [%4];"
                 : "=r"(f[0]), "=r"(f[1]), "=r"(f[2]), "=r"(f[3]) : "r"(addr));
}
__device__ __forceinline__ void ldm4t(uint32_t* f, uint32_t addr) {
    asm volatile("ldmatrix.sync.aligned.m8n8.x4.trans.shared.b16 {%0,%1,%2,%3}, [%4];"
                 : "=r"(f[0]), "=r"(f[1]), "=r"(f[2]), "=r"(f[3]) : "r"(addr));
}
__device__ __forceinline__ void mma_f16(float* d, const uint32_t* a,
                                        const uint32_t* b) {
    asm volatile(
        "mma.sync.aligned.m16n8k16.row.col.f32.f16.f16.f32 "
        "{%0,%1,%2,%3}, {%4,%5,%6,%7}, {%8,%9}, {%0,%1,%2,%3};"
        : "+f"(d[0]), "+f"(d[1]), "+f"(d[2]), "+f"(d[3])
        : "r"(a[0]), "r"(a[1]), "r"(a[2]), "r"(a[3]), "r"(b[0]), "r"(b[1]));
}
__device__ __forceinline__ void ldsA(uint32_t* f, uint32_t tile, int m0, int k0,
                                     int lane) {
    int r = lane & 7, g = lane >> 3;
    int row = m0 + r + (g & 1) * 8;
    int kch = (k0 >> 3) + (g >> 1);
    ldm4(f, tile + row * 128 + (((kch ^ (row & 7)) & 7) << 4));
}
__device__ __forceinline__ void ldsB(uint32_t* f, uint32_t tile, int n0, int k0,
                                     int lane) {
    int r = lane & 7, g = lane >> 3;
    int row = n0 + r + (g >> 1) * 8;
    int kch = (k0 >> 3) + (g & 1);
    ldm4(f, tile + row * 128 + (((kch ^ (row & 7)) & 7) << 4));
}
__device__ __forceinline__ void ldsBT(uint32_t* f, uint32_t tile, int n0, int k0,
                                      int lane) {
    int r = lane & 7, g = lane >> 3;
    int row = k0 + r + (g & 1) * 8;
    int bch = (n0 + (g >> 1) * 8) >> 3;
    ldm4t(f, tile + row * 128 + (((bch ^ (row & 7)) & 7) << 4));
}
__device__ __forceinline__ uint32_t pack2h(float a, float b) {
    __half2 p = __floats2half2_rn(a, b);
    return *(uint32_t*)&p;
}
__device__ __forceinline__ void split2h(float a, float b, uint32_t& hi,
                                        uint32_t& lo) {
    __half ah = __float2half_rn(a), bh = __float2half_rn(b);
    __half al = __float2half_rn(a - __half2float(ah));
    __half bl = __float2half_rn(b - __half2float(bh));
    hi = (uint32_t)*(uint16_t*)&ah | ((uint32_t)*(uint16_t*)&bh << 16);
    lo = (uint32_t)*(uint16_t*)&al | ((uint32_t)*(uint16_t*)&bl << 16);
}
#define CP16(dst, src)                                                         \
    asm volatile("cp.async.cg.shared.global [%0], [%1], 16;"                   \
                 :: "r"(dst), "l"(src) : "memory")

// ---------------- fused input split: x | Wqkv | rel | Wpos | Wout ----------
// x, rel -> hi+lo ; weights -> hi only
__global__ __launch_bounds__(256) void split_all(
    const float4* __restrict__ x, const float4* __restrict__ wq,
    const float4* __restrict__ rel, const float4* __restrict__ wp,
    const float4* __restrict__ wo)
{
    int i = blockIdx.x * 256 + threadIdx.x;
    const float4* src; uint32_t* H; uint32_t* L; int li; bool wl;
    if (i < 524288)       { src = x;   H = (uint32_t*)g_xh;  L = (uint32_t*)g_xl; li = i; wl = true; }
    else if (i < 1310720) { src = wq;  H = (uint32_t*)g_wqh; L = nullptr; li = i - 524288;  wl = false; }
    else if (i < 1835008) { src = rel; H = (uint32_t*)g_rh;  L = (uint32_t*)g_rl; li = i - 1310720; wl = true; }
    else if (i < 2097152) { src = wp;  H = (uint32_t*)g_wph; L = nullptr; li = i - 1835008; wl = false; }
    else                  { src = wo;  H = (uint32_t*)g_woh; L = nullptr; li = i - 2097152; wl = false; }
    float4 v = src[li];
    uint32_t h0, l0, h1, l1;
    split2h(v.x, v.y, h0, l0);
    split2h(v.z, v.w, h1, l1);
    H[2 * li] = h0; H[2 * li + 1] = h1;
    if (wl) { L[2 * li] = l0; L[2 * li + 1] = l1; }
}

// ---------------------------------------------------------------------------
// C[M,N] = A[M,K] * B[N,K]^T  via mma.sync fp16 x2 (A hi+lo, B hi).
// MODE 0: fp32 C.  MODE 1: qkv -> per-head qu/qv (hi/lo), k/v (hi).
// MODE 2: pos -> per-head rp (hi).
// ---------------------------------------------------------------------------
#define GEMM_SMEM (2 * 49152 + 1024)

template<int MODE>
__global__ __launch_bounds__(256, 1) void gemm_f16x2(
    const __half* __restrict__ Ah, const __half* __restrict__ Al,
    const __half* __restrict__ Bh,
    float* __restrict__ C, const float* __restrict__ u_vec,
    const float* __restrict__ v_vec, int M, int N, int K)
{
    extern __shared__ char smem[];
    uint32_t tiles = (s2u(smem) + 1023u) & ~1023u;
    const int tid = threadIdx.x;
    const int lane = tid & 31, wid = tid >> 5;
    const int wm = wid & 3, wn = wid >> 2;
    const int bn = blockIdx.x * 128, bm = blockIdx.y * 128;

    const __half* gsrc[12];
    uint32_t sdst[12];
#pragma unroll
    for (int u = 0; u < 12; u++) {
        int idx = u * 256 + tid;
        int tile = idx >> 10, row = (idx >> 3) & 127, cc = idx & 7;
        const __half* bp = (tile == 0) ? Ah : (tile == 1) ? Al : Bh;
        int gr = ((tile < 2) ? bm : bn) + row;
        gsrc[u] = bp + (size_t)gr * K + cc * 8;
        sdst[u] = tiles + tile * 16384u + row * 128u
                + (uint32_t)((cc ^ (row & 7)) << 4);
    }
    const int NC = K >> 6;

    float acc[2][8][4];
#pragma unroll
    for (int mi = 0; mi < 2; mi++)
#pragma unroll
        for (int ni = 0; ni < 8; ni++)
#pragma unroll
            for (int q = 0; q < 4; q++) acc[mi][ni][q] = 0.f;

#pragma unroll
    for (int u = 0; u < 12; u++) CP16(sdst[u], gsrc[u]);
    asm volatile("cp.async.commit_group;" ::: "memory");

    for (int c = 0; c < NC; c++) {
        if (c + 1 < NC) {
            uint32_t nst = (uint32_t)((c + 1) & 1) * 49152u;
            int ke = (c + 1) << 6;
#pragma unroll
            for (int u = 0; u < 12; u++) CP16(sdst[u] + nst, gsrc[u] + ke);
            asm volatile("cp.async.commit_group;" ::: "memory");
            asm volatile("cp.async.wait_group 1;" ::: "memory");
        } else {
            asm volatile("cp.async.wait_group 0;" ::: "memory");
        }
        __syncthreads();

        uint32_t st = (uint32_t)(c & 1) * 49152u;
        uint32_t tAh = tiles + st, tAl = tAh + 16384u, tBh = tAl + 16384u;
#pragma unroll
        for (int ks = 0; ks < 4; ks++) {
            int k0 = ks * 16;
            uint32_t ah[8], al[8], bb[16];
#pragma unroll
            for (int mi = 0; mi < 2; mi++)
                ldsA(&ah[mi * 4], tAh, wm * 32 + mi * 16, k0, lane);
#pragma unroll
            for (int nb = 0; nb < 4; nb++)
                ldsB(&bb[nb * 4], tBh, wn * 64 + nb * 16, k0, lane);
#pragma unroll
            for (int mi = 0; mi < 2; mi++)
#pragma unroll
                for (int ni = 0; ni < 8; ni++)
                    mma_f16(acc[mi][ni], &ah[mi * 4], &bb[ni * 2]);
#pragma unroll
            for (int mi = 0; mi < 2; mi++)
                ldsA(&al[mi * 4], tAl, wm * 32 + mi * 16, k0, lane);
#pragma unroll
            for (int mi = 0; mi < 2; mi++)
#pragma unroll
                for (int ni = 0; ni < 8; ni++)
                    mma_f16(acc[mi][ni], &al[mi * 4], &bb[ni * 2]);
        }
        __syncthreads();
    }

    const int r0 = lane >> 2, c0 = (lane & 3) * 2;
#pragma unroll
    for (int mi = 0; mi < 2; mi++) {
        int gm = bm + wm * 32 + mi * 16;
#pragma unroll
        for (int ni = 0; ni < 8; ni++) {
            int gn = bn + wn * 64 + ni * 8 + c0;
            if (MODE == 0) {
                float* p0 = C + (size_t)(gm + r0) * N + gn;
                float* p1 = C + (size_t)(gm + r0 + 8) * N + gn;
                *(float2*)p0 = make_float2(acc[mi][ni][0], acc[mi][ni][1]);
                *(float2*)p1 = make_float2(acc[mi][ni][2], acc[mi][ni][3]);
            } else if (MODE == 2) {
                int hd_ = gn & 1023;
                size_t w0 = (((size_t)(hd_ >> 6) * S_LEN + gm + r0) * HD
                             + (hd_ & 63)) >> 1;
                size_t w1 = w0 + 256;           // +8 rows
                ((uint32_t*)g_rph)[w0] = pack2h(acc[mi][ni][0], acc[mi][ni][1]);
                ((uint32_t*)g_rph)[w1] = pack2h(acc[mi][ni][2], acc[mi][ni][3]);
            } else {
                int sec = gn >> 10;
                int hd_ = gn & 1023;
                size_t w0 = (((size_t)(hd_ >> 6) * S_LEN + gm + r0) * HD
                             + (hd_ & 63)) >> 1;
                size_t w1 = w0 + 256;
                uint32_t hh, ll;
                if (sec == 0) {
                    float2 uu = *(const float2*)&u_vec[hd_];
                    float2 vv = *(const float2*)&v_vec[hd_];
                    split2h(acc[mi][ni][0] + uu.x, acc[mi][ni][1] + uu.y, hh, ll);
                    ((uint32_t*)g_quh)[w0] = hh; ((uint32_t*)g_qul)[w0] = ll;
                    split2h(acc[mi][ni][2] + uu.x, acc[mi][ni][3] + uu.y, hh, ll);
                    ((uint32_t*)g_quh)[w1] = hh; ((uint32_t*)g_qul)[w1] = ll;
                    split2h(acc[mi][ni][0] + vv.x, acc[mi][ni][1] + vv.y, hh, ll);
                    ((uint32_t*)g_qvh)[w0] = hh; ((uint32_t*)g_qvl)[w0] = ll;
                    split2h(acc[mi][ni][2] + vv.x, acc[mi][ni][3] + vv.y, hh, ll);
                    ((uint32_t*)g_qvh)[w1] = hh; ((uint32_t*)g_qvl)[w1] = ll;
                } else if (sec == 1) {
                    ((uint32_t*)g_kh)[w0] = pack2h(acc[mi][ni][0], acc[mi][ni][1]);
                    ((uint32_t*)g_kh)[w1] = pack2h(acc[mi][ni][2], acc[mi][ni][3]);
                } else {
                    ((uint32_t*)g_vh)[w0] = pack2h(acc[mi][ni][0], acc[mi][ni][1]);
                    ((uint32_t*)g_vh)[w1] = pack2h(acc[mi][ni][2], acc[mi][ni][3]);
                }
            }
        }
    }
}

// ---------------------------------------------------------------------------
// Flash-attention, Transformer-XL shift — communication-free warps, fp16 x2.
// Grid (NH, 16): x=head, y->i-tile (heavy tiles start in wave 1).
// CTA = 128 i-rows; 8 warps; warp owns 16 rows x 64 j x 64 d.
// smem 164864 B, 1 CTA/SM. One __syncthreads per j-iter.
// ---------------------------------------------------------------------------
#define oKV 65536           /* stage*16384: Kh @0, Vh @8192 */
#define oR  98304           /* Rh 256-row ring (hi only)    */
#define oS  131072          /* fp32 [128][66] warp-private strips */
#define FL_SMEM 164864

__global__ __launch_bounds__(256, 1) void flash_xl_mma()
{
    extern __shared__ char fsm[];
    const uint32_t base = s2u(fsm);
    float* sS = (float*)(fsm + oS);

    const int h   = blockIdx.x;
    const int i0  = 128 * (int)(gridDim.y - 1 - blockIdx.y);  // heavy first
    const int tid = threadIdx.x;
    const int lane = tid & 31, wid = tid >> 5;
    const int m0 = wid * 16;
    const int fr = lane >> 2, fc = (lane & 3) * 2;
    const int il0 = m0 + fr, il1 = il0 + 8;

    const size_t hb = (size_t)h * (S_LEN * HD);
    const __half* pQUh = g_quh + hb + (size_t)i0 * HD;
    const __half* pQUl = g_qul + hb + (size_t)i0 * HD;
    const __half* pQVh = g_qvh + hb + (size_t)i0 * HD;
    const __half* pQVl = g_qvl + hb + (size_t)i0 * HD;
    const __half* pKh  = g_kh  + hb;
    const __half* pVh  = g_vh  + hb;
    const __half* pRh  = g_rph + hb;

    auto fill_kv = [&](int j0, int stg) {
        uint32_t so = base + oKV + (uint32_t)stg * 16384u;
#pragma unroll
        for (int w = 0; w < 4; w++) {
            int t = w * 256 + tid;
            int tile = t >> 9, r = (t >> 3) & 63, ch = t & 7;
            const __half* gb = (tile ? pVh : pKh) + (size_t)(j0 + r) * HD + ch * 8;
            uint32_t dst = so + (uint32_t)tile * 8192u + (uint32_t)r * 128u
                         + (uint32_t)(((ch ^ (r & 7)) & 7) << 4);
            CP16(dst, gb);
        }
    };
    auto fill_r64 = [&](int Bst) {          // 64 band rows m=(Bst+r)&2047
        int ringb = Bst & 255;
#pragma unroll
        for (int w = 0; w < 2; w++) {
            int t = w * 256 + tid;
            int r = t >> 3, ch = t & 7;
            int m = (Bst + r) & 2047;
            int rr = ringb + r;
            const __half* gb = pRh + (size_t)m * HD + ch * 8;
            uint32_t dst = base + oR + (uint32_t)rr * 128u
                         + (uint32_t)(((ch ^ (rr & 7)) & 7) << 4);
            CP16(dst, gb);
        }
    };

    // prologue: Q (128 rows x 4 tiles), KV_0, band rows [0,192)
#pragma unroll
    for (int w = 0; w < 16; w++) {
        int t = w * 256 + tid;
        int tile = t >> 10, r = (t >> 3) & 127, ch = t & 7;
        const __half* gb =
            ((tile == 0) ? pQUh : (tile == 1) ? pQUl : (tile == 2) ? pQVh : pQVl)
            + (size_t)r * HD + ch * 8;
        uint32_t dst = base + (uint32_t)tile * 16384u + (uint32_t)r * 128u
                     + (uint32_t)(((ch ^ (r & 7)) & 7) << 4);
        CP16(dst, gb);
    }
    const int B0 = -i0 - 128 + 4096;        // band origin (mod-2048 safe)
    fill_kv(0, 0);
    fill_r64(B0); fill_r64(B0 + 64); fill_r64(B0 + 128);
    asm volatile("cp.async.commit_group;" ::: "memory");

    float mR0 = -1e30f, mR1 = -1e30f, lR0 = 0.f, lR1 = 0.f;
    float o[8][4];
#pragma unroll
    for (int nd = 0; nd < 8; nd++)
#pragma unroll
        for (int q = 0; q < 4; q++) o[nd][q] = 0.f;

    const int nIt = i0 / 64 + 2;
    for (int c = 0; c < nIt; c++) {
        const int j0 = c * 64;
        const int Bc = 64 * c + B0;
        asm volatile("cp.async.wait_group 0;" ::: "memory");
        __syncthreads();   // stage/ring visible; prev-iter readers done
        if (c + 1 < nIt) {
            fill_kv(j0 + 64, (c + 1) & 1);
            fill_r64(Bc + 192);
            asm volatile("cp.async.commit_group;" ::: "memory");
        }

        const bool act = (j0 <= i0 + m0 + 15);
        const uint32_t kst = base + oKV + (uint32_t)(c & 1) * 16384u;
        const uint32_t tKh = kst, tVh = kst + 8192u;

        float sF[8][4];
        if (act) {
            // ---- GEMM2: band (own 16 rows x valid t) -> warp-private sS ----
            float aT[5][2][4];
#pragma unroll
            for (int b = 0; b < 5; b++)
#pragma unroll
                for (int hf = 0; hf < 2; hf++)
#pragma unroll
                    for (int q = 0; q < 4; q++) aT[b][hf][q] = 0.f;
#pragma unroll
            for (int ks = 0; ks < 4; ks++) {
                int k0 = ks * 16;
                uint32_t ah[4], al[4];
                ldsA(ah, base + 32768u, m0, k0, lane);   // QVh
                ldsA(al, base + 49152u, m0, k0, lane);   // QVl
#pragma unroll
                for (int b = 0; b < 5; b++) {
                    int rT0 = (Bc + 112 - m0 + b * 16) & 255;
                    uint32_t bh[4];
                    ldsB(bh, base + oR, rT0, k0, lane);
                    mma_f16(aT[b][0], ah, bh); mma_f16(aT[b][1], ah, bh + 2);
                    mma_f16(aT[b][0], al, bh); mma_f16(aT[b][1], al, bh + 2);
                }
            }
            // store at target j (j = b*16 + hf*8 + fc + fr - 15 row il0; +8 il1)
#pragma unroll
            for (int b = 0; b < 5; b++)
#pragma unroll
                for (int hf = 0; hf < 2; hf++) {
                    int j0e = b * 16 + hf * 8 + fc + fr - 15;
                    if ((unsigned)j0e < 64u)       sS[il0 * 66 + j0e]     = aT[b][hf][0];
                    if ((unsigned)(j0e + 1) < 64u) sS[il0 * 66 + j0e + 1] = aT[b][hf][1];
                    int j1e = j0e + 8;
                    if ((unsigned)j1e < 64u)       sS[il1 * 66 + j1e]     = aT[b][hf][2];
                    if ((unsigned)(j1e + 1) < 64u) sS[il1 * 66 + j1e + 1] = aT[b][hf][3];
                }

            // ---- GEMM1: content scores (16 rows x 64 j) -> registers -------
#pragma unroll
            for (int f = 0; f < 8; f++)
#pragma unroll
                for (int q = 0; q < 4; q++) sF[f][q] = 0.f;
#pragma unroll
            for (int ks = 0; ks < 4; ks++) {
                int k0 = ks * 16;
                uint32_t ah[4], al[4];
                ldsA(ah, base + 0u,      m0, k0, lane);  // QUh
                ldsA(al, base + 16384u,  m0, k0, lane);  // QUl
#pragma unroll
                for (int nb = 0; nb < 4; nb++) {
                    uint32_t bh[4];
                    ldsB(bh, tKh, nb * 16, k0, lane);
                    mma_f16(sF[nb * 2], ah, bh); mma_f16(sF[nb * 2 + 1], ah, bh + 2);
                    mma_f16(sF[nb * 2], al, bh); mma_f16(sF[nb * 2 + 1], al, bh + 2);
                }
            }
            __syncwarp();

            // ---- softmax: fully quad-local --------------------------------
            float sv0[8][2], sv1[8][2];
            float mx0 = -1e30f, mx1 = -1e30f;
#pragma unroll
            for (int f = 0; f < 8; f++) {
                float2 b0 = *(float2*)&sS[il0 * 66 + f * 8 + fc];
                float2 b1 = *(float2*)&sS[il1 * 66 + f * 8 + fc];
                int jc = f * 8 + fc;
                float s00 = (sF[f][0] + b0.x) * SCALE;
                float s01 = (sF[f][1] + b0.y) * SCALE;
                float s10 = (sF[f][2] + b1.x) * SCALE;
                float s11 = (sF[f][3] + b1.y) * SCALE;
                if (j0 + jc     > i0 + il0) s00 = -1e30f;
                if (j0 + jc + 1 > i0 + il0) s01 = -1e30f;
                if (j0 + jc     > i0 + il1) s10 = -1e30f;
                if (j0 + jc + 1 > i0 + il1) s11 = -1e30f;
                sv0[f][0] = s00; sv0[f][1] = s01;
                sv1[f][0] = s10; sv1[f][1] = s11;
                mx0 = fmaxf(mx0, fmaxf(s00, s01));
                mx1 = fmaxf(mx1, fmaxf(s10, s11));
            }
            mx0 = fmaxf(mx0, __shfl_xor_sync(0xffffffffu, mx0, 1));
            mx0 = fmaxf(mx0, __shfl_xor_sync(0xffffffffu, mx0, 2));
            mx1 = fmaxf(mx1, __shfl_xor_sync(0xffffffffu, mx1, 1));
            mx1 = fmaxf(mx1, __shfl_xor_sync(0xffffffffu, mx1, 2));
            float mNew0 = fmaxf(mR0, mx0), mNew1 = fmaxf(mR1, mx1);
            float corr0 = __expf(mR0 - mNew0), corr1 = __expf(mR1 - mNew1);
            mR0 = mNew0; mR1 = mNew1;
            float rs0 = 0.f, rs1 = 0.f;
            float pv0[8][2], pv1[8][2];
#pragma unroll
            for (int f = 0; f < 8; f++) {
                pv0[f][0] = __expf(sv0[f][0] - mNew0);
                pv0[f][1] = __expf(sv0[f][1] - mNew0);
                pv1[f][0] = __expf(sv1[f][0] - mNew1);
                pv1[f][1] = __expf(sv1[f][1] - mNew1);
                rs0 += pv0[f][0] + pv0[f][1];
                rs1 += pv1[f][0] + pv1[f][1];
            }
            rs0 += __shfl_xor_sync(0xffffffffu, rs0, 1);
            rs0 += __shfl_xor_sync(0xffffffffu, rs0, 2);
            rs1 += __shfl_xor_sync(0xffffffffu, rs1, 1);
            rs1 += __shfl_xor_sync(0xffffffffu, rs1, 2);
            lR0 = lR0 * corr0 + rs0;
            lR1 = lR1 * corr1 + rs1;

            // pack P into A-frags (C-frag -> A-frag identity), hi + lo
            uint32_t ph[4][4], pl[4][4];
#pragma unroll
            for (int ks = 0; ks < 4; ks++) {
                split2h(pv0[2 * ks][0],     pv0[2 * ks][1],     ph[ks][0], pl[ks][0]);
                split2h(pv1[2 * ks][0],     pv1[2 * ks][1],     ph[ks][1], pl[ks][1]);
                split2h(pv0[2 * ks + 1][0], pv0[2 * ks + 1][1], ph[ks][2], pl[ks][2]);
                split2h(pv1[2 * ks + 1][0], pv1[2 * ks + 1][1], ph[ks][3], pl[ks][3]);
            }

            // ---- GEMM3: O = O*corr + P*V (16 rows x 64 d) ------------------
#pragma unroll
            for (int nd = 0; nd < 8; nd++) {
                o[nd][0] *= corr0; o[nd][1] *= corr0;
                o[nd][2] *= corr1; o[nd][3] *= corr1;
            }
#pragma unroll
            for (int ks = 0; ks < 4; ks++) {
                int k0 = ks * 16;
#pragma unroll
                for (int nd2 = 0; nd2 < 4; nd2++) {
                    uint32_t bh[4];
                    ldsBT(bh, tVh, nd2 * 16, k0, lane);
                    float* o0 = o[nd2 * 2 + 0];
                    float* o1 = o[nd2 * 2 + 1];
                    mma_f16(o0, ph[ks], bh); mma_f16(o1, ph[ks], bh + 2);
                    mma_f16(o0, pl[ks], bh); mma_f16(o1, pl[ks], bh + 2);
                }
            }
        }
    }

    // ---- epilogue: normalize, split to fp16 hi/lo, store -------------------
    {
        float inv0 = 1.f / lR0, inv1 = 1.f / lR1;
#pragma unroll
        for (int nd = 0; nd < 8; nd++) {
            int col = h * HD + nd * 8 + fc;
            uint32_t hh, ll;
            split2h(o[nd][0] * inv0, o[nd][1] * inv0, hh, ll);
            size_t w = ((size_t)(i0 + il0) * V_DIM + col) >> 1;
            ((uint32_t*)g_ah)[w] = hh; ((uint32_t*)g_al)[w] = ll;
            split2h(o[nd][2] * inv1, o[nd][3] * inv1, hh, ll);
            w = ((size_t)(i0 + il1) * V_DIM + col) >> 1;
            ((uint32_t*)g_ah)[w] = hh; ((uint32_t*)g_al)[w] = ll;
        }
    }
}

// ---------------------------------------------------------------------------
extern "C" void kernel_launch(void* const* d_in, const int* in_sizes, int n_in,
                              void* d_out, int out_size)
{
    const float* x    = (const float*)d_in[0];
    const float* Wqkv = (const float*)d_in[1];
    const float* Wout = (const float*)d_in[2];
    const float* Wpos = (const float*)d_in[3];
    const float* u    = (const float*)d_in[4];
    const float* v    = (const float*)d_in[5];
    const float* rel  = (const float*)d_in[6];
    float* out = (float*)d_out;

    void *xh, *xl, *wqh, *rh, *rl, *wph, *ah, *al, *woh;
    cudaGetSymbolAddress(&xh,  g_xh);  cudaGetSymbolAddress(&xl,  g_xl);
    cudaGetSymbolAddress(&wqh, g_wqh);
    cudaGetSymbolAddress(&rh,  g_rh);  cudaGetSymbolAddress(&rl,  g_rl);
    cudaGetSymbolAddress(&wph, g_wph);
    cudaGetSymbolAddress(&ah,  g_ah);  cudaGetSymbolAddress(&al,  g_al);
    cudaGetSymbolAddress(&woh, g_woh);

    cudaFuncSetAttribute(flash_xl_mma,
                         cudaFuncAttributeMaxDynamicSharedMemorySize, FL_SMEM);
    cudaFuncSetAttribute(gemm_f16x2<0>,
                         cudaFuncAttributeMaxDynamicSharedMemorySize, GEMM_SMEM);
    cudaFuncSetAttribute(gemm_f16x2<1>,
                         cudaFuncAttributeMaxDynamicSharedMemorySize, GEMM_SMEM);
    cudaFuncSetAttribute(gemm_f16x2<2>,
                         cudaFuncAttributeMaxDynamicSharedMemorySize, GEMM_SMEM);

    // 1) split all fp32 inputs (2359296 float4s)
    split_all<<<9216, 256>>>((const float4*)x, (const float4*)Wqkv,
                             (const float4*)rel, (const float4*)Wpos,
                             (const float4*)Wout);

    // 2) qkv projection -> per-head qu/qv (hi/lo), k/v (hi)
    gemm_f16x2<1><<<dim3(QKV_LD / 128, S_LEN / 128), 256, GEMM_SMEM>>>(
        (const __half*)xh, (const __half*)xl, (const __half*)wqh,
        nullptr, u, v, S_LEN, QKV_LD, V_DIM);

    // 3) pos projection -> per-head rp (hi)
    gemm_f16x2<2><<<dim3(V_DIM / 128, S_LEN / 128), 256, GEMM_SMEM>>>(
        (const __half*)rh, (const __half*)rl, (const __half*)wph,
        nullptr, nullptr, nullptr, S_LEN, V_DIM, V_DIM);

    // 4) fused attention -> g_ah/g_al (fp16 hi/lo)
    flash_xl_mma<<<dim3(NH, S_LEN / 128), 256, FL_SMEM>>>();

    // 5) out = attn @ Wout^T -> fp32 d_out
    gemm_f16x2<0><<<dim3(V_DIM / 128, S_LEN / 128), 256, GEMM_SMEM>>>(
        (const __half*)ah, (const __half*)al, (const __half*)woh,
        out, nullptr, nullptr, S_LEN, V_DIM, V_DIM);
}

// round 11
// speedup vs baseline: 7.0576x; 1.0377x over previous
#include <cuda_runtime.h>
#include <cuda_fp16.h>
#include <cstdint>

#define S_LEN 2048
#define V_DIM 1024
#define NH    16
#define HD    64
#define QKV_LD 3072
#define SCALE 0.125f

// ---------------- scratch (__device__ globals; no allocation allowed) ------
__device__ __align__(256) __half g_xh[S_LEN * V_DIM],  g_xl[S_LEN * V_DIM];
__device__ __align__(256) __half g_wqh[QKV_LD * V_DIM];
__device__ __align__(256) __half g_rh[S_LEN * V_DIM],  g_rl[S_LEN * V_DIM];
__device__ __align__(256) __half g_wph[V_DIM * V_DIM];
__device__ __align__(256) __half g_ah[S_LEN * V_DIM],  g_al[S_LEN * V_DIM];
__device__ __align__(256) __half g_woh[V_DIM * V_DIM];

// per-head fp16 tensors for flash: layout [H][S][64]
#define HSD (NH * S_LEN * HD)
__device__ __align__(256) __half g_quh[HSD], g_qul[HSD];   // q + u (hi/lo)
__device__ __align__(256) __half g_qvh[HSD], g_qvl[HSD];   // q + v (hi/lo)
__device__ __align__(256) __half g_kh[HSD];                // k (hi only)
__device__ __align__(256) __half g_vh[HSD];                // v (hi only)
__device__ __align__(256) __half g_rph[HSD];               // pos (hi only)

// ---------------- helpers ---------------------------------------------------
__device__ __forceinline__ uint32_t s2u(const void* p) {
    uint32_t a;
    asm("{ .reg .u64 t; cvta.to.shared.u64 t, %1; cvt.u32.u64 %0, t; }"
        : "=r"(a) : "l"(p));
    return a;
}
__device__ __forceinline__ void ldm4(uint32_t* f, uint32_t addr) {
    asm volatile("ldmatrix.sync.aligned.m8n8.x4.shared.b16 {%0,%1,%2,%3}, [%4];"
                 : "=r"(f[0]), "=r"(f[1]), "=r"(f[2]), "=r"(f[3]) : "r"(addr));
}
__device__ __forceinline__ void ldm4t(uint32_t* f, uint32_t addr) {
    asm volatile("ldmatrix.sync.aligned.m8n8.x4.trans.shared.b16 {%0,%1,%2,%3}, [%4];"
                 : "=r"(f[0]), "=r"(f[1]), "=r"(f[2]), "=r"(f[3]) : "r"(addr));
}
__device__ __forceinline__ void mma_f16(float* d, const uint32_t* a,
                                        const uint32_t* b) {
    asm volatile(
        "mma.sync.aligned.m16n8k16.row.col.f32.f16.f16.f32 "
        "{%0,%1,%2,%3}, {%4,%5,%6,%7}, {%8,%9}, {%0,%1,%2,%3};"
        : "+f"(d[0]), "+f"(d[1]), "+f"(d[2]), "+f"(d[3])
        : "r"(a[0]), "r"(a[1]), "r"(a[2]), "r"(a[3]), "r"(b[0]), "r"(b[1]));
}
__device__ __forceinline__ void ldsA(uint32_t* f, uint32_t tile, int m0, int k0,
                                     int lane) {
    int r = lane & 7, g = lane >> 3;
    int row = m0 + r + (g & 1) * 8;
    int kch = (k0 >> 3) + (g >> 1);
    ldm4(f, tile + row * 128 + (((kch ^ (row & 7)) & 7) << 4));
}
__device__ __forceinline__ void ldsB(uint32_t* f, uint32_t tile, int n0, int k0,
                                     int lane) {
    int r = lane & 7, g = lane >> 3;
    int row = n0 + r + (g >> 1) * 8;
    int kch = (k0 >> 3) + (g & 1);
    ldm4(f, tile + row * 128 + (((kch ^ (row & 7)) & 7) << 4));
}
__device__ __forceinline__ void ldsBT(uint32_t* f, uint32_t tile, int n0, int k0,
                                      int lane) {
    int r = lane & 7, g = lane >> 3;
    int row = k0 + r + (g & 1) * 8;
    int bch = (n0 + (g >> 1) * 8) >> 3;
    ldm4t(f, tile + row * 128 + (((bch ^ (row & 7)) & 7) << 4));
}
__device__ __forceinline__ uint32_t pack2h(float a, float b) {
    __half2 p = __floats2half2_rn(a, b);
    return *(uint32_t*)&p;
}
__device__ __forceinline__ void split2h(float a, float b, uint32_t& hi,
                                        uint32_t& lo) {
    __half ah = __float2half_rn(a), bh = __float2half_rn(b);
    __half al = __float2half_rn(a - __half2float(ah));
    __half bl = __float2half_rn(b - __half2float(bh));
    hi = (uint32_t)*(uint16_t*)&ah | ((uint32_t)*(uint16_t*)&bh << 16);
    lo = (uint32_t)*(uint16_t*)&al | ((uint32_t)*(uint16_t*)&bl << 16);
}
#define CP16(dst, src)                                                         \
    asm volatile("cp.async.cg.shared.global [%0], [%1], 16;"                   \
                 :: "r"(dst), "l"(src) : "memory")

// ---------------- fused input split: x | Wqkv | rel | Wpos | Wout ----------
__global__ __launch_bounds__(256) void split_all(
    const float4* __restrict__ x, const float4* __restrict__ wq,
    const float4* __restrict__ rel, const float4* __restrict__ wp,
    const float4* __restrict__ wo)
{
    int i = blockIdx.x * 256 + threadIdx.x;
    const float4* src; uint32_t* H; uint32_t* L; int li; bool wl;
    if (i < 524288)       { src = x;   H = (uint32_t*)g_xh;  L = (uint32_t*)g_xl; li = i; wl = true; }
    else if (i < 1310720) { src = wq;  H = (uint32_t*)g_wqh; L = nullptr; li = i - 524288;  wl = false; }
    else if (i < 1835008) { src = rel; H = (uint32_t*)g_rh;  L = (uint32_t*)g_rl; li = i - 1310720; wl = true; }
    else if (i < 2097152) { src = wp;  H = (uint32_t*)g_wph; L = nullptr; li = i - 1835008; wl = false; }
    else                  { src = wo;  H = (uint32_t*)g_woh; L = nullptr; li = i - 2097152; wl = false; }
    float4 v = src[li];
    uint32_t h0, l0, h1, l1;
    split2h(v.x, v.y, h0, l0);
    split2h(v.z, v.w, h1, l1);
    H[2 * li] = h0; H[2 * li + 1] = h1;
    if (wl) { L[2 * li] = l0; L[2 * li + 1] = l1; }
}

// ---------------------------------------------------------------------------
// C[M,N] = A[M,K] * B[N,K]^T  via mma.sync fp16 x2 (A hi+lo, B hi).
// MODE 0: fp32 C.
// MODE 3: merged projections — blockIdx.x<24: qkv (per-head qu/qv hi/lo,
//         k/v hi); else: pos (per-head rp hi). K=1024 for both.
// ---------------------------------------------------------------------------
#define GEMM_SMEM (2 * 49152 + 1024)

template<int MODE>
__global__ __launch_bounds__(256, 1) void gemm_f16x2(
    const __half* __restrict__ Ah, const __half* __restrict__ Al,
    const __half* __restrict__ Bh,
    const __half* __restrict__ Ah2, const __half* __restrict__ Al2,
    const __half* __restrict__ Bh2,
    float* __restrict__ C, const float* __restrict__ u_vec,
    const float* __restrict__ v_vec, int M, int N, int K)
{
    extern __shared__ char smem[];
    uint32_t tiles = (s2u(smem) + 1023u) & ~1023u;
    const int tid = threadIdx.x;
    const int lane = tid & 31, wid = tid >> 5;
    const int wm = wid & 3, wn = wid >> 2;
    const int bm = blockIdx.y * 128;

    bool seg2 = false;
    int bn;
    const __half *pA, *pL, *pB;
    if (MODE == 3 && blockIdx.x >= 24) {
        seg2 = true;
        bn = (blockIdx.x - 24) * 128;
        pA = Ah2; pL = Al2; pB = Bh2;
    } else {
        bn = blockIdx.x * 128;
        pA = Ah; pL = Al; pB = Bh;
    }

    const __half* gsrc[12];
    uint32_t sdst[12];
#pragma unroll
    for (int u = 0; u < 12; u++) {
        int idx = u * 256 + tid;
        int tile = idx >> 10, row = (idx >> 3) & 127, cc = idx & 7;
        const __half* bp = (tile == 0) ? pA : (tile == 1) ? pL : pB;
        int gr = ((tile < 2) ? bm : bn) + row;
        gsrc[u] = bp + (size_t)gr * K + cc * 8;
        sdst[u] = tiles + tile * 16384u + row * 128u
                + (uint32_t)((cc ^ (row & 7)) << 4);
    }
    const int NC = K >> 6;

    float acc[2][8][4];
#pragma unroll
    for (int mi = 0; mi < 2; mi++)
#pragma unroll
        for (int ni = 0; ni < 8; ni++)
#pragma unroll
            for (int q = 0; q < 4; q++) acc[mi][ni][q] = 0.f;

#pragma unroll
    for (int u = 0; u < 12; u++) CP16(sdst[u], gsrc[u]);
    asm volatile("cp.async.commit_group;" ::: "memory");

    for (int c = 0; c < NC; c++) {
        if (c + 1 < NC) {
            uint32_t nst = (uint32_t)((c + 1) & 1) * 49152u;
            int ke = (c + 1) << 6;
#pragma unroll
            for (int u = 0; u < 12; u++) CP16(sdst[u] + nst, gsrc[u] + ke);
            asm volatile("cp.async.commit_group;" ::: "memory");
            asm volatile("cp.async.wait_group 1;" ::: "memory");
        } else {
            asm volatile("cp.async.wait_group 0;" ::: "memory");
        }
        __syncthreads();

        uint32_t st = (uint32_t)(c & 1) * 49152u;
        uint32_t tAh = tiles + st, tAl = tAh + 16384u, tBh = tAl + 16384u;
#pragma unroll
        for (int ks = 0; ks < 4; ks++) {
            int k0 = ks * 16;
            uint32_t ah[8], al[8], bb[16];
#pragma unroll
            for (int mi = 0; mi < 2; mi++)
                ldsA(&ah[mi * 4], tAh, wm * 32 + mi * 16, k0, lane);
#pragma unroll
            for (int nb = 0; nb < 4; nb++)
                ldsB(&bb[nb * 4], tBh, wn * 64 + nb * 16, k0, lane);
#pragma unroll
            for (int mi = 0; mi < 2; mi++)
#pragma unroll
                for (int ni = 0; ni < 8; ni++)
                    mma_f16(acc[mi][ni], &ah[mi * 4], &bb[ni * 2]);
#pragma unroll
            for (int mi = 0; mi < 2; mi++)
                ldsA(&al[mi * 4], tAl, wm * 32 + mi * 16, k0, lane);
#pragma unroll
            for (int mi = 0; mi < 2; mi++)
#pragma unroll
                for (int ni = 0; ni < 8; ni++)
                    mma_f16(acc[mi][ni], &al[mi * 4], &bb[ni * 2]);
        }
        __syncthreads();
    }

    const int r0 = lane >> 2, c0 = (lane & 3) * 2;
#pragma unroll
    for (int mi = 0; mi < 2; mi++) {
        int gm = bm + wm * 32 + mi * 16;
#pragma unroll
        for (int ni = 0; ni < 8; ni++) {
            int gn = bn + wn * 64 + ni * 8 + c0;
            if (MODE == 0) {
                float* p0 = C + (size_t)(gm + r0) * N + gn;
                float* p1 = C + (size_t)(gm + r0 + 8) * N + gn;
                *(float2*)p0 = make_float2(acc[mi][ni][0], acc[mi][ni][1]);
                *(float2*)p1 = make_float2(acc[mi][ni][2], acc[mi][ni][3]);
            } else if (seg2) {
                int hd_ = gn & 1023;
                size_t w0 = (((size_t)(hd_ >> 6) * S_LEN + gm + r0) * HD
                             + (hd_ & 63)) >> 1;
                size_t w1 = w0 + 256;           // +8 rows
                ((uint32_t*)g_rph)[w0] = pack2h(acc[mi][ni][0], acc[mi][ni][1]);
                ((uint32_t*)g_rph)[w1] = pack2h(acc[mi][ni][2], acc[mi][ni][3]);
            } else {
                int sec = gn >> 10;
                int hd_ = gn & 1023;
                size_t w0 = (((size_t)(hd_ >> 6) * S_LEN + gm + r0) * HD
                             + (hd_ & 63)) >> 1;
                size_t w1 = w0 + 256;
                uint32_t hh, ll;
                if (sec == 0) {
                    float2 uu = *(const float2*)&u_vec[hd_];
                    float2 vv = *(const float2*)&v_vec[hd_];
                    split2h(acc[mi][ni][0] + uu.x, acc[mi][ni][1] + uu.y, hh, ll);
                    ((uint32_t*)g_quh)[w0] = hh; ((uint32_t*)g_qul)[w0] = ll;
                    split2h(acc[mi][ni][2] + uu.x, acc[mi][ni][3] + uu.y, hh, ll);
                    ((uint32_t*)g_quh)[w1] = hh; ((uint32_t*)g_qul)[w1] = ll;
                    split2h(acc[mi][ni][0] + vv.x, acc[mi][ni][1] + vv.y, hh, ll);
                    ((uint32_t*)g_qvh)[w0] = hh; ((uint32_t*)g_qvl)[w0] = ll;
                    split2h(acc[mi][ni][2] + vv.x, acc[mi][ni][3] + vv.y, hh, ll);
                    ((uint32_t*)g_qvh)[w1] = hh; ((uint32_t*)g_qvl)[w1] = ll;
                } else if (sec == 1) {
                    ((uint32_t*)g_kh)[w0] = pack2h(acc[mi][ni][0], acc[mi][ni][1]);
                    ((uint32_t*)g_kh)[w1] = pack2h(acc[mi][ni][2], acc[mi][ni][3]);
                } else {
                    ((uint32_t*)g_vh)[w0] = pack2h(acc[mi][ni][0], acc[mi][ni][1]);
                    ((uint32_t*)g_vh)[w1] = pack2h(acc[mi][ni][2], acc[mi][ni][3]);
                }
            }
        }
    }
}

// ---------------------------------------------------------------------------
// Flash-attention, Transformer-XL shift — fp16 x2, register-hoisted Q frags.
// Grid (NH, 16): x=head, y->i-tile (heavy tiles start in wave 1).
// CTA = 128 i-rows; 8 warps; warp owns 16 rows x 64 j x 64 d.
// smem 164864 B, 1 CTA/SM. One __syncthreads per j-iter.
// ---------------------------------------------------------------------------
#define oKV 65536           /* stage*16384: Kh @0, Vh @8192 */
#define oR  98304           /* Rh 256-row ring (hi only)    */
#define oS  131072          /* fp32 [128][66] warp-private strips */
#define FL_SMEM 164864

__global__ __launch_bounds__(256, 1) void flash_xl_mma()
{
    extern __shared__ char fsm[];
    const uint32_t base = s2u(fsm);
    float* sS = (float*)(fsm + oS);

    const int h   = blockIdx.x;
    const int i0  = 128 * (int)(gridDim.y - 1 - blockIdx.y);  // heavy first
    const int tid = threadIdx.x;
    const int lane = tid & 31, wid = tid >> 5;
    const int m0 = wid * 16;
    const int fr = lane >> 2, fc = (lane & 3) * 2;
    const int il0 = m0 + fr, il1 = il0 + 8;

    const size_t hb = (size_t)h * (S_LEN * HD);
    const __half* pQUh = g_quh + hb + (size_t)i0 * HD;
    const __half* pQUl = g_qul + hb + (size_t)i0 * HD;
    const __half* pQVh = g_qvh + hb + (size_t)i0 * HD;
    const __half* pQVl = g_qvl + hb + (size_t)i0 * HD;
    const __half* pKh  = g_kh  + hb;
    const __half* pVh  = g_vh  + hb;
    const __half* pRh  = g_rph + hb;

    auto fill_kv = [&](int j0, int stg) {
        uint32_t so = base + oKV + (uint32_t)stg * 16384u;
#pragma unroll
        for (int w = 0; w < 4; w++) {
            int t = w * 256 + tid;
            int tile = t >> 9, r = (t >> 3) & 63, ch = t & 7;
            const __half* gb = (tile ? pVh : pKh) + (size_t)(j0 + r) * HD + ch * 8;
            uint32_t dst = so + (uint32_t)tile * 8192u + (uint32_t)r * 128u
                         + (uint32_t)(((ch ^ (r & 7)) & 7) << 4);
            CP16(dst, gb);
        }
    };
    auto fill_r64 = [&](int Bst) {          // 64 band rows m=(Bst+r)&2047
        int ringb = Bst & 255;
#pragma unroll
        for (int w = 0; w < 2; w++) {
            int t = w * 256 + tid;
            int r = t >> 3, ch = t & 7;
            int m = (Bst + r) & 2047;
            int rr = ringb + r;
            const __half* gb = pRh + (size_t)m * HD + ch * 8;
            uint32_t dst = base + oR + (uint32_t)rr * 128u
                         + (uint32_t)(((ch ^ (rr & 7)) & 7) << 4);
            CP16(dst, gb);
        }
    };

    // prologue group 1: Q tiles (128 rows x 4 tiles)
#pragma unroll
    for (int w = 0; w < 16; w++) {
        int t = w * 256 + tid;
        int tile = t >> 10, r = (t >> 3) & 127, ch = t & 7;
        const __half* gb =
            ((tile == 0) ? pQUh : (tile == 1) ? pQUl : (tile == 2) ? pQVh : pQVl)
            + (size_t)r * HD + ch * 8;
        uint32_t dst = base + (uint32_t)tile * 16384u + (uint32_t)r * 128u
                     + (uint32_t)(((ch ^ (r & 7)) & 7) << 4);
        CP16(dst, gb);
    }
    asm volatile("cp.async.commit_group;" ::: "memory");
    // prologue group 2: KV_0 + band rows [0,192)
    const int B0 = -i0 - 128 + 4096;        // band origin (mod-2048 safe)
    fill_kv(0, 0);
    fill_r64(B0); fill_r64(B0 + 64); fill_r64(B0 + 128);
    asm volatile("cp.async.commit_group;" ::: "memory");

    // hoist Q fragments: loop-invariant A-frags for GEMM1/GEMM2
    asm volatile("cp.async.wait_group 1;" ::: "memory");
    __syncthreads();
    uint32_t fQUh[4][4], fQUl[4][4], fQVh[4][4], fQVl[4][4];
#pragma unroll
    for (int ks = 0; ks < 4; ks++) {
        int k0 = ks * 16;
        ldsA(fQUh[ks], base + 0u,      m0, k0, lane);
        ldsA(fQUl[ks], base + 16384u,  m0, k0, lane);
        ldsA(fQVh[ks], base + 32768u,  m0, k0, lane);
        ldsA(fQVl[ks], base + 49152u,  m0, k0, lane);
    }

    float mR0 = -1e30f, mR1 = -1e30f, lR0 = 0.f, lR1 = 0.f;
    float o[8][4];
#pragma unroll
    for (int nd = 0; nd < 8; nd++)
#pragma unroll
        for (int q = 0; q < 4; q++) o[nd][q] = 0.f;

    const int nIt = i0 / 64 + 2;
    for (int c = 0; c < nIt; c++) {
        const int j0 = c * 64;
        const int Bc = 64 * c + B0;
        asm volatile("cp.async.wait_group 0;" ::: "memory");
        __syncthreads();   // stage/ring visible; prev-iter readers done
        if (c + 1 < nIt) {
            fill_kv(j0 + 64, (c + 1) & 1);
            fill_r64(Bc + 192);
            asm volatile("cp.async.commit_group;" ::: "memory");
        }

        const bool act = (j0 <= i0 + m0 + 15);
        const uint32_t kst = base + oKV + (uint32_t)(c & 1) * 16384u;
        const uint32_t tKh = kst, tVh = kst + 8192u;

        float sF[8][4];
        if (act) {
            // ---- GEMM2: band (own 16 rows x valid t) -> warp-private sS ----
            float aT[5][2][4];
#pragma unroll
            for (int b = 0; b < 5; b++)
#pragma unroll
                for (int hf = 0; hf < 2; hf++)
#pragma unroll
                    for (int q = 0; q < 4; q++) aT[b][hf][q] = 0.f;
#pragma unroll
            for (int ks = 0; ks < 4; ks++) {
                int k0 = ks * 16;
#pragma unroll
                for (int b = 0; b < 5; b++) {
                    int rT0 = (Bc + 112 - m0 + b * 16) & 255;
                    uint32_t bh[4];
                    ldsB(bh, base + oR, rT0, k0, lane);
                    mma_f16(aT[b][0], fQVh[ks], bh); mma_f16(aT[b][1], fQVh[ks], bh + 2);
                    mma_f16(aT[b][0], fQVl[ks], bh); mma_f16(aT[b][1], fQVl[ks], bh + 2);
                }
            }
            // store at target j (j = b*16 + hf*8 + fc + fr - 15 row il0; +8 il1)
#pragma unroll
            for (int b = 0; b < 5; b++)
#pragma unroll
                for (int hf = 0; hf < 2; hf++) {
                    int j0e = b * 16 + hf * 8 + fc + fr - 15;
                    if ((unsigned)j0e < 64u)       sS[il0 * 66 + j0e]     = aT[b][hf][0];
                    if ((unsigned)(j0e + 1) < 64u) sS[il0 * 66 + j0e + 1] = aT[b][hf][1];
                    int j1e = j0e + 8;
                    if ((unsigned)j1e < 64u)       sS[il1 * 66 + j1e]     = aT[b][hf][2];
                    if ((unsigned)(j1e + 1) < 64u) sS[il1 * 66 + j1e + 1] = aT[b][hf][3];
                }

            // ---- GEMM1: content scores (16 rows x 64 j) -> registers -------
#pragma unroll
            for (int f = 0; f < 8; f++)
#pragma unroll
                for (int q = 0; q < 4; q++) sF[f][q] = 0.f;
#pragma unroll
            for (int ks = 0; ks < 4; ks++) {
                int k0 = ks * 16;
#pragma unroll
                for (int nb = 0; nb < 4; nb++) {
                    uint32_t bh[4];
                    ldsB(bh, tKh, nb * 16, k0, lane);
                    mma_f16(sF[nb * 2], fQUh[ks], bh); mma_f16(sF[nb * 2 + 1], fQUh[ks], bh + 2);
                    mma_f16(sF[nb * 2], fQUl[ks], bh); mma_f16(sF[nb * 2 + 1], fQUl[ks], bh + 2);
                }
            }
            __syncwarp();

            // ---- softmax: fully quad-local --------------------------------
            float sv0[8][2], sv1[8][2];
            float mx0 = -1e30f, mx1 = -1e30f;
#pragma unroll
            for (int f = 0; f < 8; f++) {
                float2 b0 = *(float2*)&sS[il0 * 66 + f * 8 + fc];
                float2 b1 = *(float2*)&sS[il1 * 66 + f * 8 + fc];
                int jc = f * 8 + fc;
                float s00 = (sF[f][0] + b0.x) * SCALE;
                float s01 = (sF[f][1] + b0.y) * SCALE;
                float s10 = (sF[f][2] + b1.x) * SCALE;
                float s11 = (sF[f][3] + b1.y) * SCALE;
                if (j0 + jc     > i0 + il0) s00 = -1e30f;
                if (j0 + jc + 1 > i0 + il0) s01 = -1e30f;
                if (j0 + jc     > i0 + il1) s10 = -1e30f;
                if (j0 + jc + 1 > i0 + il1) s11 = -1e30f;
                sv0[f][0] = s00; sv0[f][1] = s01;
                sv1[f][0] = s10; sv1[f][1] = s11;
                mx0 = fmaxf(mx0, fmaxf(s00, s01));
                mx1 = fmaxf(mx1, fmaxf(s10, s11));
            }
            mx0 = fmaxf(mx0, __shfl_xor_sync(0xffffffffu, mx0, 1));
            mx0 = fmaxf(mx0, __shfl_xor_sync(0xffffffffu, mx0, 2));
            mx1 = fmaxf(mx1, __shfl_xor_sync(0xffffffffu, mx1, 1));
            mx1 = fmaxf(mx1, __shfl_xor_sync(0xffffffffu, mx1, 2));
            float mNew0 = fmaxf(mR0, mx0), mNew1 = fmaxf(mR1, mx1);
            float corr0 = __expf(mR0 - mNew0), corr1 = __expf(mR1 - mNew1);
            mR0 = mNew0; mR1 = mNew1;
            float rs0 = 0.f, rs1 = 0.f;
            float pv0[8][2], pv1[8][2];
#pragma unroll
            for (int f = 0; f < 8; f++) {
                pv0[f][0] = __expf(sv0[f][0] - mNew0);
                pv0[f][1] = __expf(sv0[f][1] - mNew0);
                pv1[f][0] = __expf(sv1[f][0] - mNew1);
                pv1[f][1] = __expf(sv1[f][1] - mNew1);
                rs0 += pv0[f][0] + pv0[f][1];
                rs1 += pv1[f][0] + pv1[f][1];
            }
            rs0 += __shfl_xor_sync(0xffffffffu, rs0, 1);
            rs0 += __shfl_xor_sync(0xffffffffu, rs0, 2);
            rs1 += __shfl_xor_sync(0xffffffffu, rs1, 1);
            rs1 += __shfl_xor_sync(0xffffffffu, rs1, 2);
            lR0 = lR0 * corr0 + rs0;
            lR1 = lR1 * corr1 + rs1;

            // pack P into A-frags (C-frag -> A-frag identity), hi + lo
            uint32_t ph[4][4], pl[4][4];
#pragma unroll
            for (int ks = 0; ks < 4; ks++) {
                split2h(pv0[2 * ks][0],     pv0[2 * ks][1],     ph[ks][0], pl[ks][0]);
                split2h(pv1[2 * ks][0],     pv1[2 * ks][1],     ph[ks][1], pl[ks][1]);
                split2h(pv0[2 * ks + 1][0], pv0[2 * ks + 1][1], ph[ks][2], pl[ks][2]);
                split2h(pv1[2 * ks + 1][0], pv1[2 * ks + 1][1], ph[ks][3], pl[ks][3]);
            }

            // ---- GEMM3: O = O*corr + P*V (16 rows x 64 d) ------------------
#pragma unroll
            for (int nd = 0; nd < 8; nd++) {
                o[nd][0] *= corr0; o[nd][1] *= corr0;
                o[nd][2] *= corr1; o[nd][3] *= corr1;
            }
#pragma unroll
            for (int ks = 0; ks < 4; ks++) {
                int k0 = ks * 16;
#pragma unroll
                for (int nd2 = 0; nd2 < 4; nd2++) {
                    uint32_t bh[4];
                    ldsBT(bh, tVh, nd2 * 16, k0, lane);
                    float* o0 = o[nd2 * 2 + 0];
                    float* o1 = o[nd2 * 2 + 1];
                    mma_f16(o0, ph[ks], bh); mma_f16(o1, ph[ks], bh + 2);
                    mma_f16(o0, pl[ks], bh); mma_f16(o1, pl[ks], bh + 2);
                }
            }
        }
    }

    // ---- epilogue: normalize, split to fp16 hi/lo, store -------------------
    {
        float inv0 = 1.f / lR0, inv1 = 1.f / lR1;
#pragma unroll
        for (int nd = 0; nd < 8; nd++) {
            int col = h * HD + nd * 8 + fc;
            uint32_t hh, ll;
            split2h(o[nd][0] * inv0, o[nd][1] * inv0, hh, ll);
            size_t w = ((size_t)(i0 + il0) * V_DIM + col) >> 1;
            ((uint32_t*)g_ah)[w] = hh; ((uint32_t*)g_al)[w] = ll;
            split2h(o[nd][2] * inv1, o[nd][3] * inv1, hh, ll);
            w = ((size_t)(i0 + il1) * V_DIM + col) >> 1;
            ((uint32_t*)g_ah)[w] = hh; ((uint32_t*)g_al)[w] = ll;
        }
    }
}

// ---------------------------------------------------------------------------
extern "C" void kernel_launch(void* const* d_in, const int* in_sizes, int n_in,
                              void* d_out, int out_size)
{
    const float* x    = (const float*)d_in[0];
    const float* Wqkv = (const float*)d_in[1];
    const float* Wout = (const float*)d_in[2];
    const float* Wpos = (const float*)d_in[3];
    const float* u    = (const float*)d_in[4];
    const float* v    = (const float*)d_in[5];
    const float* rel  = (const float*)d_in[6];
    float* out = (float*)d_out;

    void *xh, *xl, *wqh, *rh, *rl, *wph, *ah, *al, *woh;
    cudaGetSymbolAddress(&xh,  g_xh);  cudaGetSymbolAddress(&xl,  g_xl);
    cudaGetSymbolAddress(&wqh, g_wqh);
    cudaGetSymbolAddress(&rh,  g_rh);  cudaGetSymbolAddress(&rl,  g_rl);
    cudaGetSymbolAddress(&wph, g_wph);
    cudaGetSymbolAddress(&ah,  g_ah);  cudaGetSymbolAddress(&al,  g_al);
    cudaGetSymbolAddress(&woh, g_woh);

    cudaFuncSetAttribute(flash_xl_mma,
                         cudaFuncAttributeMaxDynamicSharedMemorySize, FL_SMEM);
    cudaFuncSetAttribute(gemm_f16x2<0>,
                         cudaFuncAttributeMaxDynamicSharedMemorySize, GEMM_SMEM);
    cudaFuncSetAttribute(gemm_f16x2<3>,
                         cudaFuncAttributeMaxDynamicSharedMemorySize, GEMM_SMEM);

    // 1) split all fp32 inputs (2359296 float4s)
    split_all<<<9216, 256>>>((const float4*)x, (const float4*)Wqkv,
                             (const float4*)rel, (const float4*)Wpos,
                             (const float4*)Wout);

    // 2) merged qkv + pos projections (blocks 0-23: qkv; 24-31: pos)
    gemm_f16x2<3><<<dim3(32, 16), 256, GEMM_SMEM>>>(
        (const __half*)xh, (const __half*)xl, (const __half*)wqh,
        (const __half*)rh, (const __half*)rl, (const __half*)wph,
        nullptr, u, v, S_LEN, QKV_LD, V_DIM);

    // 3) fused attention -> g_ah/g_al (fp16 hi/lo)
    flash_xl_mma<<<dim3(NH, S_LEN / 128), 256, FL_SMEM>>>();

    // 4) out = attn @ Wout^T -> fp32 d_out
    gemm_f16x2<0><<<dim3(V_DIM / 128, S_LEN / 128), 256, GEMM_SMEM>>>(
        (const __half*)ah, (const __half*)al, (const __half*)woh,
        nullptr, nullptr, nullptr,
        out, nullptr, nullptr, S_LEN, V_DIM, V_DIM);
}